// round 1
// baseline (speedup 1.0000x reference)
#include <cuda_runtime.h>
#include <cstddef>

// Problem constants
constexpr int B_  = 4;
constexpr int T_  = 2048;
constexpr int D_  = 1024;
constexpr int H_  = 16;
constexpr int HD_ = 64;
constexpr int M_  = B_ * T_;   // 8192 rows for the projection GEMMs

// Scratch (device globals: allocation-free per harness rules).
// Layout for Q/K/V/O: [B, H, T, HD] contiguous.
__device__ float g_Q[(size_t)B_ * H_ * T_ * HD_];
__device__ float g_K[(size_t)B_ * H_ * T_ * HD_];
__device__ float g_V[(size_t)B_ * H_ * T_ * HD_];
__device__ float g_O[(size_t)B_ * H_ * T_ * HD_];

// ---------------------------------------------------------------------------
// SGEMM: C = A @ W + bias   (A: [M_,1024], W: [1024,1024])
// MODE 0: A = x (plain [M,K]); write into g_Q/g_K/g_V ([B,H,T,HD] layout),
//         weight selected by blockIdx.z (0=Q,1=K,2=V).
// MODE 1: A = g_O with k -> (h,hd) remap; write plain [M,N] to OUT.
// Classic 128x128x8 register-tiled SGEMM, 256 threads, TM=TN=8.
// ---------------------------------------------------------------------------
template <int MODE>
__global__ __launch_bounds__(256)
void gemm_kernel(const float* __restrict__ X,
                 const float* __restrict__ W0, const float* __restrict__ W1,
                 const float* __restrict__ W2,
                 const float* __restrict__ b0, const float* __restrict__ b1,
                 const float* __restrict__ b2,
                 float* __restrict__ OUT)
{
    constexpr int BM = 128, BN = 128, BK = 8, TM = 8, TN = 8;
    constexpr int N = D_, K = D_;

    const float* W;
    const float* bias;
    float* dst;
    if (MODE == 0) {
        if (blockIdx.z == 0)      { W = W0; bias = b0; dst = g_Q; }
        else if (blockIdx.z == 1) { W = W1; bias = b1; dst = g_K; }
        else                      { W = W2; bias = b2; dst = g_V; }
    } else {
        W = W0; bias = b0; dst = OUT;
    }

    __shared__ float As[BK][BM];   // transposed A tile
    __shared__ float Bs[BK][BN];

    const int tid  = threadIdx.x;
    const int cRow = blockIdx.y * BM;
    const int cCol = blockIdx.x * BN;

    const int innerRowA = tid >> 1;           // 0..127
    const int innerColA = (tid & 1) * 4;      // 0 or 4
    const int innerRowB = tid >> 5;           // 0..7
    const int innerColB = (tid & 31) * 4;     // 0..124

    const int threadRow = (tid >> 4) * TM;    // 0..120
    const int threadCol = (tid & 15) * TN;    // 0..120

    float acc[TM][TN] = {};
    float regM[TM], regN[TN];

    const int mA = cRow + innerRowA;

    for (int bk = 0; bk < K; bk += BK) {
        // --- load A tile (vectorized) ---
        float4 av;
        const int k0 = bk + innerColA;
        if (MODE == 0) {
            av = *reinterpret_cast<const float4*>(X + (size_t)mA * K + k0);
        } else {
            // A[m,k] = g_O[b, h, t, hd]; k0 is 4-aligned and BK=8 never
            // crosses a 64-wide head boundary, so the float4 is contiguous.
            const int bb = mA / T_, tt = mA % T_;
            const int hh = k0 >> 6, hd = k0 & 63;
            av = *reinterpret_cast<const float4*>(
                g_O + ((((size_t)bb * H_ + hh) * T_ + tt) << 6) + hd);
        }
        As[innerColA + 0][innerRowA] = av.x;
        As[innerColA + 1][innerRowA] = av.y;
        As[innerColA + 2][innerRowA] = av.z;
        As[innerColA + 3][innerRowA] = av.w;

        // --- load B tile (vectorized) ---
        const float4 bv = *reinterpret_cast<const float4*>(
            W + (size_t)(bk + innerRowB) * N + cCol + innerColB);
        *reinterpret_cast<float4*>(&Bs[innerRowB][innerColB]) = bv;

        __syncthreads();

        #pragma unroll
        for (int k = 0; k < BK; k++) {
            #pragma unroll
            for (int i = 0; i < TM; i++) regM[i] = As[k][threadRow + i];
            #pragma unroll
            for (int j = 0; j < TN; j++) regN[j] = Bs[k][threadCol + j];
            #pragma unroll
            for (int i = 0; i < TM; i++)
                #pragma unroll
                for (int j = 0; j < TN; j++)
                    acc[i][j] += regM[i] * regN[j];
        }
        __syncthreads();
    }

    // --- epilogue: bias + layout remap ---
    #pragma unroll
    for (int i = 0; i < TM; i++) {
        const int m = cRow + threadRow + i;
        if (MODE == 0) {
            const int bb = m / T_, tt = m % T_;
            #pragma unroll
            for (int j = 0; j < TN; j++) {
                const int n = cCol + threadCol + j;
                const float v = acc[i][j] + bias[n];
                const int hh = n >> 6, hd = n & 63;
                dst[((((size_t)bb * H_ + hh) * T_ + tt) << 6) + hd] = v;
            }
        } else {
            #pragma unroll
            for (int j = 0; j < TN; j++) {
                const int n = cCol + threadCol + j;
                dst[(size_t)m * N + n] = acc[i][j] + bias[n];
            }
        }
    }
}

// ---------------------------------------------------------------------------
// Causal flash attention, fp32.
// Grid: (T/128, H, B). 128 threads; thread i owns query row qtile*128+i.
// q row (pre-scaled by 1/sqrt(HD)) and output accumulator live in registers;
// K/V tiles (32 x 64) staged in smem and read as broadcast LDS.128.
// ---------------------------------------------------------------------------
__global__ __launch_bounds__(128)
void attn_kernel()
{
    constexpr int BQ = 128, BKt = 32;
    constexpr float SCALE = 0.125f;  // 1/sqrt(64)

    const int qtile = blockIdx.x;
    const int h = blockIdx.y, b = blockIdx.z;
    const int tid = threadIdx.x;
    const size_t bh = ((size_t)(b * H_ + h)) * T_ * HD_;
    const int qg = qtile * BQ + tid;

    __shared__ float Ks[BKt][HD_ + 4];  // pad -> 68 floats/row (16B aligned)
    __shared__ float Vs[BKt][HD_ + 4];

    // Stage Q through smem (reusing Ks) in 4 chunks of 32 rows -> registers.
    float4 q4[16];
    #pragma unroll
    for (int ch = 0; ch < 4; ch++) {
        __syncthreads();
        for (int e = tid; e < BKt * HD_; e += BQ) {
            const int r = e >> 6, c = e & 63;
            Ks[r][c] = g_Q[bh + (size_t)(qtile * BQ + ch * 32 + r) * HD_ + c];
        }
        __syncthreads();
        if ((tid >> 5) == ch) {
            const int r = tid & 31;
            #pragma unroll
            for (int jj = 0; jj < 16; jj++) {
                float4 v = *reinterpret_cast<float4*>(&Ks[r][jj * 4]);
                v.x *= SCALE; v.y *= SCALE; v.z *= SCALE; v.w *= SCALE;
                q4[jj] = v;
            }
        }
    }

    float s[BKt];
    float ov[HD_];
    #pragma unroll
    for (int j = 0; j < HD_; j++) ov[j] = 0.f;
    float m_i = -1e30f, l_i = 0.f;

    const float* gk = g_K + bh;
    const float* gv = g_V + bh;
    const int nk = (qtile + 1) * BQ;  // causal upper bound for this block

    for (int kt = 0; kt < nk; kt += BKt) {
        __syncthreads();
        for (int e = tid; e < BKt * HD_; e += BQ) {
            const int r = e >> 6, c = e & 63;
            Ks[r][c] = gk[(size_t)kt * HD_ + e];
            Vs[r][c] = gv[(size_t)kt * HD_ + e];
        }
        __syncthreads();

        // Warp-uniform causal skip: kt is a multiple of 32, warps cover
        // 32-aligned tid ranges, so this predicate is uniform per warp.
        if (kt <= qg) {
            float tmax = -1e30f;
            #pragma unroll
            for (int kk = 0; kk < BKt; kk++) {
                float acc = 0.f;
                #pragma unroll
                for (int jj = 0; jj < 16; jj++) {
                    const float4 kv = *reinterpret_cast<float4*>(&Ks[kk][jj * 4]);
                    acc += q4[jj].x * kv.x + q4[jj].y * kv.y
                         + q4[jj].z * kv.z + q4[jj].w * kv.w;
                }
                acc = (kt + kk <= qg) ? acc : -1e30f;
                s[kk] = acc;
                tmax = fmaxf(tmax, acc);
            }

            const float mnew = fmaxf(m_i, tmax);
            const float corr = __expf(m_i - mnew);
            float rsum = 0.f;
            #pragma unroll
            for (int kk = 0; kk < BKt; kk++) {
                const float p = __expf(s[kk] - mnew);
                s[kk] = p;
                rsum += p;
            }
            l_i = l_i * corr + rsum;
            m_i = mnew;

            #pragma unroll
            for (int j = 0; j < HD_; j++) ov[j] *= corr;

            #pragma unroll
            for (int kk = 0; kk < BKt; kk++) {
                const float p = s[kk];
                #pragma unroll
                for (int jj = 0; jj < 16; jj++) {
                    const float4 vv = *reinterpret_cast<float4*>(&Vs[kk][jj * 4]);
                    ov[jj * 4 + 0] += p * vv.x;
                    ov[jj * 4 + 1] += p * vv.y;
                    ov[jj * 4 + 2] += p * vv.z;
                    ov[jj * 4 + 3] += p * vv.w;
                }
            }
        }
    }

    const float inv = 1.f / l_i;
    float* go = g_O + bh + (size_t)qg * HD_;
    #pragma unroll
    for (int jj = 0; jj < 16; jj++) {
        const float4 w4 = make_float4(ov[jj * 4 + 0] * inv, ov[jj * 4 + 1] * inv,
                                      ov[jj * 4 + 2] * inv, ov[jj * 4 + 3] * inv);
        *reinterpret_cast<float4*>(go + jj * 4) = w4;
    }
}

// ---------------------------------------------------------------------------
extern "C" void kernel_launch(void* const* d_in, const int* in_sizes, int n_in,
                              void* d_out, int out_size)
{
    const float* x  = (const float*)d_in[0];
    const float* wq = (const float*)d_in[1];
    const float* bq = (const float*)d_in[2];
    const float* wk = (const float*)d_in[3];
    const float* bk = (const float*)d_in[4];
    const float* wv = (const float*)d_in[5];
    const float* bv = (const float*)d_in[6];
    const float* wo = (const float*)d_in[7];
    const float* bo = (const float*)d_in[8];
    float* out = (float*)d_out;

    // 1) Fused QKV projections (transpose to [B,H,T,HD] fused into epilogue)
    dim3 gQKV(D_ / 128, M_ / 128, 3);
    gemm_kernel<0><<<gQKV, 256>>>(x, wq, wk, wv, bq, bk, bv, nullptr);

    // 2) Causal flash attention
    attn_kernel<<<dim3(T_ / 128, H_, B_), 128>>>();

    // 3) Output projection (head-merge transpose fused into A-tile load)
    dim3 gO(D_ / 128, M_ / 128, 1);
    gemm_kernel<1><<<gO, 256>>>(nullptr, wo, nullptr, nullptr, bo, nullptr,
                                nullptr, out);
}

// round 3
// speedup vs baseline: 1.4918x; 1.4918x over previous
#include <cuda_runtime.h>
#include <cuda_bf16.h>
#include <cstdint>
#include <cstddef>

// ---------------------------------------------------------------------------
// Problem constants
// ---------------------------------------------------------------------------
constexpr int B_  = 4;
constexpr int T_  = 2048;
constexpr int D_  = 1024;
constexpr int H_  = 16;
constexpr int HD_ = 64;
constexpr int M_  = B_ * T_;   // 8192

// ---------------------------------------------------------------------------
// Device scratch
// ---------------------------------------------------------------------------
__device__ float g_Q[(size_t)B_ * H_ * T_ * HD_];
__device__ float g_K[(size_t)B_ * H_ * T_ * HD_];
__device__ float g_V[(size_t)B_ * H_ * T_ * HD_];
__device__ float g_O[(size_t)B_ * H_ * T_ * HD_];

// bf16 hi/lo splits of activations (row-major [M, D])
__device__ __align__(128) __nv_bfloat16 g_xh[(size_t)M_ * D_];
__device__ __align__(128) __nv_bfloat16 g_xl[(size_t)M_ * D_];
__device__ __align__(128) __nv_bfloat16 g_oh[(size_t)M_ * D_];
__device__ __align__(128) __nv_bfloat16 g_ol[(size_t)M_ * D_];
// 4 weights transposed to [N, K] bf16 hi/lo, stacked on z: z=0..3 -> wq,wk,wv,wo
__device__ __align__(128) __nv_bfloat16 g_wth[(size_t)4 * D_ * D_];
__device__ __align__(128) __nv_bfloat16 g_wtl[(size_t)4 * D_ * D_];

// ---------------------------------------------------------------------------
// PTX helpers (all generic-target legal: sm_80+ / sm_75+)
// ---------------------------------------------------------------------------
__device__ __forceinline__ uint32_t smem_u32(const void* p) {
    uint32_t a;
    asm("{ .reg .u64 t; cvta.to.shared.u64 t, %1; cvt.u32.u64 %0, t; }"
        : "=r"(a) : "l"(p));
    return a;
}

__device__ __forceinline__ void cp16(uint32_t saddr, const void* gaddr) {
    asm volatile("cp.async.cg.shared.global [%0], [%1], 16;"
                 :: "r"(saddr), "l"(gaddr));
}
__device__ __forceinline__ void cp_commit() {
    asm volatile("cp.async.commit_group;");
}
template <int N>
__device__ __forceinline__ void cp_wait() {
    asm volatile("cp.async.wait_group %0;" :: "n"(N));
}

__device__ __forceinline__ void ldm_x4(uint32_t* r, uint32_t addr) {
    asm volatile("ldmatrix.sync.aligned.m8n8.x4.shared.b16 {%0,%1,%2,%3}, [%4];"
                 : "=r"(r[0]), "=r"(r[1]), "=r"(r[2]), "=r"(r[3]) : "r"(addr));
}

__device__ __forceinline__ void mma_bf16(float* c, const uint32_t* a,
                                         const uint32_t* b) {
    asm volatile(
        "mma.sync.aligned.m16n8k16.row.col.f32.bf16.bf16.f32 "
        "{%0,%1,%2,%3}, {%4,%5,%6,%7}, {%8,%9}, {%0,%1,%2,%3};"
        : "+f"(c[0]), "+f"(c[1]), "+f"(c[2]), "+f"(c[3])
        : "r"(a[0]), "r"(a[1]), "r"(a[2]), "r"(a[3]), "r"(b[0]), "r"(b[1]));
}

// ---------------------------------------------------------------------------
// HMMA GEMM: C[128x128 tile] = A @ W^T + bias    (bf16x3, fp32 accum)
//   A: [M, 1024] bf16 hi/lo (g_xh/g_xl for MODE0, g_oh/g_ol for MODE1)
//   W^T: g_wth/g_wtl [z][N=1024][K=1024]
//   MODE 0: dst = g_Q/g_K/g_V per blockIdx.z, with [B,H,T,HD] remap
//   MODE 1: dst = out, plain [M, N]
// 256 threads = 8 warps (4 M x 2 N), warp tile 32x64, BK=32, 3-stage cp.async.
// ---------------------------------------------------------------------------
constexpr int BK      = 32;
constexpr int PITCH_B = (BK + 8) * 2;                 // 80 bytes per smem row
constexpr int ARR_B   = 128 * PITCH_B;                // 10240 B per tile array
constexpr int STAGE_B = 4 * ARR_B;                    // Ah, Al, Bh, Bl = 40960 B
constexpr int NSTG    = 3;
constexpr int GEMM_SMEM = NSTG * STAGE_B;             // 122880 B
constexpr int KT      = D_ / BK;                      // 32

template <int MODE>
__global__ __launch_bounds__(256)
void gemm_mma(const __nv_bfloat16* __restrict__ Ah,
              const __nv_bfloat16* __restrict__ Al,
              const float* __restrict__ b0, const float* __restrict__ b1,
              const float* __restrict__ b2,
              float* __restrict__ out, int zbase)
{
    extern __shared__ __align__(128) char smem[];
    const uint32_t sb = smem_u32(smem);

    const int tid  = threadIdx.x;
    const int wid  = tid >> 5;
    const int lane = tid & 31;
    const int wm   = (wid & 3) * 32;    // warp M offset in tile
    const int wn   = (wid >> 2) * 64;   // warp N offset in tile

    const int mBase = blockIdx.y * 128;
    const int nBase = blockIdx.x * 128;
    const int z     = zbase + blockIdx.z;

    const __nv_bfloat16* Bh = g_wth + ((size_t)z << 20);
    const __nv_bfloat16* Bl = g_wtl + ((size_t)z << 20);

    // --- per-thread load mapping: 2 16B chunks per 128x32 array ---
    // chunk c in [0,512): row = c>>2, quarter = c&3
    const int c0r = tid >> 2,        c0q = tid & 3;
    const int c1r = (tid + 256) >> 2, c1q = (tid + 256) & 3;

    auto load_stage = [&](int stg, int kt) {
        const uint32_t st = sb + stg * STAGE_B;
        const int bk = kt * BK;
        // A hi/lo
        {
            const size_t g0 = (size_t)(mBase + c0r) * D_ + bk + c0q * 8;
            const size_t g1 = (size_t)(mBase + c1r) * D_ + bk + c1q * 8;
            const uint32_t s0 = c0r * PITCH_B + c0q * 16;
            const uint32_t s1 = c1r * PITCH_B + c1q * 16;
            cp16(st + s0,           Ah + g0);
            cp16(st + s1,           Ah + g1);
            cp16(st + ARR_B + s0,   Al + g0);
            cp16(st + ARR_B + s1,   Al + g1);
        }
        // B hi/lo (rows are N, cols K)
        {
            const size_t g0 = (size_t)(nBase + c0r) * D_ + bk + c0q * 8;
            const size_t g1 = (size_t)(nBase + c1r) * D_ + bk + c1q * 8;
            const uint32_t s0 = c0r * PITCH_B + c0q * 16;
            const uint32_t s1 = c1r * PITCH_B + c1q * 16;
            cp16(st + 2 * ARR_B + s0, Bh + g0);
            cp16(st + 2 * ARR_B + s1, Bh + g1);
            cp16(st + 3 * ARR_B + s0, Bl + g0);
            cp16(st + 3 * ARR_B + s1, Bl + g1);
        }
        cp_commit();
    };

    float acc[2][8][4];
    #pragma unroll
    for (int mi = 0; mi < 2; mi++)
        #pragma unroll
        for (int ni = 0; ni < 8; ni++)
            #pragma unroll
            for (int r = 0; r < 4; r++) acc[mi][ni][r] = 0.f;

    // prologue
    load_stage(0, 0);
    load_stage(1, 1);

    // ldmatrix address components (within-array byte offsets)
    // A: row = wm + mi*16 + (lane&7) + ((lane>>3)&1)*8 ; koff = ((lane>>4)&1)*16
    const uint32_t aRowOff =
        (uint32_t)(wm + (lane & 7) + ((lane >> 3) & 1) * 8) * PITCH_B +
        ((lane >> 4) & 1) * 16;
    // B: row = wn + p*16 + ((lane>>4)&1)*8 + (lane&7) ; koff = ((lane>>3)&1)*16
    const uint32_t bRowOff =
        (uint32_t)(wn + ((lane >> 4) & 1) * 8 + (lane & 7)) * PITCH_B +
        ((lane >> 3) & 1) * 16;

    #pragma unroll 1
    for (int kt = 0; kt < KT; kt++) {
        cp_wait<NSTG - 2>();
        __syncthreads();

        const int nx = kt + NSTG - 1;
        if (nx < KT) load_stage(nx % NSTG, nx);

        const uint32_t st  = sb + (kt % NSTG) * STAGE_B;
        const uint32_t sAh = st;
        const uint32_t sAl = st + ARR_B;
        const uint32_t sBh = st + 2 * ARR_B;
        const uint32_t sBl = st + 3 * ARR_B;

        #pragma unroll
        for (int ks = 0; ks < 2; ks++) {
            const uint32_t kOff = ks * 32;

            uint32_t ah[2][4], al[2][4];
            #pragma unroll
            for (int mi = 0; mi < 2; mi++) {
                const uint32_t off = aRowOff + (uint32_t)mi * 16 * PITCH_B + kOff;
                ldm_x4(ah[mi], sAh + off);
                ldm_x4(al[mi], sAl + off);
            }
            uint32_t bh[4][4], bl[4][4];
            #pragma unroll
            for (int p = 0; p < 4; p++) {
                const uint32_t off = bRowOff + (uint32_t)p * 16 * PITCH_B + kOff;
                ldm_x4(bh[p], sBh + off);
                ldm_x4(bl[p], sBl + off);
            }

            #pragma unroll
            for (int mi = 0; mi < 2; mi++)
                #pragma unroll
                for (int p = 0; p < 4; p++)
                    #pragma unroll
                    for (int hHalf = 0; hHalf < 2; hHalf++) {
                        const int ni = p * 2 + hHalf;
                        mma_bf16(acc[mi][ni], ah[mi], &bh[p][hHalf * 2]);
                        mma_bf16(acc[mi][ni], ah[mi], &bl[p][hHalf * 2]);
                        mma_bf16(acc[mi][ni], al[mi], &bh[p][hHalf * 2]);
                    }
        }
        __syncthreads();
    }

    // --- epilogue: bias + layout remap, float2 stores ---
    const float* bias = (MODE == 0)
        ? (blockIdx.z == 0 ? b0 : blockIdx.z == 1 ? b1 : b2) : b0;
    float* dstQ = nullptr;
    if (MODE == 0) dstQ = (blockIdx.z == 0) ? g_Q : (blockIdx.z == 1) ? g_K : g_V;

    #pragma unroll
    for (int mi = 0; mi < 2; mi++) {
        #pragma unroll
        for (int ni = 0; ni < 8; ni++) {
            const int n0 = nBase + wn + ni * 8 + (lane & 3) * 2;
            const float bv0 = __ldg(bias + n0), bv1 = __ldg(bias + n0 + 1);
            #pragma unroll
            for (int rr = 0; rr < 2; rr++) {
                const int m = mBase + wm + mi * 16 + (lane >> 2) + rr * 8;
                const float v0 = acc[mi][ni][rr * 2 + 0] + bv0;
                const float v1 = acc[mi][ni][rr * 2 + 1] + bv1;
                float* p;
                if (MODE == 0) {
                    const int bb = m >> 11, tt = m & 2047;
                    const int hh = n0 >> 6, hd = n0 & 63;
                    p = dstQ + ((((size_t)bb * H_ + hh) * T_ + tt) << 6) + hd;
                } else {
                    p = out + (size_t)m * D_ + n0;
                }
                *reinterpret_cast<float2*>(p) = make_float2(v0, v1);
            }
        }
    }
}

// ---------------------------------------------------------------------------
// Conversion kernels
// ---------------------------------------------------------------------------
__global__ __launch_bounds__(256) void split_x_kernel(const float* __restrict__ src)
{
    const int i = blockIdx.x * 256 + threadIdx.x;
    const float v = src[i];
    const __nv_bfloat16 hv = __float2bfloat16(v);
    g_xh[i] = hv;
    g_xl[i] = __float2bfloat16(v - __bfloat162float(hv));
}

__global__ __launch_bounds__(256) void split_o_kernel()
{
    const int i = blockIdx.x * 256 + threadIdx.x;   // index into g_O [B,H,T,HD]
    const float v = g_O[i];
    const int hd = i & 63;
    const int tt = (i >> 6) & 2047;
    const int hh = (i >> 17) & 15;
    const int bb = i >> 21;
    const size_t di = (((size_t)bb * T_ + tt) * D_) + hh * 64 + hd;
    const __nv_bfloat16 hv = __float2bfloat16(v);
    g_oh[di] = hv;
    g_ol[di] = __float2bfloat16(v - __bfloat162float(hv));
}

// transpose+split 4 weights: g_wt[z][n][k] = w_z[k][n]
__global__ __launch_bounds__(256) void wsplit_kernel(
    const float* __restrict__ wq, const float* __restrict__ wk,
    const float* __restrict__ wv, const float* __restrict__ wo)
{
    __shared__ float tile[32][33];
    const int z = blockIdx.z;
    const float* w = (z == 0) ? wq : (z == 1) ? wk : (z == 2) ? wv : wo;
    const int nB = blockIdx.x * 32, kB = blockIdx.y * 32;
    const int tx = threadIdx.x & 31, ty = threadIdx.x >> 5;

    #pragma unroll
    for (int r = ty; r < 32; r += 8)
        tile[r][tx] = w[(size_t)(kB + r) * D_ + nB + tx];
    __syncthreads();
    #pragma unroll
    for (int r = ty; r < 32; r += 8) {
        const float v = tile[tx][r];
        const size_t di = ((size_t)z << 20) + (size_t)(nB + r) * D_ + kB + tx;
        const __nv_bfloat16 hv = __float2bfloat16(v);
        g_wth[di] = hv;
        g_wtl[di] = __float2bfloat16(v - __bfloat162float(hv));
    }
}

// ---------------------------------------------------------------------------
// Causal flash attention, fp32 (unchanged)
// ---------------------------------------------------------------------------
__global__ __launch_bounds__(128)
void attn_kernel()
{
    constexpr int BQ = 128, BKt = 32;
    constexpr float SCALE = 0.125f;

    const int qtile = blockIdx.x;
    const int h = blockIdx.y, b = blockIdx.z;
    const int tid = threadIdx.x;
    const size_t bh = ((size_t)(b * H_ + h)) * T_ * HD_;
    const int qg = qtile * BQ + tid;

    __shared__ float Ks[BKt][HD_ + 4];
    __shared__ float Vs[BKt][HD_ + 4];

    float4 q4[16];
    #pragma unroll
    for (int ch = 0; ch < 4; ch++) {
        __syncthreads();
        for (int e = tid; e < BKt * HD_; e += BQ) {
            const int r = e >> 6, c = e & 63;
            Ks[r][c] = g_Q[bh + (size_t)(qtile * BQ + ch * 32 + r) * HD_ + c];
        }
        __syncthreads();
        if ((tid >> 5) == ch) {
            const int r = tid & 31;
            #pragma unroll
            for (int jj = 0; jj < 16; jj++) {
                float4 v = *reinterpret_cast<float4*>(&Ks[r][jj * 4]);
                v.x *= SCALE; v.y *= SCALE; v.z *= SCALE; v.w *= SCALE;
                q4[jj] = v;
            }
        }
    }

    float s[BKt];
    float ov[HD_];
    #pragma unroll
    for (int j = 0; j < HD_; j++) ov[j] = 0.f;
    float m_i = -1e30f, l_i = 0.f;

    const float* gk = g_K + bh;
    const float* gv = g_V + bh;
    const int nk = (qtile + 1) * BQ;

    for (int kt = 0; kt < nk; kt += BKt) {
        __syncthreads();
        for (int e = tid; e < BKt * HD_; e += BQ) {
            const int r = e >> 6, c = e & 63;
            Ks[r][c] = gk[(size_t)kt * HD_ + e];
            Vs[r][c] = gv[(size_t)kt * HD_ + e];
        }
        __syncthreads();

        if (kt <= qg) {
            float tmax = -1e30f;
            #pragma unroll
            for (int kk = 0; kk < BKt; kk++) {
                float a = 0.f;
                #pragma unroll
                for (int jj = 0; jj < 16; jj++) {
                    const float4 kv = *reinterpret_cast<float4*>(&Ks[kk][jj * 4]);
                    a += q4[jj].x * kv.x + q4[jj].y * kv.y
                       + q4[jj].z * kv.z + q4[jj].w * kv.w;
                }
                a = (kt + kk <= qg) ? a : -1e30f;
                s[kk] = a;
                tmax = fmaxf(tmax, a);
            }

            const float mnew = fmaxf(m_i, tmax);
            const float corr = __expf(m_i - mnew);
            float rsum = 0.f;
            #pragma unroll
            for (int kk = 0; kk < BKt; kk++) {
                const float p = __expf(s[kk] - mnew);
                s[kk] = p;
                rsum += p;
            }
            l_i = l_i * corr + rsum;
            m_i = mnew;

            #pragma unroll
            for (int j = 0; j < HD_; j++) ov[j] *= corr;

            #pragma unroll
            for (int kk = 0; kk < BKt; kk++) {
                const float p = s[kk];
                #pragma unroll
                for (int jj = 0; jj < 16; jj++) {
                    const float4 vv = *reinterpret_cast<float4*>(&Vs[kk][jj * 4]);
                    ov[jj * 4 + 0] += p * vv.x;
                    ov[jj * 4 + 1] += p * vv.y;
                    ov[jj * 4 + 2] += p * vv.z;
                    ov[jj * 4 + 3] += p * vv.w;
                }
            }
        }
    }

    const float inv = 1.f / l_i;
    float* go = g_O + bh + (size_t)qg * HD_;
    #pragma unroll
    for (int jj = 0; jj < 16; jj++) {
        *reinterpret_cast<float4*>(go + jj * 4) =
            make_float4(ov[jj * 4 + 0] * inv, ov[jj * 4 + 1] * inv,
                        ov[jj * 4 + 2] * inv, ov[jj * 4 + 3] * inv);
    }
}

// ---------------------------------------------------------------------------
extern "C" void kernel_launch(void* const* d_in, const int* in_sizes, int n_in,
                              void* d_out, int out_size)
{
    const float* x  = (const float*)d_in[0];
    const float* wq = (const float*)d_in[1];
    const float* bq = (const float*)d_in[2];
    const float* wk = (const float*)d_in[3];
    const float* bk = (const float*)d_in[4];
    const float* wv = (const float*)d_in[5];
    const float* bv = (const float*)d_in[6];
    const float* wo = (const float*)d_in[7];
    const float* bo = (const float*)d_in[8];
    float* out = (float*)d_out;

    static bool attrSet = false;
    if (!attrSet) {
        cudaFuncSetAttribute(gemm_mma<0>,
                             cudaFuncAttributeMaxDynamicSharedMemorySize, GEMM_SMEM);
        cudaFuncSetAttribute(gemm_mma<1>,
                             cudaFuncAttributeMaxDynamicSharedMemorySize, GEMM_SMEM);
        attrSet = true;
    }

    void *pxh, *pxl, *poh, *pol;
    cudaGetSymbolAddress(&pxh, g_xh);
    cudaGetSymbolAddress(&pxl, g_xl);
    cudaGetSymbolAddress(&poh, g_oh);
    cudaGetSymbolAddress(&pol, g_ol);

    const int nElem = M_ * D_;

    // 1) convert inputs to bf16 hi/lo
    split_x_kernel<<<nElem / 256, 256>>>(x);
    wsplit_kernel<<<dim3(32, 32, 4), 256>>>(wq, wk, wv, wo);

    // 2) QKV projections (HMMA bf16x3), head-transpose fused in epilogue
    gemm_mma<0><<<dim3(8, 64, 3), 256, GEMM_SMEM>>>(
        (const __nv_bfloat16*)pxh, (const __nv_bfloat16*)pxl,
        bq, bk, bv, nullptr, 0);

    // 3) causal flash attention (fp32)
    attn_kernel<<<dim3(T_ / 128, H_, B_), 128>>>();

    // 4) split attention output (head-merge remap)
    split_o_kernel<<<nElem / 256, 256>>>();

    // 5) output projection
    gemm_mma<1><<<dim3(8, 64, 1), 256, GEMM_SMEM>>>(
        (const __nv_bfloat16*)poh, (const __nv_bfloat16*)pol,
        bo, bo, bo, out, 3);
}

// round 4
// speedup vs baseline: 3.8593x; 2.5870x over previous
#include <cuda_runtime.h>
#include <cuda_bf16.h>
#include <cstdint>
#include <cstddef>

// ---------------------------------------------------------------------------
// Problem constants
// ---------------------------------------------------------------------------
constexpr int B_  = 4;
constexpr int T_  = 2048;
constexpr int D_  = 1024;
constexpr int H_  = 16;
constexpr int HD_ = 64;
constexpr int M_  = B_ * T_;   // 8192

// 0.125 * log2(e): folded into Q so softmax uses exp2
constexpr float QSCALE = 0.18033688011112042f;

// ---------------------------------------------------------------------------
// Device scratch (bf16 hi/lo everywhere; no fp32 intermediates)
// ---------------------------------------------------------------------------
__device__ __align__(128) __nv_bfloat16 g_xh[(size_t)M_ * D_];
__device__ __align__(128) __nv_bfloat16 g_xl[(size_t)M_ * D_];
__device__ __align__(128) __nv_bfloat16 g_oh[(size_t)M_ * D_];   // [B*T, D]
__device__ __align__(128) __nv_bfloat16 g_ol[(size_t)M_ * D_];
// QKV in [B, H, T, HD]
__device__ __align__(128) __nv_bfloat16 g_qh[(size_t)M_ * D_];
__device__ __align__(128) __nv_bfloat16 g_ql[(size_t)M_ * D_];
__device__ __align__(128) __nv_bfloat16 g_kh[(size_t)M_ * D_];
__device__ __align__(128) __nv_bfloat16 g_kl[(size_t)M_ * D_];
__device__ __align__(128) __nv_bfloat16 g_vh[(size_t)M_ * D_];
__device__ __align__(128) __nv_bfloat16 g_vl[(size_t)M_ * D_];
// 4 weights transposed to [N, K] bf16 hi/lo, z: 0..3 -> wq,wk,wv,wo
__device__ __align__(128) __nv_bfloat16 g_wth[(size_t)4 * D_ * D_];
__device__ __align__(128) __nv_bfloat16 g_wtl[(size_t)4 * D_ * D_];

// ---------------------------------------------------------------------------
// PTX helpers (generic-target legal: sm_80+ / sm_75+)
// ---------------------------------------------------------------------------
__device__ __forceinline__ uint32_t smem_u32(const void* p) {
    uint32_t a;
    asm("{ .reg .u64 t; cvta.to.shared.u64 t, %1; cvt.u32.u64 %0, t; }"
        : "=r"(a) : "l"(p));
    return a;
}
__device__ __forceinline__ void cp16(uint32_t saddr, const void* gaddr) {
    asm volatile("cp.async.cg.shared.global [%0], [%1], 16;"
                 :: "r"(saddr), "l"(gaddr));
}
__device__ __forceinline__ void cp_commit() {
    asm volatile("cp.async.commit_group;");
}
template <int N>
__device__ __forceinline__ void cp_wait() {
    asm volatile("cp.async.wait_group %0;" :: "n"(N));
}
__device__ __forceinline__ void ldm_x4(uint32_t* r, uint32_t addr) {
    asm volatile("ldmatrix.sync.aligned.m8n8.x4.shared.b16 {%0,%1,%2,%3}, [%4];"
                 : "=r"(r[0]), "=r"(r[1]), "=r"(r[2]), "=r"(r[3]) : "r"(addr));
}
__device__ __forceinline__ void ldm_x4_t(uint32_t* r, uint32_t addr) {
    asm volatile("ldmatrix.sync.aligned.m8n8.x4.trans.shared.b16 {%0,%1,%2,%3}, [%4];"
                 : "=r"(r[0]), "=r"(r[1]), "=r"(r[2]), "=r"(r[3]) : "r"(addr));
}
__device__ __forceinline__ void mma_bf16(float* c, const uint32_t* a,
                                         const uint32_t* b) {
    asm volatile(
        "mma.sync.aligned.m16n8k16.row.col.f32.bf16.bf16.f32 "
        "{%0,%1,%2,%3}, {%4,%5,%6,%7}, {%8,%9}, {%0,%1,%2,%3};"
        : "+f"(c[0]), "+f"(c[1]), "+f"(c[2]), "+f"(c[3])
        : "r"(a[0]), "r"(a[1]), "r"(a[2]), "r"(a[3]), "r"(b[0]), "r"(b[1]));
}
__device__ __forceinline__ float ex2f(float x) {
    float r;
    asm("ex2.approx.ftz.f32 %0, %1;" : "=f"(r) : "f"(x));
    return r;
}
// hi/lo bf16 split helpers (truncation hi; residual fits bf16)
__device__ __forceinline__ float hi_trunc(float v) {
    return __uint_as_float(__float_as_uint(v) & 0xFFFF0000u);
}
__device__ __forceinline__ uint32_t pack_hi_trunc(float lo, float hi) {
    return (__float_as_uint(hi) & 0xFFFF0000u) | (__float_as_uint(lo) >> 16);
}
__device__ __forceinline__ uint32_t pack_bf16x2_rn(float lo, float hi) {
    uint32_t r;
    asm("cvt.rn.bf16x2.f32 %0, %1, %2;" : "=r"(r) : "f"(hi), "f"(lo));
    return r;
}

// ---------------------------------------------------------------------------
// HMMA GEMM (bf16x3, fp32 accum). 256 thr = 8 warps (4Mx2N), warp 32x64, BK=32.
// MODE 0: C = x @ W^T + bias -> q/k/v bf16 hi/lo, [B,H,T,HD]; Q pre-scaled.
// MODE 1: C = attnO @ wo^T + bias -> out fp32 [M, D].
// ---------------------------------------------------------------------------
constexpr int BK      = 32;
constexpr int PITCH_B = (BK + 8) * 2;                 // 80 B per smem row
constexpr int ARR_B   = 128 * PITCH_B;                // 10240 B
constexpr int STAGE_B = 4 * ARR_B;                    // 40960 B
constexpr int NSTG    = 3;
constexpr int GEMM_SMEM = NSTG * STAGE_B;             // 122880 B
constexpr int KT_G    = D_ / BK;                      // 32

template <int MODE>
__global__ __launch_bounds__(256)
void gemm_mma(const __nv_bfloat16* __restrict__ Ah,
              const __nv_bfloat16* __restrict__ Al,
              const float* __restrict__ b0, const float* __restrict__ b1,
              const float* __restrict__ b2,
              float* __restrict__ out, int zbase)
{
    extern __shared__ __align__(128) char smem[];
    const uint32_t sb = smem_u32(smem);

    const int tid  = threadIdx.x;
    const int wid  = tid >> 5;
    const int lane = tid & 31;
    const int wm   = (wid & 3) * 32;
    const int wn   = (wid >> 2) * 64;

    const int mBase = blockIdx.y * 128;
    const int nBase = blockIdx.x * 128;
    const int z     = zbase + blockIdx.z;

    const __nv_bfloat16* Bh = g_wth + ((size_t)z << 20);
    const __nv_bfloat16* Bl = g_wtl + ((size_t)z << 20);

    const int c0r = tid >> 2,         c0q = tid & 3;
    const int c1r = (tid + 256) >> 2, c1q = (tid + 256) & 3;

    auto load_stage = [&](int stg, int kt) {
        const uint32_t st = sb + stg * STAGE_B;
        const int bk = kt * BK;
        {
            const size_t g0 = (size_t)(mBase + c0r) * D_ + bk + c0q * 8;
            const size_t g1 = (size_t)(mBase + c1r) * D_ + bk + c1q * 8;
            const uint32_t s0 = c0r * PITCH_B + c0q * 16;
            const uint32_t s1 = c1r * PITCH_B + c1q * 16;
            cp16(st + s0,         Ah + g0);
            cp16(st + s1,         Ah + g1);
            cp16(st + ARR_B + s0, Al + g0);
            cp16(st + ARR_B + s1, Al + g1);
        }
        {
            const size_t g0 = (size_t)(nBase + c0r) * D_ + bk + c0q * 8;
            const size_t g1 = (size_t)(nBase + c1r) * D_ + bk + c1q * 8;
            const uint32_t s0 = c0r * PITCH_B + c0q * 16;
            const uint32_t s1 = c1r * PITCH_B + c1q * 16;
            cp16(st + 2 * ARR_B + s0, Bh + g0);
            cp16(st + 2 * ARR_B + s1, Bh + g1);
            cp16(st + 3 * ARR_B + s0, Bl + g0);
            cp16(st + 3 * ARR_B + s1, Bl + g1);
        }
        cp_commit();
    };

    float acc[2][8][4];
    #pragma unroll
    for (int mi = 0; mi < 2; mi++)
        #pragma unroll
        for (int ni = 0; ni < 8; ni++)
            #pragma unroll
            for (int r = 0; r < 4; r++) acc[mi][ni][r] = 0.f;

    load_stage(0, 0);
    load_stage(1, 1);

    const uint32_t aRowOff =
        (uint32_t)(wm + (lane & 7) + ((lane >> 3) & 1) * 8) * PITCH_B +
        ((lane >> 4) & 1) * 16;
    const uint32_t bRowOff =
        (uint32_t)(wn + ((lane >> 4) & 1) * 8 + (lane & 7)) * PITCH_B +
        ((lane >> 3) & 1) * 16;

    #pragma unroll 1
    for (int kt = 0; kt < KT_G; kt++) {
        cp_wait<NSTG - 2>();
        __syncthreads();

        const int nx = kt + NSTG - 1;
        if (nx < KT_G) load_stage(nx % NSTG, nx);

        const uint32_t st  = sb + (kt % NSTG) * STAGE_B;
        const uint32_t sAh = st;
        const uint32_t sAl = st + ARR_B;
        const uint32_t sBh = st + 2 * ARR_B;
        const uint32_t sBl = st + 3 * ARR_B;

        #pragma unroll
        for (int ks = 0; ks < 2; ks++) {
            const uint32_t kOff = ks * 32;

            uint32_t ah[2][4], al[2][4];
            #pragma unroll
            for (int mi = 0; mi < 2; mi++) {
                const uint32_t off = aRowOff + (uint32_t)mi * 16 * PITCH_B + kOff;
                ldm_x4(ah[mi], sAh + off);
                ldm_x4(al[mi], sAl + off);
            }
            uint32_t bh[4][4], bl[4][4];
            #pragma unroll
            for (int p = 0; p < 4; p++) {
                const uint32_t off = bRowOff + (uint32_t)p * 16 * PITCH_B + kOff;
                ldm_x4(bh[p], sBh + off);
                ldm_x4(bl[p], sBl + off);
            }
            #pragma unroll
            for (int mi = 0; mi < 2; mi++)
                #pragma unroll
                for (int p = 0; p < 4; p++)
                    #pragma unroll
                    for (int hf = 0; hf < 2; hf++) {
                        const int ni = p * 2 + hf;
                        mma_bf16(acc[mi][ni], ah[mi], &bh[p][hf * 2]);
                        mma_bf16(acc[mi][ni], ah[mi], &bl[p][hf * 2]);
                        mma_bf16(acc[mi][ni], al[mi], &bh[p][hf * 2]);
                    }
        }
        __syncthreads();
    }

    // --- epilogue ---
    const float* bias = (MODE == 0)
        ? (blockIdx.z == 0 ? b0 : blockIdx.z == 1 ? b1 : b2) : b0;

    __nv_bfloat16 *dh = nullptr, *dl = nullptr;
    float scale = 1.f;
    if (MODE == 0) {
        if (blockIdx.z == 0)      { dh = g_qh; dl = g_ql; scale = QSCALE; }
        else if (blockIdx.z == 1) { dh = g_kh; dl = g_kl; }
        else                      { dh = g_vh; dl = g_vl; }
    }

    #pragma unroll
    for (int mi = 0; mi < 2; mi++) {
        #pragma unroll
        for (int ni = 0; ni < 8; ni++) {
            const int n0 = nBase + wn + ni * 8 + (lane & 3) * 2;
            const float bv0 = __ldg(bias + n0), bv1 = __ldg(bias + n0 + 1);
            #pragma unroll
            for (int rr = 0; rr < 2; rr++) {
                const int m = mBase + wm + mi * 16 + (lane >> 2) + rr * 8;
                float v0 = acc[mi][ni][rr * 2 + 0] + bv0;
                float v1 = acc[mi][ni][rr * 2 + 1] + bv1;
                if (MODE == 0) {
                    v0 *= scale; v1 *= scale;
                    const int bb = m >> 11, tt = m & 2047;
                    const int hh = n0 >> 6, hd = n0 & 63;
                    const size_t idx =
                        ((((size_t)bb * H_ + hh) * T_ + tt) << 6) + hd;
                    reinterpret_cast<uint32_t*>(dh)[idx >> 1] =
                        pack_hi_trunc(v0, v1);
                    reinterpret_cast<uint32_t*>(dl)[idx >> 1] =
                        pack_bf16x2_rn(v0 - hi_trunc(v0), v1 - hi_trunc(v1));
                } else {
                    *reinterpret_cast<float2*>(out + (size_t)m * D_ + n0) =
                        make_float2(v0, v1);
                }
            }
        }
    }
}

// ---------------------------------------------------------------------------
// Tensor-core causal flash attention (bf16x3, fp32 accum, exp2 softmax).
// CTA: 128 queries, 8 warps (16 rows each); key tiles of 64, double-buffered.
// ---------------------------------------------------------------------------
constexpr int APITCH_B    = 144;                    // 64 bf16 + 8 pad, bytes
constexpr int ATT_Q_B     = 128 * APITCH_B;         // 18432 per Q array
constexpr int ATT_ARR_B   = 64 * APITCH_B;          // 9216 per K/V array
constexpr int ATT_STAGE_B = 4 * ATT_ARR_B;          // 36864 (kh,kl,vh,vl)
constexpr int ATT_SMEM    = 2 * ATT_Q_B + 2 * ATT_STAGE_B;  // 110592

__global__ __launch_bounds__(256)
void attn_mma()
{
    extern __shared__ __align__(128) char smem[];
    const uint32_t sb = smem_u32(smem);

    const int tid  = threadIdx.x;
    const int wid  = tid >> 5;
    const int lane = tid & 31;

    const int qb = (gridDim.x - 1) - blockIdx.x;     // largest-first
    const int h  = blockIdx.y, b = blockIdx.z;
    const size_t bh = ((size_t)(b * H_ + h)) * T_ * HD_;

    const __nv_bfloat16* Qh = g_qh + bh + (size_t)qb * 128 * HD_;
    const __nv_bfloat16* Ql = g_ql + bh + (size_t)qb * 128 * HD_;
    const __nv_bfloat16* Kh = g_kh + bh;
    const __nv_bfloat16* Kl = g_kl + bh;
    const __nv_bfloat16* Vh = g_vh + bh;
    const __nv_bfloat16* Vl = g_vl + bh;

    // ---- issue Q loads (group 0): 2 arrays x 128 rows x 8 16B-chunks ----
    #pragma unroll
    for (int i = 0; i < 8; i++) {
        const int c = i * 256 + tid;
        const int arr = c >> 10, row = (c >> 3) & 127, q8 = c & 7;
        const __nv_bfloat16* src = (arr ? Ql : Qh) + (size_t)row * HD_ + q8 * 8;
        cp16(sb + arr * ATT_Q_B + row * APITCH_B + q8 * 16, src);
    }
    cp_commit();

    const int KT = 2 * qb + 2;

    auto load_kv = [&](int stg, int kt) {
        const uint32_t base = sb + 2 * ATT_Q_B + stg * ATT_STAGE_B;
        #pragma unroll
        for (int i = 0; i < 8; i++) {
            const int c = i * 256 + tid;
            const int arr = c >> 9, row = (c >> 3) & 63, q8 = c & 7;
            const __nv_bfloat16* g =
                (arr == 0) ? Kh : (arr == 1) ? Kl : (arr == 2) ? Vh : Vl;
            cp16(base + arr * ATT_ARR_B + row * APITCH_B + q8 * 16,
                 g + (size_t)(kt * 64 + row) * HD_ + q8 * 8);
        }
        cp_commit();
    };
    load_kv(0, 0);

    // ---- Q fragments to registers ----
    cp_wait<1>();
    __syncthreads();
    uint32_t qfh[4][4], qfl[4][4];
    {
        const uint32_t aoff = sb +
            (uint32_t)(wid * 16 + (lane & 7) + ((lane >> 3) & 1) * 8) * APITCH_B +
            ((lane >> 4) & 1) * 16;
        #pragma unroll
        for (int kc = 0; kc < 4; kc++) {
            ldm_x4(qfh[kc], aoff + kc * 32);
            ldm_x4(qfl[kc], aoff + ATT_Q_B + kc * 32);
        }
    }

    float o[8][4];
    #pragma unroll
    for (int nt = 0; nt < 8; nt++)
        #pragma unroll
        for (int r = 0; r < 4; r++) o[nt][r] = 0.f;
    float m0 = -1e30f, m1 = -1e30f, l0 = 0.f, l1 = 0.f;

    const int r0g = qb * 128 + wid * 16 + (lane >> 2);  // global row, subrow0

    const uint32_t bBase =
        (uint32_t)(((lane >> 4) & 1) * 8 + (lane & 7)) * APITCH_B +
        ((lane >> 3) & 1) * 16;
    const uint32_t vBase =
        (uint32_t)((lane & 7) + ((lane >> 3) & 1) * 8) * APITCH_B +
        ((lane >> 4) & 1) * 16;

    #pragma unroll 1
    for (int kt = 0; kt < KT; kt++) {
        cp_wait<0>();
        __syncthreads();
        if (kt + 1 < KT) load_kv((kt + 1) & 1, kt + 1);

        const uint32_t st = sb + 2 * ATT_Q_B + (kt & 1) * ATT_STAGE_B;

        // ---- S = Q K^T ----
        float s[8][4];
        #pragma unroll
        for (int nt = 0; nt < 8; nt++)
            #pragma unroll
            for (int r = 0; r < 4; r++) s[nt][r] = 0.f;

        #pragma unroll
        for (int kc = 0; kc < 4; kc++) {
            #pragma unroll
            for (int nt16 = 0; nt16 < 4; nt16++) {
                uint32_t kh4[4], kl4[4];
                const uint32_t ad = st + bBase + nt16 * 16 * APITCH_B + kc * 32;
                ldm_x4(kh4, ad);
                ldm_x4(kl4, ad + ATT_ARR_B);
                #pragma unroll
                for (int hf = 0; hf < 2; hf++) {
                    float* sd = s[nt16 * 2 + hf];
                    mma_bf16(sd, qfh[kc], &kh4[hf * 2]);
                    mma_bf16(sd, qfl[kc], &kh4[hf * 2]);
                    mma_bf16(sd, qfh[kc], &kl4[hf * 2]);
                }
            }
        }

        // ---- causal mask (last two tiles only) ----
        if (kt >= KT - 2) {
            const int colBase = kt * 64 + (lane & 3) * 2;
            #pragma unroll
            for (int nt = 0; nt < 8; nt++)
                #pragma unroll
                for (int j = 0; j < 2; j++) {
                    const int c = colBase + nt * 8 + j;
                    if (c > r0g)     s[nt][j]     = -1e30f;
                    if (c > r0g + 8) s[nt][2 + j] = -1e30f;
                }
        }

        // ---- online softmax (base-2) ----
        float tm0 = -1e30f, tm1 = -1e30f;
        #pragma unroll
        for (int nt = 0; nt < 8; nt++) {
            tm0 = fmaxf(tm0, fmaxf(s[nt][0], s[nt][1]));
            tm1 = fmaxf(tm1, fmaxf(s[nt][2], s[nt][3]));
        }
        tm0 = fmaxf(tm0, __shfl_xor_sync(0xffffffffu, tm0, 1));
        tm0 = fmaxf(tm0, __shfl_xor_sync(0xffffffffu, tm0, 2));
        tm1 = fmaxf(tm1, __shfl_xor_sync(0xffffffffu, tm1, 1));
        tm1 = fmaxf(tm1, __shfl_xor_sync(0xffffffffu, tm1, 2));

        const float mn0 = fmaxf(m0, tm0), mn1 = fmaxf(m1, tm1);
        const float c0 = ex2f(m0 - mn0), c1 = ex2f(m1 - mn1);
        m0 = mn0; m1 = mn1;

        float sum0 = 0.f, sum1 = 0.f;
        #pragma unroll
        for (int nt = 0; nt < 8; nt++) {
            #pragma unroll
            for (int j = 0; j < 2; j++) {
                const float p0 = ex2f(s[nt][j] - mn0);
                const float p1 = ex2f(s[nt][2 + j] - mn1);
                s[nt][j] = p0;     sum0 += p0;
                s[nt][2 + j] = p1; sum1 += p1;
            }
        }
        l0 = l0 * c0 + sum0;
        l1 = l1 * c1 + sum1;

        #pragma unroll
        for (int nt = 0; nt < 8; nt++) {
            o[nt][0] *= c0; o[nt][1] *= c0;
            o[nt][2] *= c1; o[nt][3] *= c1;
        }

        // ---- O += P V ----
        #pragma unroll
        for (int kc = 0; kc < 4; kc++) {
            const float* s0 = s[2 * kc];
            const float* s1 = s[2 * kc + 1];
            uint32_t ph[4], pl[4];
            ph[0] = pack_hi_trunc(s0[0], s0[1]);
            ph[1] = pack_hi_trunc(s0[2], s0[3]);
            ph[2] = pack_hi_trunc(s1[0], s1[1]);
            ph[3] = pack_hi_trunc(s1[2], s1[3]);
            pl[0] = pack_bf16x2_rn(s0[0] - hi_trunc(s0[0]), s0[1] - hi_trunc(s0[1]));
            pl[1] = pack_bf16x2_rn(s0[2] - hi_trunc(s0[2]), s0[3] - hi_trunc(s0[3]));
            pl[2] = pack_bf16x2_rn(s1[0] - hi_trunc(s1[0]), s1[1] - hi_trunc(s1[1]));
            pl[3] = pack_bf16x2_rn(s1[2] - hi_trunc(s1[2]), s1[3] - hi_trunc(s1[3]));

            #pragma unroll
            for (int nt16 = 0; nt16 < 4; nt16++) {
                uint32_t vh4[4], vl4[4];
                const uint32_t ad = st + 2 * ATT_ARR_B + vBase +
                                    kc * 16 * APITCH_B + nt16 * 32;
                ldm_x4_t(vh4, ad);
                ldm_x4_t(vl4, ad + ATT_ARR_B);
                #pragma unroll
                for (int hf = 0; hf < 2; hf++) {
                    float* od = o[nt16 * 2 + hf];
                    mma_bf16(od, ph, &vh4[hf * 2]);
                    mma_bf16(od, pl, &vh4[hf * 2]);
                    mma_bf16(od, ph, &vl4[hf * 2]);
                }
            }
        }
    }

    // ---- finalize: row sums, normalize, write bf16 hi/lo to [B*T, D] ----
    l0 += __shfl_xor_sync(0xffffffffu, l0, 1);
    l0 += __shfl_xor_sync(0xffffffffu, l0, 2);
    l1 += __shfl_xor_sync(0xffffffffu, l1, 1);
    l1 += __shfl_xor_sync(0xffffffffu, l1, 2);
    const float inv0 = 1.f / l0, inv1 = 1.f / l1;

    const size_t row0 = (size_t)b * T_ + qb * 128 + wid * 16 + (lane >> 2);
    const size_t row1 = row0 + 8;
    const int colB = h * HD_ + (lane & 3) * 2;

    #pragma unroll
    for (int nt = 0; nt < 8; nt++) {
        const float v0 = o[nt][0] * inv0, v1 = o[nt][1] * inv0;
        const float v2 = o[nt][2] * inv1, v3 = o[nt][3] * inv1;
        const size_t i0 = row0 * D_ + colB + nt * 8;
        const size_t i1 = row1 * D_ + colB + nt * 8;
        reinterpret_cast<uint32_t*>(g_oh)[i0 >> 1] = pack_hi_trunc(v0, v1);
        reinterpret_cast<uint32_t*>(g_ol)[i0 >> 1] =
            pack_bf16x2_rn(v0 - hi_trunc(v0), v1 - hi_trunc(v1));
        reinterpret_cast<uint32_t*>(g_oh)[i1 >> 1] = pack_hi_trunc(v2, v3);
        reinterpret_cast<uint32_t*>(g_ol)[i1 >> 1] =
            pack_bf16x2_rn(v2 - hi_trunc(v2), v3 - hi_trunc(v3));
    }
}

// ---------------------------------------------------------------------------
// Conversion kernels
// ---------------------------------------------------------------------------
__global__ __launch_bounds__(256) void split_x_kernel(const float* __restrict__ src)
{
    const int i = blockIdx.x * 256 + threadIdx.x;
    const float v = src[i];
    const __nv_bfloat16 hv = __float2bfloat16(v);
    g_xh[i] = hv;
    g_xl[i] = __float2bfloat16(v - __bfloat162float(hv));
}

__global__ __launch_bounds__(256) void wsplit_kernel(
    const float* __restrict__ wq, const float* __restrict__ wk,
    const float* __restrict__ wv, const float* __restrict__ wo)
{
    __shared__ float tile[32][33];
    const int z = blockIdx.z;
    const float* w = (z == 0) ? wq : (z == 1) ? wk : (z == 2) ? wv : wo;
    const int nB = blockIdx.x * 32, kB = blockIdx.y * 32;
    const int tx = threadIdx.x & 31, ty = threadIdx.x >> 5;

    #pragma unroll
    for (int r = ty; r < 32; r += 8)
        tile[r][tx] = w[(size_t)(kB + r) * D_ + nB + tx];
    __syncthreads();
    #pragma unroll
    for (int r = ty; r < 32; r += 8) {
        const float v = tile[tx][r];
        const size_t di = ((size_t)z << 20) + (size_t)(nB + r) * D_ + kB + tx;
        const __nv_bfloat16 hv = __float2bfloat16(v);
        g_wth[di] = hv;
        g_wtl[di] = __float2bfloat16(v - __bfloat162float(hv));
    }
}

// ---------------------------------------------------------------------------
extern "C" void kernel_launch(void* const* d_in, const int* in_sizes, int n_in,
                              void* d_out, int out_size)
{
    const float* x  = (const float*)d_in[0];
    const float* wq = (const float*)d_in[1];
    const float* bq = (const float*)d_in[2];
    const float* wk = (const float*)d_in[3];
    const float* bk = (const float*)d_in[4];
    const float* wv = (const float*)d_in[5];
    const float* bv = (const float*)d_in[6];
    const float* wo = (const float*)d_in[7];
    const float* bo = (const float*)d_in[8];
    float* out = (float*)d_out;

    static bool attrSet = false;
    if (!attrSet) {
        cudaFuncSetAttribute(gemm_mma<0>,
                             cudaFuncAttributeMaxDynamicSharedMemorySize, GEMM_SMEM);
        cudaFuncSetAttribute(gemm_mma<1>,
                             cudaFuncAttributeMaxDynamicSharedMemorySize, GEMM_SMEM);
        cudaFuncSetAttribute(attn_mma,
                             cudaFuncAttributeMaxDynamicSharedMemorySize, ATT_SMEM);
        attrSet = true;
    }

    void *pxh, *pxl, *poh, *pol;
    cudaGetSymbolAddress(&pxh, g_xh);
    cudaGetSymbolAddress(&pxl, g_xl);
    cudaGetSymbolAddress(&poh, g_oh);
    cudaGetSymbolAddress(&pol, g_ol);

    const int nElem = M_ * D_;

    // 1) convert inputs to bf16 hi/lo
    split_x_kernel<<<nElem / 256, 256>>>(x);
    wsplit_kernel<<<dim3(32, 32, 4), 256>>>(wq, wk, wv, wo);

    // 2) QKV projections -> bf16 hi/lo [B,H,T,HD]; Q pre-scaled by 0.125*log2e
    gemm_mma<0><<<dim3(8, 64, 3), 256, GEMM_SMEM>>>(
        (const __nv_bfloat16*)pxh, (const __nv_bfloat16*)pxl,
        bq, bk, bv, nullptr, 0);

    // 3) tensor-core causal flash attention -> g_oh/g_ol [B*T, D]
    attn_mma<<<dim3(T_ / 128, H_, B_), 256, ATT_SMEM>>>();

    // 4) output projection
    gemm_mma<1><<<dim3(8, 64, 1), 256, GEMM_SMEM>>>(
        (const __nv_bfloat16*)poh, (const __nv_bfloat16*)pol,
        bo, bo, bo, out, 3);
}

// round 5
// speedup vs baseline: 4.2959x; 1.1131x over previous
#include <cuda_runtime.h>
#include <cuda_bf16.h>
#include <cstdint>
#include <cstddef>

// ---------------------------------------------------------------------------
// Problem constants
// ---------------------------------------------------------------------------
constexpr int B_  = 4;
constexpr int T_  = 2048;
constexpr int D_  = 1024;
constexpr int H_  = 16;
constexpr int HD_ = 64;
constexpr int M_  = B_ * T_;   // 8192

// 0.125 * log2(e): folded into Q so softmax uses exp2
constexpr float QSCALE = 0.18033688011112042f;

// ---------------------------------------------------------------------------
// Device scratch (bf16 hi/lo everywhere; no fp32 intermediates)
// ---------------------------------------------------------------------------
__device__ __align__(128) __nv_bfloat16 g_xh[(size_t)M_ * D_];
__device__ __align__(128) __nv_bfloat16 g_xl[(size_t)M_ * D_];
__device__ __align__(128) __nv_bfloat16 g_oh[(size_t)M_ * D_];   // [B*T, D]
__device__ __align__(128) __nv_bfloat16 g_ol[(size_t)M_ * D_];
// QKV in [B, H, T, HD]
__device__ __align__(128) __nv_bfloat16 g_qh[(size_t)M_ * D_];
__device__ __align__(128) __nv_bfloat16 g_ql[(size_t)M_ * D_];
__device__ __align__(128) __nv_bfloat16 g_kh[(size_t)M_ * D_];
__device__ __align__(128) __nv_bfloat16 g_kl[(size_t)M_ * D_];
__device__ __align__(128) __nv_bfloat16 g_vh[(size_t)M_ * D_];
__device__ __align__(128) __nv_bfloat16 g_vl[(size_t)M_ * D_];
// 4 weights transposed to [N, K] bf16 hi/lo, z: 0..3 -> wq,wk,wv,wo
__device__ __align__(128) __nv_bfloat16 g_wth[(size_t)4 * D_ * D_];
__device__ __align__(128) __nv_bfloat16 g_wtl[(size_t)4 * D_ * D_];

// ---------------------------------------------------------------------------
// PTX helpers (generic-target legal: sm_80+ / sm_75+)
// ---------------------------------------------------------------------------
__device__ __forceinline__ uint32_t smem_u32(const void* p) {
    uint32_t a;
    asm("{ .reg .u64 t; cvta.to.shared.u64 t, %1; cvt.u32.u64 %0, t; }"
        : "=r"(a) : "l"(p));
    return a;
}
__device__ __forceinline__ void cp16(uint32_t saddr, const void* gaddr) {
    asm volatile("cp.async.cg.shared.global [%0], [%1], 16;"
                 :: "r"(saddr), "l"(gaddr));
}
__device__ __forceinline__ void cp_commit() {
    asm volatile("cp.async.commit_group;");
}
template <int N>
__device__ __forceinline__ void cp_wait() {
    asm volatile("cp.async.wait_group %0;" :: "n"(N));
}
__device__ __forceinline__ void ldm_x4(uint32_t* r, uint32_t addr) {
    asm volatile("ldmatrix.sync.aligned.m8n8.x4.shared.b16 {%0,%1,%2,%3}, [%4];"
                 : "=r"(r[0]), "=r"(r[1]), "=r"(r[2]), "=r"(r[3]) : "r"(addr));
}
__device__ __forceinline__ void ldm_x4_t(uint32_t* r, uint32_t addr) {
    asm volatile("ldmatrix.sync.aligned.m8n8.x4.trans.shared.b16 {%0,%1,%2,%3}, [%4];"
                 : "=r"(r[0]), "=r"(r[1]), "=r"(r[2]), "=r"(r[3]) : "r"(addr));
}
__device__ __forceinline__ void mma_bf16(float* c, const uint32_t* a,
                                         const uint32_t* b) {
    asm volatile(
        "mma.sync.aligned.m16n8k16.row.col.f32.bf16.bf16.f32 "
        "{%0,%1,%2,%3}, {%4,%5,%6,%7}, {%8,%9}, {%0,%1,%2,%3};"
        : "+f"(c[0]), "+f"(c[1]), "+f"(c[2]), "+f"(c[3])
        : "r"(a[0]), "r"(a[1]), "r"(a[2]), "r"(a[3]), "r"(b[0]), "r"(b[1]));
}
__device__ __forceinline__ float ex2f(float x) {
    float r;
    asm("ex2.approx.ftz.f32 %0, %1;" : "=f"(r) : "f"(x));
    return r;
}
__device__ __forceinline__ float hi_trunc(float v) {
    return __uint_as_float(__float_as_uint(v) & 0xFFFF0000u);
}
__device__ __forceinline__ uint32_t pack_hi_trunc(float lo, float hi) {
    return (__float_as_uint(hi) & 0xFFFF0000u) | (__float_as_uint(lo) >> 16);
}
__device__ __forceinline__ uint32_t pack_bf16x2_rn(float lo, float hi) {
    uint32_t r;
    asm("cvt.rn.bf16x2.f32 %0, %1, %2;" : "=r"(r) : "f"(hi), "f"(lo));
    return r;
}

// ---------------------------------------------------------------------------
// HMMA GEMM (bf16x3, fp32 accum). 256 thr = 8 warps (4Mx2N), warp 32x64,
// BK=32, 2-stage cp.async, 2 CTAs/SM.
// MODE 0: C = x @ W^T + bias -> q/k/v bf16 hi/lo, [B,H,T,HD]; Q pre-scaled.
// MODE 1: C = attnO @ wo^T + bias -> out fp32 [M, D].
// ---------------------------------------------------------------------------
constexpr int BK      = 32;
constexpr int PITCH_B = (BK + 8) * 2;                 // 80 B per smem row
constexpr int ARR_B   = 128 * PITCH_B;                // 10240 B
constexpr int STAGE_B = 4 * ARR_B;                    // 40960 B
constexpr int NSTG    = 2;
constexpr int GEMM_SMEM = NSTG * STAGE_B;             // 81920 B -> 2 CTAs/SM
constexpr int KT_G    = D_ / BK;                      // 32

template <int MODE>
__global__ __launch_bounds__(256, 2)
void gemm_mma(const __nv_bfloat16* __restrict__ Ah,
              const __nv_bfloat16* __restrict__ Al,
              const float* __restrict__ b0, const float* __restrict__ b1,
              const float* __restrict__ b2,
              float* __restrict__ out, int zbase)
{
    extern __shared__ __align__(128) char smem[];
    const uint32_t sb = smem_u32(smem);

    const int tid  = threadIdx.x;
    const int wid  = tid >> 5;
    const int lane = tid & 31;
    const int wm   = (wid & 3) * 32;
    const int wn   = (wid >> 2) * 64;

    const int mBase = blockIdx.y * 128;
    const int nBase = blockIdx.x * 128;
    const int z     = zbase + blockIdx.z;

    const __nv_bfloat16* Bh = g_wth + ((size_t)z << 20);
    const __nv_bfloat16* Bl = g_wtl + ((size_t)z << 20);

    const int c0r = tid >> 2,         c0q = tid & 3;
    const int c1r = (tid + 256) >> 2, c1q = (tid + 256) & 3;

    auto load_stage = [&](int stg, int kt) {
        const uint32_t st = sb + stg * STAGE_B;
        const int bk = kt * BK;
        {
            const size_t g0 = (size_t)(mBase + c0r) * D_ + bk + c0q * 8;
            const size_t g1 = (size_t)(mBase + c1r) * D_ + bk + c1q * 8;
            const uint32_t s0 = c0r * PITCH_B + c0q * 16;
            const uint32_t s1 = c1r * PITCH_B + c1q * 16;
            cp16(st + s0,         Ah + g0);
            cp16(st + s1,         Ah + g1);
            cp16(st + ARR_B + s0, Al + g0);
            cp16(st + ARR_B + s1, Al + g1);
        }
        {
            const size_t g0 = (size_t)(nBase + c0r) * D_ + bk + c0q * 8;
            const size_t g1 = (size_t)(nBase + c1r) * D_ + bk + c1q * 8;
            const uint32_t s0 = c0r * PITCH_B + c0q * 16;
            const uint32_t s1 = c1r * PITCH_B + c1q * 16;
            cp16(st + 2 * ARR_B + s0, Bh + g0);
            cp16(st + 2 * ARR_B + s1, Bh + g1);
            cp16(st + 3 * ARR_B + s0, Bl + g0);
            cp16(st + 3 * ARR_B + s1, Bl + g1);
        }
        cp_commit();
    };

    float acc[2][8][4];
    #pragma unroll
    for (int mi = 0; mi < 2; mi++)
        #pragma unroll
        for (int ni = 0; ni < 8; ni++)
            #pragma unroll
            for (int r = 0; r < 4; r++) acc[mi][ni][r] = 0.f;

    load_stage(0, 0);
    load_stage(1, 1);

    const uint32_t aRowOff =
        (uint32_t)(wm + (lane & 7) + ((lane >> 3) & 1) * 8) * PITCH_B +
        ((lane >> 4) & 1) * 16;
    const uint32_t bRowOff =
        (uint32_t)(wn + ((lane >> 4) & 1) * 8 + (lane & 7)) * PITCH_B +
        ((lane >> 3) & 1) * 16;

    cp_wait<1>();           // stage 0 ready
    __syncthreads();

    #pragma unroll 1
    for (int kt = 0; kt < KT_G; kt++) {
        const uint32_t st  = sb + (kt & 1) * STAGE_B;
        const uint32_t sAh = st;
        const uint32_t sAl = st + ARR_B;
        const uint32_t sBh = st + 2 * ARR_B;
        const uint32_t sBl = st + 3 * ARR_B;

        #pragma unroll
        for (int ks = 0; ks < 2; ks++) {
            const uint32_t kOff = ks * 32;

            uint32_t ah[2][4], al[2][4];
            #pragma unroll
            for (int mi = 0; mi < 2; mi++) {
                const uint32_t off = aRowOff + (uint32_t)mi * 16 * PITCH_B + kOff;
                ldm_x4(ah[mi], sAh + off);
                ldm_x4(al[mi], sAl + off);
            }
            #pragma unroll
            for (int p = 0; p < 4; p++) {
                uint32_t bh4[4], bl4[4];
                const uint32_t off = bRowOff + (uint32_t)p * 16 * PITCH_B + kOff;
                ldm_x4(bh4, sBh + off);
                ldm_x4(bl4, sBl + off);
                #pragma unroll
                for (int mi = 0; mi < 2; mi++)
                    #pragma unroll
                    for (int hf = 0; hf < 2; hf++) {
                        const int ni = p * 2 + hf;
                        mma_bf16(acc[mi][ni], ah[mi], &bh4[hf * 2]);
                        mma_bf16(acc[mi][ni], ah[mi], &bl4[hf * 2]);
                        mma_bf16(acc[mi][ni], al[mi], &bh4[hf * 2]);
                    }
            }
        }
        __syncthreads();
        if (kt + 2 < KT_G) {
            load_stage(kt & 1, kt + 2);
            cp_wait<1>();
            __syncthreads();
        } else if (kt + 1 < KT_G) {
            cp_wait<0>();
            __syncthreads();
        }
    }

    // --- epilogue ---
    const float* bias = (MODE == 0)
        ? (blockIdx.z == 0 ? b0 : blockIdx.z == 1 ? b1 : b2) : b0;

    __nv_bfloat16 *dh = nullptr, *dl = nullptr;
    float scale = 1.f;
    if (MODE == 0) {
        if (blockIdx.z == 0)      { dh = g_qh; dl = g_ql; scale = QSCALE; }
        else if (blockIdx.z == 1) { dh = g_kh; dl = g_kl; }
        else                      { dh = g_vh; dl = g_vl; }
    }

    #pragma unroll
    for (int mi = 0; mi < 2; mi++) {
        #pragma unroll
        for (int ni = 0; ni < 8; ni++) {
            const int n0 = nBase + wn + ni * 8 + (lane & 3) * 2;
            const float bv0 = __ldg(bias + n0), bv1 = __ldg(bias + n0 + 1);
            #pragma unroll
            for (int rr = 0; rr < 2; rr++) {
                const int m = mBase + wm + mi * 16 + (lane >> 2) + rr * 8;
                float v0 = acc[mi][ni][rr * 2 + 0] + bv0;
                float v1 = acc[mi][ni][rr * 2 + 1] + bv1;
                if (MODE == 0) {
                    v0 *= scale; v1 *= scale;
                    const int bb = m >> 11, tt = m & 2047;
                    const int hh = n0 >> 6, hd = n0 & 63;
                    const size_t idx =
                        ((((size_t)bb * H_ + hh) * T_ + tt) << 6) + hd;
                    reinterpret_cast<uint32_t*>(dh)[idx >> 1] =
                        pack_hi_trunc(v0, v1);
                    reinterpret_cast<uint32_t*>(dl)[idx >> 1] =
                        pack_bf16x2_rn(v0 - hi_trunc(v0), v1 - hi_trunc(v1));
                } else {
                    *reinterpret_cast<float2*>(out + (size_t)m * D_ + n0) =
                        make_float2(v0, v1);
                }
            }
        }
    }
}

// ---------------------------------------------------------------------------
// Tensor-core causal flash attention (bf16x3, fp32 accum, exp2 softmax).
// CTA: 128 queries, 8 warps; key tiles of 64, double-buffered; Q staged
// through the stage-1 buffer (register-resident afterwards) -> 73.7 KB smem,
// 2 CTAs/SM.
// ---------------------------------------------------------------------------
constexpr int APITCH_B    = 144;                    // 64 bf16 + 8 pad, bytes
constexpr int ATT_ARR_B   = 64 * APITCH_B;          // 9216 per K/V array
constexpr int ATT_STAGE_B = 4 * ATT_ARR_B;          // 36864 (kh,kl,vh,vl)
constexpr int ATT_SMEM    = 2 * ATT_STAGE_B;        // 73728 -> 2 CTAs/SM

__global__ __launch_bounds__(256, 2)
void attn_mma()
{
    extern __shared__ __align__(128) char smem[];
    const uint32_t sb = smem_u32(smem);

    const int tid  = threadIdx.x;
    const int wid  = tid >> 5;
    const int lane = tid & 31;

    const int qb = (gridDim.x - 1) - blockIdx.x;     // largest-first
    const int h  = blockIdx.y, b = blockIdx.z;
    const size_t bh = ((size_t)(b * H_ + h)) * T_ * HD_;

    const __nv_bfloat16* Qh = g_qh + bh + (size_t)qb * 128 * HD_;
    const __nv_bfloat16* Ql = g_ql + bh + (size_t)qb * 128 * HD_;
    const __nv_bfloat16* Kh = g_kh + bh;
    const __nv_bfloat16* Kl = g_kl + bh;
    const __nv_bfloat16* Vh = g_vh + bh;
    const __nv_bfloat16* Vl = g_vl + bh;

    // ---- Q loads into stage-1 buffer (group 0): qh rows 0..127, then ql ----
    const uint32_t qsb = sb + ATT_STAGE_B;
    #pragma unroll
    for (int i = 0; i < 8; i++) {
        const int c = i * 256 + tid;
        const int arr = c >> 10, row = (c >> 3) & 127, q8 = c & 7;
        const __nv_bfloat16* src = (arr ? Ql : Qh) + (size_t)row * HD_ + q8 * 8;
        cp16(qsb + arr * (2 * ATT_ARR_B) + row * APITCH_B + q8 * 16, src);
    }
    cp_commit();

    const int KT = 2 * qb + 2;   // always >= 2

    auto load_kv = [&](int stg, int kt) {
        const uint32_t base = sb + stg * ATT_STAGE_B;
        #pragma unroll
        for (int i = 0; i < 8; i++) {
            const int c = i * 256 + tid;
            const int arr = c >> 9, row = (c >> 3) & 63, q8 = c & 7;
            const __nv_bfloat16* g =
                (arr == 0) ? Kh : (arr == 1) ? Kl : (arr == 2) ? Vh : Vl;
            cp16(base + arr * ATT_ARR_B + row * APITCH_B + q8 * 16,
                 g + (size_t)(kt * 64 + row) * HD_ + q8 * 8);
        }
        cp_commit();
    };
    load_kv(0, 0);   // group 1

    // ---- Q fragments to registers (Q group done; KV0 may still fly) ----
    cp_wait<1>();
    __syncthreads();
    uint32_t qfh[4][4], qfl[4][4];
    {
        const uint32_t aoff = qsb +
            (uint32_t)(wid * 16 + (lane & 7) + ((lane >> 3) & 1) * 8) * APITCH_B +
            ((lane >> 4) & 1) * 16;
        #pragma unroll
        for (int kc = 0; kc < 4; kc++) {
            ldm_x4(qfh[kc], aoff + kc * 32);
            ldm_x4(qfl[kc], aoff + 2 * ATT_ARR_B + kc * 32);
        }
    }
    __syncthreads();           // all warps done reading stage-1 region
    load_kv(1, 1);             // overwrite it with KV tile 1
    cp_wait<1>();              // KV0 ready
    __syncthreads();

    float o[8][4];
    #pragma unroll
    for (int nt = 0; nt < 8; nt++)
        #pragma unroll
        for (int r = 0; r < 4; r++) o[nt][r] = 0.f;
    float m0 = -1e30f, m1 = -1e30f, l0 = 0.f, l1 = 0.f;

    const int r0g = qb * 128 + wid * 16 + (lane >> 2);

    const uint32_t bBase =
        (uint32_t)(((lane >> 4) & 1) * 8 + (lane & 7)) * APITCH_B +
        ((lane >> 3) & 1) * 16;
    const uint32_t vBase =
        (uint32_t)((lane & 7) + ((lane >> 3) & 1) * 8) * APITCH_B +
        ((lane >> 4) & 1) * 16;

    #pragma unroll 1
    for (int kt = 0; kt < KT; kt++) {
        const uint32_t st = sb + (kt & 1) * ATT_STAGE_B;

        // ---- S = Q K^T ----
        float s[8][4];
        #pragma unroll
        for (int nt = 0; nt < 8; nt++)
            #pragma unroll
            for (int r = 0; r < 4; r++) s[nt][r] = 0.f;

        #pragma unroll
        for (int kc = 0; kc < 4; kc++) {
            #pragma unroll
            for (int nt16 = 0; nt16 < 4; nt16++) {
                uint32_t kh4[4], kl4[4];
                const uint32_t ad = st + bBase + nt16 * 16 * APITCH_B + kc * 32;
                ldm_x4(kh4, ad);
                ldm_x4(kl4, ad + ATT_ARR_B);
                #pragma unroll
                for (int hf = 0; hf < 2; hf++) {
                    float* sd = s[nt16 * 2 + hf];
                    mma_bf16(sd, qfh[kc], &kh4[hf * 2]);
                    mma_bf16(sd, qfl[kc], &kh4[hf * 2]);
                    mma_bf16(sd, qfh[kc], &kl4[hf * 2]);
                }
            }
        }

        // ---- causal mask (last two tiles only) ----
        if (kt >= KT - 2) {
            const int colBase = kt * 64 + (lane & 3) * 2;
            #pragma unroll
            for (int nt = 0; nt < 8; nt++)
                #pragma unroll
                for (int j = 0; j < 2; j++) {
                    const int c = colBase + nt * 8 + j;
                    if (c > r0g)     s[nt][j]     = -1e30f;
                    if (c > r0g + 8) s[nt][2 + j] = -1e30f;
                }
        }

        // ---- online softmax (base-2) ----
        float tm0 = -1e30f, tm1 = -1e30f;
        #pragma unroll
        for (int nt = 0; nt < 8; nt++) {
            tm0 = fmaxf(tm0, fmaxf(s[nt][0], s[nt][1]));
            tm1 = fmaxf(tm1, fmaxf(s[nt][2], s[nt][3]));
        }
        tm0 = fmaxf(tm0, __shfl_xor_sync(0xffffffffu, tm0, 1));
        tm0 = fmaxf(tm0, __shfl_xor_sync(0xffffffffu, tm0, 2));
        tm1 = fmaxf(tm1, __shfl_xor_sync(0xffffffffu, tm1, 1));
        tm1 = fmaxf(tm1, __shfl_xor_sync(0xffffffffu, tm1, 2));

        const float mn0 = fmaxf(m0, tm0), mn1 = fmaxf(m1, tm1);
        const float c0 = ex2f(m0 - mn0), c1 = ex2f(m1 - mn1);
        m0 = mn0; m1 = mn1;

        float sum0 = 0.f, sum1 = 0.f;
        #pragma unroll
        for (int nt = 0; nt < 8; nt++) {
            #pragma unroll
            for (int j = 0; j < 2; j++) {
                const float p0 = ex2f(s[nt][j] - mn0);
                const float p1 = ex2f(s[nt][2 + j] - mn1);
                s[nt][j] = p0;     sum0 += p0;
                s[nt][2 + j] = p1; sum1 += p1;
            }
        }
        l0 = l0 * c0 + sum0;
        l1 = l1 * c1 + sum1;

        #pragma unroll
        for (int nt = 0; nt < 8; nt++) {
            o[nt][0] *= c0; o[nt][1] *= c0;
            o[nt][2] *= c1; o[nt][3] *= c1;
        }

        // ---- O += P V ----
        #pragma unroll
        for (int kc = 0; kc < 4; kc++) {
            const float* s0 = s[2 * kc];
            const float* s1 = s[2 * kc + 1];
            uint32_t ph[4], pl[4];
            ph[0] = pack_hi_trunc(s0[0], s0[1]);
            ph[1] = pack_hi_trunc(s0[2], s0[3]);
            ph[2] = pack_hi_trunc(s1[0], s1[1]);
            ph[3] = pack_hi_trunc(s1[2], s1[3]);
            pl[0] = pack_bf16x2_rn(s0[0] - hi_trunc(s0[0]), s0[1] - hi_trunc(s0[1]));
            pl[1] = pack_bf16x2_rn(s0[2] - hi_trunc(s0[2]), s0[3] - hi_trunc(s0[3]));
            pl[2] = pack_bf16x2_rn(s1[0] - hi_trunc(s1[0]), s1[1] - hi_trunc(s1[1]));
            pl[3] = pack_bf16x2_rn(s1[2] - hi_trunc(s1[2]), s1[3] - hi_trunc(s1[3]));

            #pragma unroll
            for (int nt16 = 0; nt16 < 4; nt16++) {
                uint32_t vh4[4], vl4[4];
                const uint32_t ad = st + 2 * ATT_ARR_B + vBase +
                                    kc * 16 * APITCH_B + nt16 * 32;
                ldm_x4_t(vh4, ad);
                ldm_x4_t(vl4, ad + ATT_ARR_B);
                #pragma unroll
                for (int hf = 0; hf < 2; hf++) {
                    float* od = o[nt16 * 2 + hf];
                    mma_bf16(od, ph, &vh4[hf * 2]);
                    mma_bf16(od, pl, &vh4[hf * 2]);
                    mma_bf16(od, ph, &vl4[hf * 2]);
                }
            }
        }

        // ---- advance pipeline ----
        __syncthreads();
        if (kt + 2 < KT) {
            load_kv(kt & 1, kt + 2);
            cp_wait<1>();
            __syncthreads();
        } else if (kt + 1 < KT) {
            cp_wait<0>();
            __syncthreads();
        }
    }

    // ---- finalize ----
    l0 += __shfl_xor_sync(0xffffffffu, l0, 1);
    l0 += __shfl_xor_sync(0xffffffffu, l0, 2);
    l1 += __shfl_xor_sync(0xffffffffu, l1, 1);
    l1 += __shfl_xor_sync(0xffffffffu, l1, 2);
    const float inv0 = 1.f / l0, inv1 = 1.f / l1;

    const size_t row0 = (size_t)b * T_ + qb * 128 + wid * 16 + (lane >> 2);
    const size_t row1 = row0 + 8;
    const int colB = h * HD_ + (lane & 3) * 2;

    #pragma unroll
    for (int nt = 0; nt < 8; nt++) {
        const float v0 = o[nt][0] * inv0, v1 = o[nt][1] * inv0;
        const float v2 = o[nt][2] * inv1, v3 = o[nt][3] * inv1;
        const size_t i0 = row0 * D_ + colB + nt * 8;
        const size_t i1 = row1 * D_ + colB + nt * 8;
        reinterpret_cast<uint32_t*>(g_oh)[i0 >> 1] = pack_hi_trunc(v0, v1);
        reinterpret_cast<uint32_t*>(g_ol)[i0 >> 1] =
            pack_bf16x2_rn(v0 - hi_trunc(v0), v1 - hi_trunc(v1));
        reinterpret_cast<uint32_t*>(g_oh)[i1 >> 1] = pack_hi_trunc(v2, v3);
        reinterpret_cast<uint32_t*>(g_ol)[i1 >> 1] =
            pack_bf16x2_rn(v2 - hi_trunc(v2), v3 - hi_trunc(v3));
    }
}

// ---------------------------------------------------------------------------
// Conversion kernels
// ---------------------------------------------------------------------------
__global__ __launch_bounds__(256) void split_x_kernel(const float* __restrict__ src)
{
    const int i = blockIdx.x * 256 + threadIdx.x;
    const float v = src[i];
    const __nv_bfloat16 hv = __float2bfloat16(v);
    g_xh[i] = hv;
    g_xl[i] = __float2bfloat16(v - __bfloat162float(hv));
}

__global__ __launch_bounds__(256) void wsplit_kernel(
    const float* __restrict__ wq, const float* __restrict__ wk,
    const float* __restrict__ wv, const float* __restrict__ wo)
{
    __shared__ float tile[32][33];
    const int z = blockIdx.z;
    const float* w = (z == 0) ? wq : (z == 1) ? wk : (z == 2) ? wv : wo;
    const int nB = blockIdx.x * 32, kB = blockIdx.y * 32;
    const int tx = threadIdx.x & 31, ty = threadIdx.x >> 5;

    #pragma unroll
    for (int r = ty; r < 32; r += 8)
        tile[r][tx] = w[(size_t)(kB + r) * D_ + nB + tx];
    __syncthreads();
    #pragma unroll
    for (int r = ty; r < 32; r += 8) {
        const float v = tile[tx][r];
        const size_t di = ((size_t)z << 20) + (size_t)(nB + r) * D_ + kB + tx;
        const __nv_bfloat16 hv = __float2bfloat16(v);
        g_wth[di] = hv;
        g_wtl[di] = __float2bfloat16(v - __bfloat162float(hv));
    }
}

// ---------------------------------------------------------------------------
extern "C" void kernel_launch(void* const* d_in, const int* in_sizes, int n_in,
                              void* d_out, int out_size)
{
    const float* x  = (const float*)d_in[0];
    const float* wq = (const float*)d_in[1];
    const float* bq = (const float*)d_in[2];
    const float* wk = (const float*)d_in[3];
    const float* bk = (const float*)d_in[4];
    const float* wv = (const float*)d_in[5];
    const float* bv = (const float*)d_in[6];
    const float* wo = (const float*)d_in[7];
    const float* bo = (const float*)d_in[8];
    float* out = (float*)d_out;

    static bool attrSet = false;
    if (!attrSet) {
        cudaFuncSetAttribute(gemm_mma<0>,
                             cudaFuncAttributeMaxDynamicSharedMemorySize, GEMM_SMEM);
        cudaFuncSetAttribute(gemm_mma<1>,
                             cudaFuncAttributeMaxDynamicSharedMemorySize, GEMM_SMEM);
        cudaFuncSetAttribute(attn_mma,
                             cudaFuncAttributeMaxDynamicSharedMemorySize, ATT_SMEM);
        attrSet = true;
    }

    void *pxh, *pxl, *poh, *pol;
    cudaGetSymbolAddress(&pxh, g_xh);
    cudaGetSymbolAddress(&pxl, g_xl);
    cudaGetSymbolAddress(&poh, g_oh);
    cudaGetSymbolAddress(&pol, g_ol);

    const int nElem = M_ * D_;

    // 1) convert inputs to bf16 hi/lo
    split_x_kernel<<<nElem / 256, 256>>>(x);
    wsplit_kernel<<<dim3(32, 32, 4), 256>>>(wq, wk, wv, wo);

    // 2) QKV projections -> bf16 hi/lo [B,H,T,HD]; Q pre-scaled by 0.125*log2e
    gemm_mma<0><<<dim3(8, 64, 3), 256, GEMM_SMEM>>>(
        (const __nv_bfloat16*)pxh, (const __nv_bfloat16*)pxl,
        bq, bk, bv, nullptr, 0);

    // 3) tensor-core causal flash attention -> g_oh/g_ol [B*T, D]
    attn_mma<<<dim3(T_ / 128, H_, B_), 256, ATT_SMEM>>>();

    // 4) output projection
    gemm_mma<1><<<dim3(8, 64, 1), 256, GEMM_SMEM>>>(
        (const __nv_bfloat16*)poh, (const __nv_bfloat16*)pol,
        bo, bo, bo, out, 3);
}

// round 6
// speedup vs baseline: 4.3555x; 1.0139x over previous
#include <cuda_runtime.h>
#include <cuda_bf16.h>
#include <cstdint>
#include <cstddef>

// ---------------------------------------------------------------------------
// Problem constants
// ---------------------------------------------------------------------------
constexpr int B_  = 4;
constexpr int T_  = 2048;
constexpr int D_  = 1024;
constexpr int H_  = 16;
constexpr int HD_ = 64;
constexpr int M_  = B_ * T_;   // 8192

// 0.125 * log2(e): folded into Q so softmax uses exp2
constexpr float QSCALE = 0.18033688011112042f;

// ---------------------------------------------------------------------------
// Device scratch (bf16 hi/lo everywhere; no fp32 intermediates)
// ---------------------------------------------------------------------------
__device__ __align__(128) __nv_bfloat16 g_xh[(size_t)M_ * D_];
__device__ __align__(128) __nv_bfloat16 g_xl[(size_t)M_ * D_];
__device__ __align__(128) __nv_bfloat16 g_oh[(size_t)M_ * D_];   // [B*T, D]
__device__ __align__(128) __nv_bfloat16 g_ol[(size_t)M_ * D_];
// QKV in [B, H, T, HD]
__device__ __align__(128) __nv_bfloat16 g_qh[(size_t)M_ * D_];
__device__ __align__(128) __nv_bfloat16 g_ql[(size_t)M_ * D_];
__device__ __align__(128) __nv_bfloat16 g_kh[(size_t)M_ * D_];
__device__ __align__(128) __nv_bfloat16 g_kl[(size_t)M_ * D_];
__device__ __align__(128) __nv_bfloat16 g_vh[(size_t)M_ * D_];
__device__ __align__(128) __nv_bfloat16 g_vl[(size_t)M_ * D_];
// 4 weights transposed to [N, K] bf16 hi/lo, z: 0..3 -> wq,wk,wv,wo
__device__ __align__(128) __nv_bfloat16 g_wth[(size_t)4 * D_ * D_];
__device__ __align__(128) __nv_bfloat16 g_wtl[(size_t)4 * D_ * D_];

// ---------------------------------------------------------------------------
// PTX helpers (generic-target legal: sm_80+ / sm_75+)
// ---------------------------------------------------------------------------
__device__ __forceinline__ uint32_t smem_u32(const void* p) {
    uint32_t a;
    asm("{ .reg .u64 t; cvta.to.shared.u64 t, %1; cvt.u32.u64 %0, t; }"
        : "=r"(a) : "l"(p));
    return a;
}
__device__ __forceinline__ void cp16(uint32_t saddr, const void* gaddr) {
    asm volatile("cp.async.cg.shared.global [%0], [%1], 16;"
                 :: "r"(saddr), "l"(gaddr));
}
__device__ __forceinline__ void cp_commit() {
    asm volatile("cp.async.commit_group;");
}
template <int N>
__device__ __forceinline__ void cp_wait() {
    asm volatile("cp.async.wait_group %0;" :: "n"(N));
}
__device__ __forceinline__ void ldm_x4(uint32_t* r, uint32_t addr) {
    asm volatile("ldmatrix.sync.aligned.m8n8.x4.shared.b16 {%0,%1,%2,%3}, [%4];"
                 : "=r"(r[0]), "=r"(r[1]), "=r"(r[2]), "=r"(r[3]) : "r"(addr));
}
__device__ __forceinline__ void ldm_x4_t(uint32_t* r, uint32_t addr) {
    asm volatile("ldmatrix.sync.aligned.m8n8.x4.trans.shared.b16 {%0,%1,%2,%3}, [%4];"
                 : "=r"(r[0]), "=r"(r[1]), "=r"(r[2]), "=r"(r[3]) : "r"(addr));
}
__device__ __forceinline__ void mma_bf16(float* c, const uint32_t* a,
                                         const uint32_t* b) {
    asm volatile(
        "mma.sync.aligned.m16n8k16.row.col.f32.bf16.bf16.f32 "
        "{%0,%1,%2,%3}, {%4,%5,%6,%7}, {%8,%9}, {%0,%1,%2,%3};"
        : "+f"(c[0]), "+f"(c[1]), "+f"(c[2]), "+f"(c[3])
        : "r"(a[0]), "r"(a[1]), "r"(a[2]), "r"(a[3]), "r"(b[0]), "r"(b[1]));
}
__device__ __forceinline__ float ex2f(float x) {
    float r;
    asm("ex2.approx.ftz.f32 %0, %1;" : "=f"(r) : "f"(x));
    return r;
}
__device__ __forceinline__ float hi_trunc(float v) {
    return __uint_as_float(__float_as_uint(v) & 0xFFFF0000u);
}
__device__ __forceinline__ uint32_t pack_hi_trunc(float lo, float hi) {
    return (__float_as_uint(hi) & 0xFFFF0000u) | (__float_as_uint(lo) >> 16);
}
__device__ __forceinline__ uint32_t pack_bf16x2_rn(float lo, float hi) {
    uint32_t r;
    asm("cvt.rn.bf16x2.f32 %0, %1, %2;" : "=r"(r) : "f"(hi), "f"(lo));
    return r;
}

// ---------------------------------------------------------------------------
// HMMA GEMM (bf16x3, fp32 accum). 256 thr = 8 warps (4Mx2N), warp 32x64,
// BK=32, 2-stage cp.async, 2 CTAs/SM. Split-term MMA passes: each pass is
// 16 independent MMAs (distinct accumulators) -> no RAW chain on C.
// ---------------------------------------------------------------------------
constexpr int BK      = 32;
constexpr int PITCH_B = (BK + 8) * 2;                 // 80 B per smem row
constexpr int ARR_B   = 128 * PITCH_B;                // 10240 B
constexpr int STAGE_B = 4 * ARR_B;                    // 40960 B
constexpr int NSTG    = 2;
constexpr int GEMM_SMEM = NSTG * STAGE_B;             // 81920 B -> 2 CTAs/SM
constexpr int KT_G    = D_ / BK;                      // 32

template <int MODE>
__global__ __launch_bounds__(256, 2)
void gemm_mma(const __nv_bfloat16* __restrict__ Ah,
              const __nv_bfloat16* __restrict__ Al,
              const float* __restrict__ b0, const float* __restrict__ b1,
              const float* __restrict__ b2,
              float* __restrict__ out, int zbase)
{
    extern __shared__ __align__(128) char smem[];
    const uint32_t sb = smem_u32(smem);

    const int tid  = threadIdx.x;
    const int wid  = tid >> 5;
    const int lane = tid & 31;
    const int wm   = (wid & 3) * 32;
    const int wn   = (wid >> 2) * 64;

    const int mBase = blockIdx.y * 128;
    const int nBase = blockIdx.x * 128;
    const int z     = zbase + blockIdx.z;

    const __nv_bfloat16* Bh = g_wth + ((size_t)z << 20);
    const __nv_bfloat16* Bl = g_wtl + ((size_t)z << 20);

    const int c0r = tid >> 2,         c0q = tid & 3;
    const int c1r = (tid + 256) >> 2, c1q = (tid + 256) & 3;

    auto load_stage = [&](int stg, int kt) {
        const uint32_t st = sb + stg * STAGE_B;
        const int bk = kt * BK;
        {
            const size_t g0 = (size_t)(mBase + c0r) * D_ + bk + c0q * 8;
            const size_t g1 = (size_t)(mBase + c1r) * D_ + bk + c1q * 8;
            const uint32_t s0 = c0r * PITCH_B + c0q * 16;
            const uint32_t s1 = c1r * PITCH_B + c1q * 16;
            cp16(st + s0,         Ah + g0);
            cp16(st + s1,         Ah + g1);
            cp16(st + ARR_B + s0, Al + g0);
            cp16(st + ARR_B + s1, Al + g1);
        }
        {
            const size_t g0 = (size_t)(nBase + c0r) * D_ + bk + c0q * 8;
            const size_t g1 = (size_t)(nBase + c1r) * D_ + bk + c1q * 8;
            const uint32_t s0 = c0r * PITCH_B + c0q * 16;
            const uint32_t s1 = c1r * PITCH_B + c1q * 16;
            cp16(st + 2 * ARR_B + s0, Bh + g0);
            cp16(st + 2 * ARR_B + s1, Bh + g1);
            cp16(st + 3 * ARR_B + s0, Bl + g0);
            cp16(st + 3 * ARR_B + s1, Bl + g1);
        }
        cp_commit();
    };

    float acc[2][8][4];
    #pragma unroll
    for (int mi = 0; mi < 2; mi++)
        #pragma unroll
        for (int ni = 0; ni < 8; ni++)
            #pragma unroll
            for (int r = 0; r < 4; r++) acc[mi][ni][r] = 0.f;

    load_stage(0, 0);
    load_stage(1, 1);

    const uint32_t aRowOff =
        (uint32_t)(wm + (lane & 7) + ((lane >> 3) & 1) * 8) * PITCH_B +
        ((lane >> 4) & 1) * 16;
    const uint32_t bRowOff =
        (uint32_t)(wn + ((lane >> 4) & 1) * 8 + (lane & 7)) * PITCH_B +
        ((lane >> 3) & 1) * 16;

    cp_wait<1>();           // stage 0 ready
    __syncthreads();

    #pragma unroll 1
    for (int kt = 0; kt < KT_G; kt++) {
        const uint32_t st  = sb + (kt & 1) * STAGE_B;
        const uint32_t sAh = st;
        const uint32_t sAl = st + ARR_B;
        const uint32_t sBh = st + 2 * ARR_B;
        const uint32_t sBl = st + 3 * ARR_B;

        #pragma unroll
        for (int ks = 0; ks < 2; ks++) {
            const uint32_t kOff = ks * 32;

            // load all fragments for this k-slice
            uint32_t ah[2][4], al[2][4];
            #pragma unroll
            for (int mi = 0; mi < 2; mi++) {
                const uint32_t off = aRowOff + (uint32_t)mi * 16 * PITCH_B + kOff;
                ldm_x4(ah[mi], sAh + off);
                ldm_x4(al[mi], sAl + off);
            }
            uint32_t bh4[4][4], bl4[4][4];
            #pragma unroll
            for (int p = 0; p < 4; p++) {
                const uint32_t off = bRowOff + (uint32_t)p * 16 * PITCH_B + kOff;
                ldm_x4(bh4[p], sBh + off);
                ldm_x4(bl4[p], sBl + off);
            }

            // pass 1: Ah x Bh — 16 independent MMAs
            #pragma unroll
            for (int mi = 0; mi < 2; mi++)
                #pragma unroll
                for (int p = 0; p < 4; p++)
                    #pragma unroll
                    for (int hf = 0; hf < 2; hf++)
                        mma_bf16(acc[mi][p * 2 + hf], ah[mi], &bh4[p][hf * 2]);
            // pass 2: Ah x Bl
            #pragma unroll
            for (int mi = 0; mi < 2; mi++)
                #pragma unroll
                for (int p = 0; p < 4; p++)
                    #pragma unroll
                    for (int hf = 0; hf < 2; hf++)
                        mma_bf16(acc[mi][p * 2 + hf], ah[mi], &bl4[p][hf * 2]);
            // pass 3: Al x Bh
            #pragma unroll
            for (int mi = 0; mi < 2; mi++)
                #pragma unroll
                for (int p = 0; p < 4; p++)
                    #pragma unroll
                    for (int hf = 0; hf < 2; hf++)
                        mma_bf16(acc[mi][p * 2 + hf], al[mi], &bh4[p][hf * 2]);
        }
        __syncthreads();
        if (kt + 2 < KT_G) {
            load_stage(kt & 1, kt + 2);
            cp_wait<1>();
            __syncthreads();
        } else if (kt + 1 < KT_G) {
            cp_wait<0>();
            __syncthreads();
        }
    }

    // --- epilogue ---
    const float* bias = (MODE == 0)
        ? (blockIdx.z == 0 ? b0 : blockIdx.z == 1 ? b1 : b2) : b0;

    __nv_bfloat16 *dh = nullptr, *dl = nullptr;
    float scale = 1.f;
    if (MODE == 0) {
        if (blockIdx.z == 0)      { dh = g_qh; dl = g_ql; scale = QSCALE; }
        else if (blockIdx.z == 1) { dh = g_kh; dl = g_kl; }
        else                      { dh = g_vh; dl = g_vl; }
    }

    #pragma unroll
    for (int mi = 0; mi < 2; mi++) {
        #pragma unroll
        for (int ni = 0; ni < 8; ni++) {
            const int n0 = nBase + wn + ni * 8 + (lane & 3) * 2;
            const float bv0 = __ldg(bias + n0), bv1 = __ldg(bias + n0 + 1);
            #pragma unroll
            for (int rr = 0; rr < 2; rr++) {
                const int m = mBase + wm + mi * 16 + (lane >> 2) + rr * 8;
                float v0 = acc[mi][ni][rr * 2 + 0] + bv0;
                float v1 = acc[mi][ni][rr * 2 + 1] + bv1;
                if (MODE == 0) {
                    v0 *= scale; v1 *= scale;
                    const int bb = m >> 11, tt = m & 2047;
                    const int hh = n0 >> 6, hd = n0 & 63;
                    const size_t idx =
                        ((((size_t)bb * H_ + hh) * T_ + tt) << 6) + hd;
                    reinterpret_cast<uint32_t*>(dh)[idx >> 1] =
                        pack_hi_trunc(v0, v1);
                    reinterpret_cast<uint32_t*>(dl)[idx >> 1] =
                        pack_bf16x2_rn(v0 - hi_trunc(v0), v1 - hi_trunc(v1));
                } else {
                    *reinterpret_cast<float2*>(out + (size_t)m * D_ + n0) =
                        make_float2(v0, v1);
                }
            }
        }
    }
}

// ---------------------------------------------------------------------------
// Tensor-core causal flash attention (bf16x3, fp32 accum, exp2 softmax).
// CTA: 128 queries, 8 warps; key tiles of 64, double-buffered; Q register-
// resident. Split-term MMA passes over 2-tile fragment groups (4 independent
// MMAs between same-accumulator reuse).
// ---------------------------------------------------------------------------
constexpr int APITCH_B    = 144;                    // 64 bf16 + 8 pad, bytes
constexpr int ATT_ARR_B   = 64 * APITCH_B;          // 9216 per K/V array
constexpr int ATT_STAGE_B = 4 * ATT_ARR_B;          // 36864 (kh,kl,vh,vl)
constexpr int ATT_SMEM    = 2 * ATT_STAGE_B;        // 73728 -> 2 CTAs/SM

__global__ __launch_bounds__(256, 2)
void attn_mma()
{
    extern __shared__ __align__(128) char smem[];
    const uint32_t sb = smem_u32(smem);

    const int tid  = threadIdx.x;
    const int wid  = tid >> 5;
    const int lane = tid & 31;

    const int qb = (gridDim.x - 1) - blockIdx.x;     // largest-first
    const int h  = blockIdx.y, b = blockIdx.z;
    const size_t bh = ((size_t)(b * H_ + h)) * T_ * HD_;

    const __nv_bfloat16* Qh = g_qh + bh + (size_t)qb * 128 * HD_;
    const __nv_bfloat16* Ql = g_ql + bh + (size_t)qb * 128 * HD_;
    const __nv_bfloat16* Kh = g_kh + bh;
    const __nv_bfloat16* Kl = g_kl + bh;
    const __nv_bfloat16* Vh = g_vh + bh;
    const __nv_bfloat16* Vl = g_vl + bh;

    // ---- Q loads into stage-1 buffer (group 0) ----
    const uint32_t qsb = sb + ATT_STAGE_B;
    #pragma unroll
    for (int i = 0; i < 8; i++) {
        const int c = i * 256 + tid;
        const int arr = c >> 10, row = (c >> 3) & 127, q8 = c & 7;
        const __nv_bfloat16* src = (arr ? Ql : Qh) + (size_t)row * HD_ + q8 * 8;
        cp16(qsb + arr * (2 * ATT_ARR_B) + row * APITCH_B + q8 * 16, src);
    }
    cp_commit();

    const int KT = 2 * qb + 2;   // always >= 2

    auto load_kv = [&](int stg, int kt) {
        const uint32_t base = sb + stg * ATT_STAGE_B;
        #pragma unroll
        for (int i = 0; i < 8; i++) {
            const int c = i * 256 + tid;
            const int arr = c >> 9, row = (c >> 3) & 63, q8 = c & 7;
            const __nv_bfloat16* g =
                (arr == 0) ? Kh : (arr == 1) ? Kl : (arr == 2) ? Vh : Vl;
            cp16(base + arr * ATT_ARR_B + row * APITCH_B + q8 * 16,
                 g + (size_t)(kt * 64 + row) * HD_ + q8 * 8);
        }
        cp_commit();
    };
    load_kv(0, 0);   // group 1

    // ---- Q fragments to registers ----
    cp_wait<1>();
    __syncthreads();
    uint32_t qfh[4][4], qfl[4][4];
    {
        const uint32_t aoff = qsb +
            (uint32_t)(wid * 16 + (lane & 7) + ((lane >> 3) & 1) * 8) * APITCH_B +
            ((lane >> 4) & 1) * 16;
        #pragma unroll
        for (int kc = 0; kc < 4; kc++) {
            ldm_x4(qfh[kc], aoff + kc * 32);
            ldm_x4(qfl[kc], aoff + 2 * ATT_ARR_B + kc * 32);
        }
    }
    __syncthreads();           // all warps done reading stage-1 region
    load_kv(1, 1);             // overwrite it with KV tile 1
    cp_wait<1>();              // KV0 ready
    __syncthreads();

    float o[8][4];
    #pragma unroll
    for (int nt = 0; nt < 8; nt++)
        #pragma unroll
        for (int r = 0; r < 4; r++) o[nt][r] = 0.f;
    float m0 = -1e30f, m1 = -1e30f, l0 = 0.f, l1 = 0.f;

    const int r0g = qb * 128 + wid * 16 + (lane >> 2);

    const uint32_t bBase =
        (uint32_t)(((lane >> 4) & 1) * 8 + (lane & 7)) * APITCH_B +
        ((lane >> 3) & 1) * 16;
    const uint32_t vBase =
        (uint32_t)((lane & 7) + ((lane >> 3) & 1) * 8) * APITCH_B +
        ((lane >> 4) & 1) * 16;

    #pragma unroll 1
    for (int kt = 0; kt < KT; kt++) {
        const uint32_t st = sb + (kt & 1) * ATT_STAGE_B;

        // ---- S = Q K^T : per (kc, 2-tile group), 3 passes of 4 indep MMAs
        float s[8][4];
        #pragma unroll
        for (int nt = 0; nt < 8; nt++)
            #pragma unroll
            for (int r = 0; r < 4; r++) s[nt][r] = 0.f;

        #pragma unroll
        for (int kc = 0; kc < 4; kc++) {
            #pragma unroll
            for (int g = 0; g < 2; g++) {
                uint32_t kh4[2][4], kl4[2][4];
                #pragma unroll
                for (int t = 0; t < 2; t++) {
                    const int nt16 = g * 2 + t;
                    const uint32_t ad = st + bBase + nt16 * 16 * APITCH_B + kc * 32;
                    ldm_x4(kh4[t], ad);
                    ldm_x4(kl4[t], ad + ATT_ARR_B);
                }
                #pragma unroll
                for (int t = 0; t < 2; t++)
                    #pragma unroll
                    for (int hf = 0; hf < 2; hf++)
                        mma_bf16(s[(g * 2 + t) * 2 + hf], qfh[kc], &kh4[t][hf * 2]);
                #pragma unroll
                for (int t = 0; t < 2; t++)
                    #pragma unroll
                    for (int hf = 0; hf < 2; hf++)
                        mma_bf16(s[(g * 2 + t) * 2 + hf], qfl[kc], &kh4[t][hf * 2]);
                #pragma unroll
                for (int t = 0; t < 2; t++)
                    #pragma unroll
                    for (int hf = 0; hf < 2; hf++)
                        mma_bf16(s[(g * 2 + t) * 2 + hf], qfh[kc], &kl4[t][hf * 2]);
            }
        }

        // ---- causal mask (last two tiles only) ----
        if (kt >= KT - 2) {
            const int colBase = kt * 64 + (lane & 3) * 2;
            #pragma unroll
            for (int nt = 0; nt < 8; nt++)
                #pragma unroll
                for (int j = 0; j < 2; j++) {
                    const int c = colBase + nt * 8 + j;
                    if (c > r0g)     s[nt][j]     = -1e30f;
                    if (c > r0g + 8) s[nt][2 + j] = -1e30f;
                }
        }

        // ---- online softmax (base-2) ----
        float tm0 = -1e30f, tm1 = -1e30f;
        #pragma unroll
        for (int nt = 0; nt < 8; nt++) {
            tm0 = fmaxf(tm0, fmaxf(s[nt][0], s[nt][1]));
            tm1 = fmaxf(tm1, fmaxf(s[nt][2], s[nt][3]));
        }
        tm0 = fmaxf(tm0, __shfl_xor_sync(0xffffffffu, tm0, 1));
        tm0 = fmaxf(tm0, __shfl_xor_sync(0xffffffffu, tm0, 2));
        tm1 = fmaxf(tm1, __shfl_xor_sync(0xffffffffu, tm1, 1));
        tm1 = fmaxf(tm1, __shfl_xor_sync(0xffffffffu, tm1, 2));

        const float mn0 = fmaxf(m0, tm0), mn1 = fmaxf(m1, tm1);
        const float c0 = ex2f(m0 - mn0), c1 = ex2f(m1 - mn1);
        m0 = mn0; m1 = mn1;

        float sum0 = 0.f, sum1 = 0.f;
        #pragma unroll
        for (int nt = 0; nt < 8; nt++) {
            #pragma unroll
            for (int j = 0; j < 2; j++) {
                const float p0 = ex2f(s[nt][j] - mn0);
                const float p1 = ex2f(s[nt][2 + j] - mn1);
                s[nt][j] = p0;     sum0 += p0;
                s[nt][2 + j] = p1; sum1 += p1;
            }
        }
        l0 = l0 * c0 + sum0;
        l1 = l1 * c1 + sum1;

        #pragma unroll
        for (int nt = 0; nt < 8; nt++) {
            o[nt][0] *= c0; o[nt][1] *= c0;
            o[nt][2] *= c1; o[nt][3] *= c1;
        }

        // ---- O += P V : per (kc, 2-tile group), 3 passes of 4 indep MMAs
        #pragma unroll
        for (int kc = 0; kc < 4; kc++) {
            const float* s0 = s[2 * kc];
            const float* s1 = s[2 * kc + 1];
            uint32_t ph[4], pl[4];
            ph[0] = pack_hi_trunc(s0[0], s0[1]);
            ph[1] = pack_hi_trunc(s0[2], s0[3]);
            ph[2] = pack_hi_trunc(s1[0], s1[1]);
            ph[3] = pack_hi_trunc(s1[2], s1[3]);
            pl[0] = pack_bf16x2_rn(s0[0] - hi_trunc(s0[0]), s0[1] - hi_trunc(s0[1]));
            pl[1] = pack_bf16x2_rn(s0[2] - hi_trunc(s0[2]), s0[3] - hi_trunc(s0[3]));
            pl[2] = pack_bf16x2_rn(s1[0] - hi_trunc(s1[0]), s1[1] - hi_trunc(s1[1]));
            pl[3] = pack_bf16x2_rn(s1[2] - hi_trunc(s1[2]), s1[3] - hi_trunc(s1[3]));

            #pragma unroll
            for (int g = 0; g < 2; g++) {
                uint32_t vh4[2][4], vl4[2][4];
                #pragma unroll
                for (int t = 0; t < 2; t++) {
                    const int nt16 = g * 2 + t;
                    const uint32_t ad = st + 2 * ATT_ARR_B + vBase +
                                        kc * 16 * APITCH_B + nt16 * 32;
                    ldm_x4_t(vh4[t], ad);
                    ldm_x4_t(vl4[t], ad + ATT_ARR_B);
                }
                #pragma unroll
                for (int t = 0; t < 2; t++)
                    #pragma unroll
                    for (int hf = 0; hf < 2; hf++)
                        mma_bf16(o[(g * 2 + t) * 2 + hf], ph, &vh4[t][hf * 2]);
                #pragma unroll
                for (int t = 0; t < 2; t++)
                    #pragma unroll
                    for (int hf = 0; hf < 2; hf++)
                        mma_bf16(o[(g * 2 + t) * 2 + hf], pl, &vh4[t][hf * 2]);
                #pragma unroll
                for (int t = 0; t < 2; t++)
                    #pragma unroll
                    for (int hf = 0; hf < 2; hf++)
                        mma_bf16(o[(g * 2 + t) * 2 + hf], ph, &vl4[t][hf * 2]);
            }
        }

        // ---- advance pipeline ----
        __syncthreads();
        if (kt + 2 < KT) {
            load_kv(kt & 1, kt + 2);
            cp_wait<1>();
            __syncthreads();
        } else if (kt + 1 < KT) {
            cp_wait<0>();
            __syncthreads();
        }
    }

    // ---- finalize ----
    l0 += __shfl_xor_sync(0xffffffffu, l0, 1);
    l0 += __shfl_xor_sync(0xffffffffu, l0, 2);
    l1 += __shfl_xor_sync(0xffffffffu, l1, 1);
    l1 += __shfl_xor_sync(0xffffffffu, l1, 2);
    const float inv0 = 1.f / l0, inv1 = 1.f / l1;

    const size_t row0 = (size_t)b * T_ + qb * 128 + wid * 16 + (lane >> 2);
    const size_t row1 = row0 + 8;
    const int colB = h * HD_ + (lane & 3) * 2;

    #pragma unroll
    for (int nt = 0; nt < 8; nt++) {
        const float v0 = o[nt][0] * inv0, v1 = o[nt][1] * inv0;
        const float v2 = o[nt][2] * inv1, v3 = o[nt][3] * inv1;
        const size_t i0 = row0 * D_ + colB + nt * 8;
        const size_t i1 = row1 * D_ + colB + nt * 8;
        reinterpret_cast<uint32_t*>(g_oh)[i0 >> 1] = pack_hi_trunc(v0, v1);
        reinterpret_cast<uint32_t*>(g_ol)[i0 >> 1] =
            pack_bf16x2_rn(v0 - hi_trunc(v0), v1 - hi_trunc(v1));
        reinterpret_cast<uint32_t*>(g_oh)[i1 >> 1] = pack_hi_trunc(v2, v3);
        reinterpret_cast<uint32_t*>(g_ol)[i1 >> 1] =
            pack_bf16x2_rn(v2 - hi_trunc(v2), v3 - hi_trunc(v3));
    }
}

// ---------------------------------------------------------------------------
// Conversion kernels
// ---------------------------------------------------------------------------
__global__ __launch_bounds__(256) void split_x_kernel(const float* __restrict__ src)
{
    const int i = blockIdx.x * 256 + threadIdx.x;
    const float v = src[i];
    const __nv_bfloat16 hv = __float2bfloat16(v);
    g_xh[i] = hv;
    g_xl[i] = __float2bfloat16(v - __bfloat162float(hv));
}

__global__ __launch_bounds__(256) void wsplit_kernel(
    const float* __restrict__ wq, const float* __restrict__ wk,
    const float* __restrict__ wv, const float* __restrict__ wo)
{
    __shared__ float tile[32][33];
    const int z = blockIdx.z;
    const float* w = (z == 0) ? wq : (z == 1) ? wk : (z == 2) ? wv : wo;
    const int nB = blockIdx.x * 32, kB = blockIdx.y * 32;
    const int tx = threadIdx.x & 31, ty = threadIdx.x >> 5;

    #pragma unroll
    for (int r = ty; r < 32; r += 8)
        tile[r][tx] = w[(size_t)(kB + r) * D_ + nB + tx];
    __syncthreads();
    #pragma unroll
    for (int r = ty; r < 32; r += 8) {
        const float v = tile[tx][r];
        const size_t di = ((size_t)z << 20) + (size_t)(nB + r) * D_ + kB + tx;
        const __nv_bfloat16 hv = __float2bfloat16(v);
        g_wth[di] = hv;
        g_wtl[di] = __float2bfloat16(v - __bfloat162float(hv));
    }
}

// ---------------------------------------------------------------------------
extern "C" void kernel_launch(void* const* d_in, const int* in_sizes, int n_in,
                              void* d_out, int out_size)
{
    const float* x  = (const float*)d_in[0];
    const float* wq = (const float*)d_in[1];
    const float* bq = (const float*)d_in[2];
    const float* wk = (const float*)d_in[3];
    const float* bk = (const float*)d_in[4];
    const float* wv = (const float*)d_in[5];
    const float* bv = (const float*)d_in[6];
    const float* wo = (const float*)d_in[7];
    const float* bo = (const float*)d_in[8];
    float* out = (float*)d_out;

    static bool attrSet = false;
    if (!attrSet) {
        cudaFuncSetAttribute(gemm_mma<0>,
                             cudaFuncAttributeMaxDynamicSharedMemorySize, GEMM_SMEM);
        cudaFuncSetAttribute(gemm_mma<1>,
                             cudaFuncAttributeMaxDynamicSharedMemorySize, GEMM_SMEM);
        cudaFuncSetAttribute(attn_mma,
                             cudaFuncAttributeMaxDynamicSharedMemorySize, ATT_SMEM);
        attrSet = true;
    }

    void *pxh, *pxl, *poh, *pol;
    cudaGetSymbolAddress(&pxh, g_xh);
    cudaGetSymbolAddress(&pxl, g_xl);
    cudaGetSymbolAddress(&poh, g_oh);
    cudaGetSymbolAddress(&pol, g_ol);

    const int nElem = M_ * D_;

    // 1) convert inputs to bf16 hi/lo
    split_x_kernel<<<nElem / 256, 256>>>(x);
    wsplit_kernel<<<dim3(32, 32, 4), 256>>>(wq, wk, wv, wo);

    // 2) QKV projections -> bf16 hi/lo [B,H,T,HD]; Q pre-scaled by 0.125*log2e
    gemm_mma<0><<<dim3(8, 64, 3), 256, GEMM_SMEM>>>(
        (const __nv_bfloat16*)pxh, (const __nv_bfloat16*)pxl,
        bq, bk, bv, nullptr, 0);

    // 3) tensor-core causal flash attention -> g_oh/g_ol [B*T, D]
    attn_mma<<<dim3(T_ / 128, H_, B_), 256, ATT_SMEM>>>();

    // 4) output projection
    gemm_mma<1><<<dim3(8, 64, 1), 256, GEMM_SMEM>>>(
        (const __nv_bfloat16*)poh, (const __nv_bfloat16*)pol,
        bo, bo, bo, out, 3);
}

// round 7
// speedup vs baseline: 5.1764x; 1.1885x over previous
#include <cuda_runtime.h>
#include <cuda_fp16.h>
#include <cstdint>
#include <cstddef>

// ---------------------------------------------------------------------------
// Problem constants
// ---------------------------------------------------------------------------
constexpr int B_  = 4;
constexpr int T_  = 2048;
constexpr int D_  = 1024;
constexpr int H_  = 16;
constexpr int HD_ = 64;
constexpr int M_  = B_ * T_;   // 8192

// 0.125 * log2(e): folded into Q so softmax uses exp2
constexpr float QSCALE = 0.18033688011112042f;

// ---------------------------------------------------------------------------
// Device scratch (f16 hi/lo splits everywhere)
// ---------------------------------------------------------------------------
__device__ __align__(128) __half g_xh[(size_t)M_ * D_];
__device__ __align__(128) __half g_xl[(size_t)M_ * D_];
__device__ __align__(128) __half g_oh[(size_t)M_ * D_];   // [B*T, D]
__device__ __align__(128) __half g_ol[(size_t)M_ * D_];
// QKV in [B, H, T, HD]
__device__ __align__(128) __half g_qh[(size_t)M_ * D_];
__device__ __align__(128) __half g_ql[(size_t)M_ * D_];
__device__ __align__(128) __half g_kh[(size_t)M_ * D_];
__device__ __align__(128) __half g_kl[(size_t)M_ * D_];
__device__ __align__(128) __half g_vh[(size_t)M_ * D_];
__device__ __align__(128) __half g_vl[(size_t)M_ * D_];
// 4 weights transposed to [N, K] f16 hi/lo, z: 0..3 -> wq,wk,wv,wo
__device__ __align__(128) __half g_wth[(size_t)4 * D_ * D_];
__device__ __align__(128) __half g_wtl[(size_t)4 * D_ * D_];

// ---------------------------------------------------------------------------
// PTX helpers
// ---------------------------------------------------------------------------
__device__ __forceinline__ uint32_t smem_u32(const void* p) {
    uint32_t a;
    asm("{ .reg .u64 t; cvta.to.shared.u64 t, %1; cvt.u32.u64 %0, t; }"
        : "=r"(a) : "l"(p));
    return a;
}
__device__ __forceinline__ void cp16(uint32_t saddr, const void* gaddr) {
    asm volatile("cp.async.cg.shared.global [%0], [%1], 16;"
                 :: "r"(saddr), "l"(gaddr));
}
__device__ __forceinline__ void cp_commit() {
    asm volatile("cp.async.commit_group;");
}
template <int N>
__device__ __forceinline__ void cp_wait() {
    asm volatile("cp.async.wait_group %0;" :: "n"(N));
}
__device__ __forceinline__ void ldm_x4(uint32_t* r, uint32_t addr) {
    asm volatile("ldmatrix.sync.aligned.m8n8.x4.shared.b16 {%0,%1,%2,%3}, [%4];"
                 : "=r"(r[0]), "=r"(r[1]), "=r"(r[2]), "=r"(r[3]) : "r"(addr));
}
__device__ __forceinline__ void ldm_x4_t(uint32_t* r, uint32_t addr) {
    asm volatile("ldmatrix.sync.aligned.m8n8.x4.trans.shared.b16 {%0,%1,%2,%3}, [%4];"
                 : "=r"(r[0]), "=r"(r[1]), "=r"(r[2]), "=r"(r[3]) : "r"(addr));
}
__device__ __forceinline__ void mma_f16(float* c, const uint32_t* a,
                                        const uint32_t* b) {
    asm volatile(
        "mma.sync.aligned.m16n8k16.row.col.f32.f16.f16.f32 "
        "{%0,%1,%2,%3}, {%4,%5,%6,%7}, {%8,%9}, {%0,%1,%2,%3};"
        : "+f"(c[0]), "+f"(c[1]), "+f"(c[2]), "+f"(c[3])
        : "r"(a[0]), "r"(a[1]), "r"(a[2]), "r"(a[3]), "r"(b[0]), "r"(b[1]));
}
__device__ __forceinline__ float ex2f(float x) {
    float r;
    asm("ex2.approx.ftz.f32 %0, %1;" : "=f"(r) : "f"(x));
    return r;
}
// packed f16x2: {low=lo, high=hi}
__device__ __forceinline__ uint32_t packh2(float lo, float hi) {
    uint32_t r;
    asm("cvt.rn.f16x2.f32 %0, %1, %2;" : "=r"(r) : "f"(hi), "f"(lo));
    return r;
}
__device__ __forceinline__ uint32_t ex2h2(uint32_t x) {
    uint32_t r;
    asm("ex2.approx.f16x2 %0, %1;" : "=r"(r) : "r"(x));
    return r;
}
// split v0,v1 into f16 hi pair + f16 lo (residual) pair
__device__ __forceinline__ void split_pack_f16(float v0, float v1,
                                               uint32_t& hi, uint32_t& lo) {
    hi = packh2(v0, v1);
    const float h0 = __half2float(__ushort_as_half((unsigned short)(hi & 0xFFFF)));
    const float h1 = __half2float(__ushort_as_half((unsigned short)(hi >> 16)));
    lo = packh2(v0 - h0, v1 - h1);
}

// ---------------------------------------------------------------------------
// HMMA GEMM (f16x3, fp32 accum). 8 warps (4Mx2N), warp 32x64, BK=32,
// 3-stage cp.async with 64B-pitch XOR-swizzled tiles, 2 CTAs/SM.
// ---------------------------------------------------------------------------
constexpr int BK        = 32;
constexpr int G_ARR_B   = 128 * 64;                   // 8192 B per tile array
constexpr int G_STAGE_B = 4 * G_ARR_B;                // 32768 B
constexpr int GEMM_SMEM = 3 * G_STAGE_B;              // 98304 B
constexpr int KT_G      = D_ / BK;                    // 32

// 64B-pitch swizzle: physical byte offset of (row, 16B-chunk)
__device__ __forceinline__ uint32_t gswz(int row, int chunk) {
    return (uint32_t)row * 64u + (uint32_t)((chunk ^ ((row >> 1) & 3)) << 4);
}

template <int MODE>
__global__ __launch_bounds__(256, 2)
void gemm_mma(const __half* __restrict__ Ah, const __half* __restrict__ Al,
              const float* __restrict__ b0, const float* __restrict__ b1,
              const float* __restrict__ b2,
              float* __restrict__ out, int zbase)
{
    extern __shared__ __align__(128) char smem[];
    const uint32_t sb = smem_u32(smem);

    const int tid  = threadIdx.x;
    const int wid  = tid >> 5;
    const int lane = tid & 31;
    const int wm   = (wid & 3) * 32;
    const int wn   = (wid >> 2) * 64;

    const int mBase = blockIdx.y * 128;
    const int nBase = blockIdx.x * 128;
    const int z     = zbase + blockIdx.z;

    const __half* Bh = g_wth + ((size_t)z << 20);
    const __half* Bl = g_wtl + ((size_t)z << 20);

    // per-thread load mapping: 2 chunks per 128x32 array (512 chunks total)
    const int c0r = tid >> 2,         c0q = tid & 3;
    const int c1r = (tid + 256) >> 2, c1q = (tid + 256) & 3;
    const uint32_t s0 = gswz(c0r, c0q), s1 = gswz(c1r, c1q);

    auto load_stage = [&](int stg, int kt) {
        const uint32_t st = sb + stg * G_STAGE_B;
        const int bk = kt * BK;
        {
            const size_t ga = (size_t)(mBase + c0r) * D_ + bk + c0q * 8;
            const size_t gb = (size_t)(mBase + c1r) * D_ + bk + c1q * 8;
            cp16(st + s0,           Ah + ga);
            cp16(st + s1,           Ah + gb);
            cp16(st + G_ARR_B + s0, Al + ga);
            cp16(st + G_ARR_B + s1, Al + gb);
        }
        {
            const size_t ga = (size_t)(nBase + c0r) * D_ + bk + c0q * 8;
            const size_t gb = (size_t)(nBase + c1r) * D_ + bk + c1q * 8;
            cp16(st + 2 * G_ARR_B + s0, Bh + ga);
            cp16(st + 2 * G_ARR_B + s1, Bh + gb);
            cp16(st + 3 * G_ARR_B + s0, Bl + ga);
            cp16(st + 3 * G_ARR_B + s1, Bl + gb);
        }
        cp_commit();
    };

    float acc[2][8][4];
    #pragma unroll
    for (int mi = 0; mi < 2; mi++)
        #pragma unroll
        for (int ni = 0; ni < 8; ni++)
            #pragma unroll
            for (int r = 0; r < 4; r++) acc[mi][ni][r] = 0.f;

    load_stage(0, 0);
    load_stage(1, 1);
    load_stage(2, 2);

    // ldmatrix row/swizzle precompute
    int rowA[2], rowB[4];
    #pragma unroll
    for (int mi = 0; mi < 2; mi++)
        rowA[mi] = wm + (lane & 7) + ((lane >> 3) & 1) * 8 + mi * 16;
    #pragma unroll
    for (int p = 0; p < 4; p++)
        rowB[p] = wn + ((lane >> 4) & 1) * 8 + (lane & 7) + p * 16;
    const int chA = (lane >> 4) & 1;     // + ks*2
    const int chB = (lane >> 3) & 1;     // + ks*2

    cp_wait<2>();            // stage 0 ready
    __syncthreads();

    #pragma unroll 1
    for (int kt = 0; kt < KT_G; kt++) {
        const uint32_t st  = sb + (kt % 3) * G_STAGE_B;
        const uint32_t sAh = st;
        const uint32_t sAl = st + G_ARR_B;
        const uint32_t sBh = st + 2 * G_ARR_B;
        const uint32_t sBl = st + 3 * G_ARR_B;

        #pragma unroll
        for (int ks = 0; ks < 2; ks++) {
            uint32_t ah[2][4], al[2][4];
            #pragma unroll
            for (int mi = 0; mi < 2; mi++) {
                const uint32_t off = gswz(rowA[mi], chA + ks * 2);
                ldm_x4(ah[mi], sAh + off);
                ldm_x4(al[mi], sAl + off);
            }
            uint32_t bh4[4][4], bl4[4][4];
            #pragma unroll
            for (int p = 0; p < 4; p++) {
                const uint32_t off = gswz(rowB[p], chB + ks * 2);
                ldm_x4(bh4[p], sBh + off);
                ldm_x4(bl4[p], sBl + off);
            }
            #pragma unroll
            for (int mi = 0; mi < 2; mi++)
                #pragma unroll
                for (int p = 0; p < 4; p++)
                    #pragma unroll
                    for (int hf = 0; hf < 2; hf++)
                        mma_f16(acc[mi][p * 2 + hf], ah[mi], &bh4[p][hf * 2]);
            #pragma unroll
            for (int mi = 0; mi < 2; mi++)
                #pragma unroll
                for (int p = 0; p < 4; p++)
                    #pragma unroll
                    for (int hf = 0; hf < 2; hf++)
                        mma_f16(acc[mi][p * 2 + hf], ah[mi], &bl4[p][hf * 2]);
            #pragma unroll
            for (int mi = 0; mi < 2; mi++)
                #pragma unroll
                for (int p = 0; p < 4; p++)
                    #pragma unroll
                    for (int hf = 0; hf < 2; hf++)
                        mma_f16(acc[mi][p * 2 + hf], al[mi], &bh4[p][hf * 2]);
        }
        __syncthreads();
        if (kt + 3 < KT_G) {
            load_stage(kt % 3, kt + 3);
            cp_wait<2>();
            __syncthreads();
        } else if (kt + 2 < KT_G) {
            cp_wait<1>();
            __syncthreads();
        } else if (kt + 1 < KT_G) {
            cp_wait<0>();
            __syncthreads();
        }
    }

    // --- epilogue ---
    const float* bias = (MODE == 0)
        ? (blockIdx.z == 0 ? b0 : blockIdx.z == 1 ? b1 : b2) : b0;

    __half *dh = nullptr, *dl = nullptr;
    float scale = 1.f;
    if (MODE == 0) {
        if (blockIdx.z == 0)      { dh = g_qh; dl = g_ql; scale = QSCALE; }
        else if (blockIdx.z == 1) { dh = g_kh; dl = g_kl; }
        else                      { dh = g_vh; dl = g_vl; }
    }

    #pragma unroll
    for (int mi = 0; mi < 2; mi++) {
        #pragma unroll
        for (int ni = 0; ni < 8; ni++) {
            const int n0 = nBase + wn + ni * 8 + (lane & 3) * 2;
            const float bv0 = __ldg(bias + n0), bv1 = __ldg(bias + n0 + 1);
            #pragma unroll
            for (int rr = 0; rr < 2; rr++) {
                const int m = mBase + wm + mi * 16 + (lane >> 2) + rr * 8;
                float v0 = acc[mi][ni][rr * 2 + 0] + bv0;
                float v1 = acc[mi][ni][rr * 2 + 1] + bv1;
                if (MODE == 0) {
                    v0 *= scale; v1 *= scale;
                    const int bb = m >> 11, tt = m & 2047;
                    const int hh = n0 >> 6, hd = n0 & 63;
                    const size_t idx =
                        ((((size_t)bb * H_ + hh) * T_ + tt) << 6) + hd;
                    uint32_t hp, lp;
                    split_pack_f16(v0, v1, hp, lp);
                    reinterpret_cast<uint32_t*>(dh)[idx >> 1] = hp;
                    reinterpret_cast<uint32_t*>(dl)[idx >> 1] = lp;
                } else {
                    *reinterpret_cast<float2*>(out + (size_t)m * D_ + n0) =
                        make_float2(v0, v1);
                }
            }
        }
    }
}

// ---------------------------------------------------------------------------
// Tensor-core causal flash attention.
// f16x3 for S = QK^T; P native f16 from ex2.approx.f16x2; PV = 2 terms.
// Row sums via P x ones MMA. 3-stage KV pipeline, SW128 swizzle, 2 CTAs/SM.
// ---------------------------------------------------------------------------
constexpr int ATT_ARR_B   = 64 * 128;                 // 8192 per K/V array
constexpr int ATT_STAGE_B = 4 * ATT_ARR_B;            // 32768 (kh,kl,vh,vl)
constexpr int ATT_SMEM    = 3 * ATT_STAGE_B;          // 98304 -> 2 CTAs/SM

// 128B-pitch SW128 swizzle
__device__ __forceinline__ uint32_t aswz(int row, int chunk) {
    return (uint32_t)row * 128u + (uint32_t)((chunk ^ (row & 7)) << 4);
}

__global__ __launch_bounds__(256, 2)
void attn_mma()
{
    extern __shared__ __align__(128) char smem[];
    const uint32_t sb = smem_u32(smem);

    const int tid  = threadIdx.x;
    const int wid  = tid >> 5;
    const int lane = tid & 31;

    const int qb = (gridDim.x - 1) - blockIdx.x;     // largest-first
    const int h  = blockIdx.y, b = blockIdx.z;
    const size_t bh = ((size_t)(b * H_ + h)) * T_ * HD_;

    const __half* Qh = g_qh + bh + (size_t)qb * 128 * HD_;
    const __half* Ql = g_ql + bh + (size_t)qb * 128 * HD_;
    const __half* Kh = g_kh + bh;
    const __half* Kl = g_kl + bh;
    const __half* Vh = g_vh + bh;
    const __half* Vl = g_vl + bh;

    const int KT = 2 * qb + 2;   // >= 2

    // ---- prologue loads: Q -> stage2; KV0 -> stage0; KV1 -> stage1 ----
    const uint32_t qsb = sb + 2 * ATT_STAGE_B;
    #pragma unroll
    for (int i = 0; i < 8; i++) {
        const int c = i * 256 + tid;
        const int arr = c >> 10, row = (c >> 3) & 127, q8 = c & 7;
        const __half* src = (arr ? Ql : Qh) + (size_t)row * HD_ + q8 * 8;
        cp16(qsb + arr * (2 * ATT_ARR_B) + aswz(row, q8), src);
    }
    cp_commit();

    auto load_kv = [&](int stg, int kt) {
        const uint32_t base = sb + stg * ATT_STAGE_B;
        #pragma unroll
        for (int i = 0; i < 8; i++) {
            const int c = i * 256 + tid;
            const int arr = c >> 9, row = (c >> 3) & 63, q8 = c & 7;
            const __half* g =
                (arr == 0) ? Kh : (arr == 1) ? Kl : (arr == 2) ? Vh : Vl;
            cp16(base + arr * ATT_ARR_B + aswz(row, q8),
                 g + (size_t)(kt * 64 + row) * HD_ + q8 * 8);
        }
        cp_commit();
    };
    load_kv(0, 0);
    load_kv(1, 1);

    // ---- Q fragments to registers ----
    cp_wait<2>();            // Q done
    __syncthreads();
    uint32_t qfh[4][4], qfl[4][4];
    {
        const int rowQ = wid * 16 + (lane & 7) + ((lane >> 3) & 1) * 8;
        const int chQ  = (lane >> 4) & 1;
        #pragma unroll
        for (int kc = 0; kc < 4; kc++) {
            const uint32_t off = aswz(rowQ, chQ + kc * 2);
            ldm_x4(qfh[kc], qsb + off);
            ldm_x4(qfl[kc], qsb + 2 * ATT_ARR_B + off);
        }
    }
    __syncthreads();                         // all warps done reading Q smem
    load_kv(2, (2 < KT) ? 2 : KT - 1);       // stage2 reused (dup load if KT==2)
    cp_wait<2>();                            // KV0 ready
    __syncthreads();

    float o[8][4];
    #pragma unroll
    for (int nt = 0; nt < 8; nt++)
        #pragma unroll
        for (int r = 0; r < 4; r++) o[nt][r] = 0.f;
    float m0 = -1e30f, m1 = -1e30f, l0 = 0.f, l1 = 0.f;

    const int r0g = qb * 128 + wid * 16 + (lane >> 2);

    // K-side ldm: row varies with nt16; chunk = chK + kc*2
    const int rKbase = ((lane >> 4) & 1) * 8 + (lane & 7);
    const int chK    = (lane >> 3) & 1;
    // V-side ldm (trans): row = rVbase + kc*16; chunk = chV + nt16*2
    const int rVbase = (lane & 7) + ((lane >> 3) & 1) * 8;
    const int chV    = (lane >> 4) & 1;

    const uint32_t ONES2[2] = {0x3C003C00u, 0x3C003C00u};

    #pragma unroll 1
    for (int kt = 0; kt < KT; kt++) {
        const uint32_t st  = sb + (kt % 3) * ATT_STAGE_B;
        const uint32_t stK = st;
        const uint32_t stV = st + 2 * ATT_ARR_B;

        // ---- S = Q K^T (f16x3) ----
        float s[8][4];
        #pragma unroll
        for (int nt = 0; nt < 8; nt++)
            #pragma unroll
            for (int r = 0; r < 4; r++) s[nt][r] = 0.f;

        #pragma unroll
        for (int kc = 0; kc < 4; kc++) {
            #pragma unroll
            for (int g = 0; g < 2; g++) {
                uint32_t kh4[2][4], kl4[2][4];
                #pragma unroll
                for (int t = 0; t < 2; t++) {
                    const int nt16 = g * 2 + t;
                    const uint32_t ad = aswz(rKbase + nt16 * 16, chK + kc * 2);
                    ldm_x4(kh4[t], stK + ad);
                    ldm_x4(kl4[t], stK + ATT_ARR_B + ad);
                }
                #pragma unroll
                for (int t = 0; t < 2; t++)
                    #pragma unroll
                    for (int hf = 0; hf < 2; hf++)
                        mma_f16(s[(g * 2 + t) * 2 + hf], qfh[kc], &kh4[t][hf * 2]);
                #pragma unroll
                for (int t = 0; t < 2; t++)
                    #pragma unroll
                    for (int hf = 0; hf < 2; hf++)
                        mma_f16(s[(g * 2 + t) * 2 + hf], qfl[kc], &kh4[t][hf * 2]);
                #pragma unroll
                for (int t = 0; t < 2; t++)
                    #pragma unroll
                    for (int hf = 0; hf < 2; hf++)
                        mma_f16(s[(g * 2 + t) * 2 + hf], qfh[kc], &kl4[t][hf * 2]);
            }
        }

        // ---- causal mask (last two tiles only) ----
        if (kt >= KT - 2) {
            const int colBase = kt * 64 + (lane & 3) * 2;
            #pragma unroll
            for (int nt = 0; nt < 8; nt++)
                #pragma unroll
                for (int j = 0; j < 2; j++) {
                    const int c = colBase + nt * 8 + j;
                    if (c > r0g)     s[nt][j]     = -30000.f;
                    if (c > r0g + 8) s[nt][2 + j] = -30000.f;
                }
        }

        // ---- max-reduce + o rescale ----
        float tm0 = -1e30f, tm1 = -1e30f;
        #pragma unroll
        for (int nt = 0; nt < 8; nt++) {
            tm0 = fmaxf(tm0, fmaxf(s[nt][0], s[nt][1]));
            tm1 = fmaxf(tm1, fmaxf(s[nt][2], s[nt][3]));
        }
        tm0 = fmaxf(tm0, __shfl_xor_sync(0xffffffffu, tm0, 1));
        tm0 = fmaxf(tm0, __shfl_xor_sync(0xffffffffu, tm0, 2));
        tm1 = fmaxf(tm1, __shfl_xor_sync(0xffffffffu, tm1, 1));
        tm1 = fmaxf(tm1, __shfl_xor_sync(0xffffffffu, tm1, 2));

        const float mn0 = fmaxf(m0, tm0), mn1 = fmaxf(m1, tm1);
        const float c0 = ex2f(m0 - mn0), c1 = ex2f(m1 - mn1);
        m0 = mn0; m1 = mn1;

        #pragma unroll
        for (int nt = 0; nt < 8; nt++) {
            o[nt][0] *= c0; o[nt][1] *= c0;
            o[nt][2] *= c1; o[nt][3] *= c1;
        }

        // ---- per-chunk: P = ex2(S-m) in f16; sums via MMA; O += P V ----
        float dsum[4] = {0.f, 0.f, 0.f, 0.f};
        #pragma unroll
        for (int kc = 0; kc < 4; kc++) {
            const float* s0 = s[2 * kc];
            const float* s1 = s[2 * kc + 1];
            uint32_t ph[4];
            ph[0] = ex2h2(packh2(s0[0] - mn0, s0[1] - mn0));
            ph[1] = ex2h2(packh2(s0[2] - mn1, s0[3] - mn1));
            ph[2] = ex2h2(packh2(s1[0] - mn0, s1[1] - mn0));
            ph[3] = ex2h2(packh2(s1[2] - mn1, s1[3] - mn1));

            mma_f16(dsum, ph, ONES2);   // row sums of this 16-key chunk

            const int rowV = rVbase + kc * 16;
            #pragma unroll
            for (int nt16 = 0; nt16 < 4; nt16++) {
                uint32_t vh4[4], vl4[4];
                const uint32_t ad = aswz(rowV, chV + nt16 * 2);
                ldm_x4_t(vh4, stV + ad);
                ldm_x4_t(vl4, stV + ATT_ARR_B + ad);
                #pragma unroll
                for (int hf = 0; hf < 2; hf++)
                    mma_f16(o[nt16 * 2 + hf], ph, &vh4[hf * 2]);
                #pragma unroll
                for (int hf = 0; hf < 2; hf++)
                    mma_f16(o[nt16 * 2 + hf], ph, &vl4[hf * 2]);
            }
        }
        l0 = l0 * c0 + dsum[0];
        l1 = l1 * c1 + dsum[2];

        // ---- advance pipeline ----
        __syncthreads();
        if (kt + 3 < KT) {
            load_kv(kt % 3, kt + 3);
            cp_wait<2>();
            __syncthreads();
        } else if (kt + 2 < KT) {
            cp_wait<1>();
            __syncthreads();
        } else if (kt + 1 < KT) {
            cp_wait<0>();
            __syncthreads();
        }
    }

    // ---- finalize (l already full row sums via sum-MMA) ----
    const float inv0 = 1.f / l0, inv1 = 1.f / l1;

    const size_t row0 = (size_t)b * T_ + qb * 128 + wid * 16 + (lane >> 2);
    const size_t row1 = row0 + 8;
    const int colB = h * HD_ + (lane & 3) * 2;

    #pragma unroll
    for (int nt = 0; nt < 8; nt++) {
        const float v0 = o[nt][0] * inv0, v1 = o[nt][1] * inv0;
        const float v2 = o[nt][2] * inv1, v3 = o[nt][3] * inv1;
        const size_t i0 = row0 * D_ + colB + nt * 8;
        const size_t i1 = row1 * D_ + colB + nt * 8;
        uint32_t hp, lp;
        split_pack_f16(v0, v1, hp, lp);
        reinterpret_cast<uint32_t*>(g_oh)[i0 >> 1] = hp;
        reinterpret_cast<uint32_t*>(g_ol)[i0 >> 1] = lp;
        split_pack_f16(v2, v3, hp, lp);
        reinterpret_cast<uint32_t*>(g_oh)[i1 >> 1] = hp;
        reinterpret_cast<uint32_t*>(g_ol)[i1 >> 1] = lp;
    }
}

// ---------------------------------------------------------------------------
// Conversion kernels
// ---------------------------------------------------------------------------
__global__ __launch_bounds__(256) void split_x_kernel(const float* __restrict__ src)
{
    const int i = blockIdx.x * 256 + threadIdx.x;
    const float v = src[i];
    const __half hv = __float2half_rn(v);
    g_xh[i] = hv;
    g_xl[i] = __float2half_rn(v - __half2float(hv));
}

__global__ __launch_bounds__(256) void wsplit_kernel(
    const float* __restrict__ wq, const float* __restrict__ wk,
    const float* __restrict__ wv, const float* __restrict__ wo)
{
    __shared__ float tile[32][33];
    const int z = blockIdx.z;
    const float* w = (z == 0) ? wq : (z == 1) ? wk : (z == 2) ? wv : wo;
    const int nB = blockIdx.x * 32, kB = blockIdx.y * 32;
    const int tx = threadIdx.x & 31, ty = threadIdx.x >> 5;

    #pragma unroll
    for (int r = ty; r < 32; r += 8)
        tile[r][tx] = w[(size_t)(kB + r) * D_ + nB + tx];
    __syncthreads();
    #pragma unroll
    for (int r = ty; r < 32; r += 8) {
        const float v = tile[tx][r];
        const size_t di = ((size_t)z << 20) + (size_t)(nB + r) * D_ + kB + tx;
        const __half hv = __float2half_rn(v);
        g_wth[di] = hv;
        g_wtl[di] = __float2half_rn(v - __half2float(hv));
    }
}

// ---------------------------------------------------------------------------
extern "C" void kernel_launch(void* const* d_in, const int* in_sizes, int n_in,
                              void* d_out, int out_size)
{
    const float* x  = (const float*)d_in[0];
    const float* wq = (const float*)d_in[1];
    const float* bq = (const float*)d_in[2];
    const float* wk = (const float*)d_in[3];
    const float* bk = (const float*)d_in[4];
    const float* wv = (const float*)d_in[5];
    const float* bv = (const float*)d_in[6];
    const float* wo = (const float*)d_in[7];
    const float* bo = (const float*)d_in[8];
    float* out = (float*)d_out;

    static bool attrSet = false;
    if (!attrSet) {
        cudaFuncSetAttribute(gemm_mma<0>,
                             cudaFuncAttributeMaxDynamicSharedMemorySize, GEMM_SMEM);
        cudaFuncSetAttribute(gemm_mma<1>,
                             cudaFuncAttributeMaxDynamicSharedMemorySize, GEMM_SMEM);
        cudaFuncSetAttribute(attn_mma,
                             cudaFuncAttributeMaxDynamicSharedMemorySize, ATT_SMEM);
        attrSet = true;
    }

    void *pxh, *pxl, *poh, *pol;
    cudaGetSymbolAddress(&pxh, g_xh);
    cudaGetSymbolAddress(&pxl, g_xl);
    cudaGetSymbolAddress(&poh, g_oh);
    cudaGetSymbolAddress(&pol, g_ol);

    const int nElem = M_ * D_;

    // 1) convert inputs to f16 hi/lo
    split_x_kernel<<<nElem / 256, 256>>>(x);
    wsplit_kernel<<<dim3(32, 32, 4), 256>>>(wq, wk, wv, wo);

    // 2) QKV projections -> f16 hi/lo [B,H,T,HD]; Q pre-scaled by 0.125*log2e
    gemm_mma<0><<<dim3(8, 64, 3), 256, GEMM_SMEM>>>(
        (const __half*)pxh, (const __half*)pxl, bq, bk, bv, nullptr, 0);

    // 3) tensor-core causal flash attention -> g_oh/g_ol [B*T, D]
    attn_mma<<<dim3(T_ / 128, H_, B_), 256, ATT_SMEM>>>();

    // 4) output projection
    gemm_mma<1><<<dim3(8, 64, 1), 256, GEMM_SMEM>>>(
        (const __half*)poh, (const __half*)pol, bo, bo, bo, out, 3);
}

// round 8
// speedup vs baseline: 5.4966x; 1.0619x over previous
#include <cuda_runtime.h>
#include <cuda_fp16.h>
#include <cstdint>
#include <cstddef>

// ---------------------------------------------------------------------------
// Problem constants
// ---------------------------------------------------------------------------
constexpr int B_  = 4;
constexpr int T_  = 2048;
constexpr int D_  = 1024;
constexpr int H_  = 16;
constexpr int HD_ = 64;
constexpr int M_  = B_ * T_;   // 8192

// 0.125 * log2(e): folded into Q so softmax uses exp2
constexpr float QSCALE = 0.18033688011112042f;

// ---------------------------------------------------------------------------
// Device scratch (f16 hi/lo splits)
// ---------------------------------------------------------------------------
__device__ __align__(128) __half g_xh[(size_t)M_ * D_];
__device__ __align__(128) __half g_xl[(size_t)M_ * D_];
__device__ __align__(128) __half g_oh[(size_t)M_ * D_];   // [B*T, D]
__device__ __align__(128) __half g_ol[(size_t)M_ * D_];
// QKV in [B, H, T, HD]
__device__ __align__(128) __half g_qh[(size_t)M_ * D_];
__device__ __align__(128) __half g_ql[(size_t)M_ * D_];
__device__ __align__(128) __half g_kh[(size_t)M_ * D_];
__device__ __align__(128) __half g_kl[(size_t)M_ * D_];
__device__ __align__(128) __half g_vh[(size_t)M_ * D_];
__device__ __align__(128) __half g_vl[(size_t)M_ * D_];
// 4 weights transposed to [N, K] f16 hi/lo, z: 0..3 -> wq,wk,wv,wo
__device__ __align__(128) __half g_wth[(size_t)4 * D_ * D_];
__device__ __align__(128) __half g_wtl[(size_t)4 * D_ * D_];

// ---------------------------------------------------------------------------
// PTX helpers
// ---------------------------------------------------------------------------
__device__ __forceinline__ uint32_t smem_u32(const void* p) {
    uint32_t a;
    asm("{ .reg .u64 t; cvta.to.shared.u64 t, %1; cvt.u32.u64 %0, t; }"
        : "=r"(a) : "l"(p));
    return a;
}
__device__ __forceinline__ void cp16(uint32_t saddr, const void* gaddr) {
    asm volatile("cp.async.cg.shared.global [%0], [%1], 16;"
                 :: "r"(saddr), "l"(gaddr));
}
__device__ __forceinline__ void cp_commit() {
    asm volatile("cp.async.commit_group;");
}
template <int N>
__device__ __forceinline__ void cp_wait() {
    asm volatile("cp.async.wait_group %0;" :: "n"(N));
}
__device__ __forceinline__ void ldm_x4(uint32_t* r, uint32_t addr) {
    asm volatile("ldmatrix.sync.aligned.m8n8.x4.shared.b16 {%0,%1,%2,%3}, [%4];"
                 : "=r"(r[0]), "=r"(r[1]), "=r"(r[2]), "=r"(r[3]) : "r"(addr));
}
__device__ __forceinline__ void ldm_x4_t(uint32_t* r, uint32_t addr) {
    asm volatile("ldmatrix.sync.aligned.m8n8.x4.trans.shared.b16 {%0,%1,%2,%3}, [%4];"
                 : "=r"(r[0]), "=r"(r[1]), "=r"(r[2]), "=r"(r[3]) : "r"(addr));
}
__device__ __forceinline__ void mma_f16(float* c, const uint32_t* a,
                                        const uint32_t* b) {
    asm volatile(
        "mma.sync.aligned.m16n8k16.row.col.f32.f16.f16.f32 "
        "{%0,%1,%2,%3}, {%4,%5,%6,%7}, {%8,%9}, {%0,%1,%2,%3};"
        : "+f"(c[0]), "+f"(c[1]), "+f"(c[2]), "+f"(c[3])
        : "r"(a[0]), "r"(a[1]), "r"(a[2]), "r"(a[3]), "r"(b[0]), "r"(b[1]));
}
__device__ __forceinline__ float ex2f(float x) {
    float r;
    asm("ex2.approx.ftz.f32 %0, %1;" : "=f"(r) : "f"(x));
    return r;
}
// packed f16x2: {low=lo, high=hi}
__device__ __forceinline__ uint32_t packh2(float lo, float hi) {
    uint32_t r;
    asm("cvt.rn.f16x2.f32 %0, %1, %2;" : "=r"(r) : "f"(hi), "f"(lo));
    return r;
}
__device__ __forceinline__ uint32_t ex2h2(uint32_t x) {
    uint32_t r;
    asm("ex2.approx.f16x2 %0, %1;" : "=r"(r) : "r"(x));
    return r;
}
// split v0,v1 into f16 hi pair + f16 lo (residual) pair
__device__ __forceinline__ void split_pack_f16(float v0, float v1,
                                               uint32_t& hi, uint32_t& lo) {
    hi = packh2(v0, v1);
    const float h0 = __half2float(__ushort_as_half((unsigned short)(hi & 0xFFFF)));
    const float h1 = __half2float(__ushort_as_half((unsigned short)(hi >> 16)));
    lo = packh2(v0 - h0, v1 - h1);
}

// ---------------------------------------------------------------------------
// HMMA GEMM (f16x3, fp32 accum). 8 warps (4Mx2N), warp 32x64, BK=32,
// 3-stage cp.async with 64B-pitch XOR-swizzled tiles, 2 CTAs/SM. (unchanged)
// ---------------------------------------------------------------------------
constexpr int BK        = 32;
constexpr int G_ARR_B   = 128 * 64;                   // 8192 B per tile array
constexpr int G_STAGE_B = 4 * G_ARR_B;                // 32768 B
constexpr int GEMM_SMEM = 3 * G_STAGE_B;              // 98304 B
constexpr int KT_G      = D_ / BK;                    // 32

__device__ __forceinline__ uint32_t gswz(int row, int chunk) {
    return (uint32_t)row * 64u + (uint32_t)((chunk ^ ((row >> 1) & 3)) << 4);
}

template <int MODE>
__global__ __launch_bounds__(256, 2)
void gemm_mma(const __half* __restrict__ Ah, const __half* __restrict__ Al,
              const float* __restrict__ b0, const float* __restrict__ b1,
              const float* __restrict__ b2,
              float* __restrict__ out, int zbase)
{
    extern __shared__ __align__(128) char smem[];
    const uint32_t sb = smem_u32(smem);

    const int tid  = threadIdx.x;
    const int wid  = tid >> 5;
    const int lane = tid & 31;
    const int wm   = (wid & 3) * 32;
    const int wn   = (wid >> 2) * 64;

    const int mBase = blockIdx.y * 128;
    const int nBase = blockIdx.x * 128;
    const int z     = zbase + blockIdx.z;

    const __half* Bh = g_wth + ((size_t)z << 20);
    const __half* Bl = g_wtl + ((size_t)z << 20);

    const int c0r = tid >> 2,         c0q = tid & 3;
    const int c1r = (tid + 256) >> 2, c1q = (tid + 256) & 3;
    const uint32_t s0 = gswz(c0r, c0q), s1 = gswz(c1r, c1q);

    auto load_stage = [&](int stg, int kt) {
        const uint32_t st = sb + stg * G_STAGE_B;
        const int bk = kt * BK;
        {
            const size_t ga = (size_t)(mBase + c0r) * D_ + bk + c0q * 8;
            const size_t gb = (size_t)(mBase + c1r) * D_ + bk + c1q * 8;
            cp16(st + s0,           Ah + ga);
            cp16(st + s1,           Ah + gb);
            cp16(st + G_ARR_B + s0, Al + ga);
            cp16(st + G_ARR_B + s1, Al + gb);
        }
        {
            const size_t ga = (size_t)(nBase + c0r) * D_ + bk + c0q * 8;
            const size_t gb = (size_t)(nBase + c1r) * D_ + bk + c1q * 8;
            cp16(st + 2 * G_ARR_B + s0, Bh + ga);
            cp16(st + 2 * G_ARR_B + s1, Bh + gb);
            cp16(st + 3 * G_ARR_B + s0, Bl + ga);
            cp16(st + 3 * G_ARR_B + s1, Bl + gb);
        }
        cp_commit();
    };

    float acc[2][8][4];
    #pragma unroll
    for (int mi = 0; mi < 2; mi++)
        #pragma unroll
        for (int ni = 0; ni < 8; ni++)
            #pragma unroll
            for (int r = 0; r < 4; r++) acc[mi][ni][r] = 0.f;

    load_stage(0, 0);
    load_stage(1, 1);
    load_stage(2, 2);

    int rowA[2], rowB[4];
    #pragma unroll
    for (int mi = 0; mi < 2; mi++)
        rowA[mi] = wm + (lane & 7) + ((lane >> 3) & 1) * 8 + mi * 16;
    #pragma unroll
    for (int p = 0; p < 4; p++)
        rowB[p] = wn + ((lane >> 4) & 1) * 8 + (lane & 7) + p * 16;
    const int chA = (lane >> 4) & 1;
    const int chB = (lane >> 3) & 1;

    cp_wait<2>();
    __syncthreads();

    #pragma unroll 1
    for (int kt = 0; kt < KT_G; kt++) {
        const uint32_t st  = sb + (kt % 3) * G_STAGE_B;
        const uint32_t sAh = st;
        const uint32_t sAl = st + G_ARR_B;
        const uint32_t sBh = st + 2 * G_ARR_B;
        const uint32_t sBl = st + 3 * G_ARR_B;

        #pragma unroll
        for (int ks = 0; ks < 2; ks++) {
            uint32_t ah[2][4], al[2][4];
            #pragma unroll
            for (int mi = 0; mi < 2; mi++) {
                const uint32_t off = gswz(rowA[mi], chA + ks * 2);
                ldm_x4(ah[mi], sAh + off);
                ldm_x4(al[mi], sAl + off);
            }
            uint32_t bh4[4][4], bl4[4][4];
            #pragma unroll
            for (int p = 0; p < 4; p++) {
                const uint32_t off = gswz(rowB[p], chB + ks * 2);
                ldm_x4(bh4[p], sBh + off);
                ldm_x4(bl4[p], sBl + off);
            }
            #pragma unroll
            for (int mi = 0; mi < 2; mi++)
                #pragma unroll
                for (int p = 0; p < 4; p++)
                    #pragma unroll
                    for (int hf = 0; hf < 2; hf++)
                        mma_f16(acc[mi][p * 2 + hf], ah[mi], &bh4[p][hf * 2]);
            #pragma unroll
            for (int mi = 0; mi < 2; mi++)
                #pragma unroll
                for (int p = 0; p < 4; p++)
                    #pragma unroll
                    for (int hf = 0; hf < 2; hf++)
                        mma_f16(acc[mi][p * 2 + hf], ah[mi], &bl4[p][hf * 2]);
            #pragma unroll
            for (int mi = 0; mi < 2; mi++)
                #pragma unroll
                for (int p = 0; p < 4; p++)
                    #pragma unroll
                    for (int hf = 0; hf < 2; hf++)
                        mma_f16(acc[mi][p * 2 + hf], al[mi], &bh4[p][hf * 2]);
        }
        __syncthreads();
        if (kt + 3 < KT_G) {
            load_stage(kt % 3, kt + 3);
            cp_wait<2>();
            __syncthreads();
        } else if (kt + 2 < KT_G) {
            cp_wait<1>();
            __syncthreads();
        } else if (kt + 1 < KT_G) {
            cp_wait<0>();
            __syncthreads();
        }
    }

    // --- epilogue ---
    const float* bias = (MODE == 0)
        ? (blockIdx.z == 0 ? b0 : blockIdx.z == 1 ? b1 : b2) : b0;

    __half *dh = nullptr, *dl = nullptr;
    float scale = 1.f;
    if (MODE == 0) {
        if (blockIdx.z == 0)      { dh = g_qh; dl = g_ql; scale = QSCALE; }
        else if (blockIdx.z == 1) { dh = g_kh; dl = g_kl; }
        else                      { dh = g_vh; dl = g_vl; }
    }

    #pragma unroll
    for (int mi = 0; mi < 2; mi++) {
        #pragma unroll
        for (int ni = 0; ni < 8; ni++) {
            const int n0 = nBase + wn + ni * 8 + (lane & 3) * 2;
            const float bv0 = __ldg(bias + n0), bv1 = __ldg(bias + n0 + 1);
            #pragma unroll
            for (int rr = 0; rr < 2; rr++) {
                const int m = mBase + wm + mi * 16 + (lane >> 2) + rr * 8;
                float v0 = acc[mi][ni][rr * 2 + 0] + bv0;
                float v1 = acc[mi][ni][rr * 2 + 1] + bv1;
                if (MODE == 0) {
                    v0 *= scale; v1 *= scale;
                    const int bb = m >> 11, tt = m & 2047;
                    const int hh = n0 >> 6, hd = n0 & 63;
                    const size_t idx =
                        ((((size_t)bb * H_ + hh) * T_ + tt) << 6) + hd;
                    uint32_t hp, lp;
                    split_pack_f16(v0, v1, hp, lp);
                    reinterpret_cast<uint32_t*>(dh)[idx >> 1] = hp;
                    reinterpret_cast<uint32_t*>(dl)[idx >> 1] = lp;
                } else {
                    *reinterpret_cast<float2*>(out + (size_t)m * D_ + n0) =
                        make_float2(v0, v1);
                }
            }
        }
    }
}

// ---------------------------------------------------------------------------
// Tensor-core causal flash attention.
// f16x3 for S = QK^T; P native f16 via ex2.approx.f16x2; PV = P·Vh only
// (V-lo dropped: adds ~2.4e-4 rms, cuts MMAs 20% / LDSM 25% / loads 25%).
// 4-stage KV pipeline (kh,kl,vh = 24KB/stage), SW128 swizzle, 2 CTAs/SM.
// ---------------------------------------------------------------------------
constexpr int ATT_ARR_B   = 64 * 128;                 // 8192 per array
constexpr int ATT_STAGE_B = 3 * ATT_ARR_B;            // 24576 (kh,kl,vh)
constexpr int ATT_NSTG    = 4;
constexpr int ATT_SMEM    = ATT_NSTG * ATT_STAGE_B;   // 98304 -> 2 CTAs/SM

// 128B-pitch SW128 swizzle
__device__ __forceinline__ uint32_t aswz(int row, int chunk) {
    return (uint32_t)row * 128u + (uint32_t)((chunk ^ (row & 7)) << 4);
}

__global__ __launch_bounds__(256, 2)
void attn_mma()
{
    extern __shared__ __align__(128) char smem[];
    const uint32_t sb = smem_u32(smem);

    const int tid  = threadIdx.x;
    const int wid  = tid >> 5;
    const int lane = tid & 31;

    const int qb = (gridDim.x - 1) - blockIdx.x;     // largest-first
    const int h  = blockIdx.y, b = blockIdx.z;
    const size_t bh = ((size_t)(b * H_ + h)) * T_ * HD_;

    const __half* Qh = g_qh + bh + (size_t)qb * 128 * HD_;
    const __half* Ql = g_ql + bh + (size_t)qb * 128 * HD_;
    const __half* Kh = g_kh + bh;
    const __half* Kl = g_kl + bh;
    const __half* Vh = g_vh + bh;

    const int KT = 2 * qb + 2;   // >= 2

    // ---- prologue: Q -> stages 2..3 region (32KB of 48KB) ----
    const uint32_t qsb = sb + 2 * ATT_STAGE_B;
    #pragma unroll
    for (int i = 0; i < 8; i++) {
        const int c = i * 256 + tid;
        const int arr = c >> 10, row = (c >> 3) & 127, q8 = c & 7;
        const __half* src = (arr ? Ql : Qh) + (size_t)row * HD_ + q8 * 8;
        cp16(qsb + arr * (128 * 128) + aswz(row, q8), src);
    }
    cp_commit();                                     // group: Q

    auto load_kv = [&](int stg, int kt) {
        const uint32_t base = sb + stg * ATT_STAGE_B;
        #pragma unroll
        for (int i = 0; i < 6; i++) {                // 3 arrays * 512 chunks
            const int c = i * 256 + tid;
            const int arr = c >> 9, row = (c >> 3) & 63, q8 = c & 7;
            const __half* g = (arr == 0) ? Kh : (arr == 1) ? Kl : Vh;
            cp16(base + arr * ATT_ARR_B + aswz(row, q8),
                 g + (size_t)(kt * 64 + row) * HD_ + q8 * 8);
        }
        cp_commit();
    };
    load_kv(0, 0);
    load_kv(1, 1);

    // ---- Q fragments to registers ----
    cp_wait<2>();            // Q done
    __syncthreads();
    uint32_t qfh[4][4], qfl[4][4];
    {
        const int rowQ = wid * 16 + (lane & 7) + ((lane >> 3) & 1) * 8;
        const int chQ  = (lane >> 4) & 1;
        #pragma unroll
        for (int kc = 0; kc < 4; kc++) {
            const uint32_t off = aswz(rowQ, chQ + kc * 2);
            ldm_x4(qfh[kc], qsb + off);
            ldm_x4(qfl[kc], qsb + 128 * 128 + off);
        }
    }
    __syncthreads();                           // all warps done reading Q smem
    load_kv(2, (2 < KT) ? 2 : KT - 1);         // clamp: dup loads never read
    load_kv(3, (3 < KT) ? 3 : KT - 1);
    cp_wait<3>();                              // KV0 ready
    __syncthreads();

    float o[8][4];
    #pragma unroll
    for (int nt = 0; nt < 8; nt++)
        #pragma unroll
        for (int r = 0; r < 4; r++) o[nt][r] = 0.f;
    float m0 = -1e30f, m1 = -1e30f, l0 = 0.f, l1 = 0.f;

    const int r0g = qb * 128 + wid * 16 + (lane >> 2);

    const int rKbase = ((lane >> 4) & 1) * 8 + (lane & 7);
    const int chK    = (lane >> 3) & 1;
    const int rVbase = (lane & 7) + ((lane >> 3) & 1) * 8;
    const int chV    = (lane >> 4) & 1;

    const uint32_t ONES2[2] = {0x3C003C00u, 0x3C003C00u};

    #pragma unroll 1
    for (int kt = 0; kt < KT; kt++) {
        const uint32_t st  = sb + (kt % ATT_NSTG) * ATT_STAGE_B;
        const uint32_t stK = st;
        const uint32_t stV = st + 2 * ATT_ARR_B;

        // ---- S = Q K^T (f16x3) ----
        float s[8][4];
        #pragma unroll
        for (int nt = 0; nt < 8; nt++)
            #pragma unroll
            for (int r = 0; r < 4; r++) s[nt][r] = 0.f;

        #pragma unroll
        for (int kc = 0; kc < 4; kc++) {
            #pragma unroll
            for (int g = 0; g < 2; g++) {
                uint32_t kh4[2][4], kl4[2][4];
                #pragma unroll
                for (int t = 0; t < 2; t++) {
                    const int nt16 = g * 2 + t;
                    const uint32_t ad = aswz(rKbase + nt16 * 16, chK + kc * 2);
                    ldm_x4(kh4[t], stK + ad);
                    ldm_x4(kl4[t], stK + ATT_ARR_B + ad);
                }
                #pragma unroll
                for (int t = 0; t < 2; t++)
                    #pragma unroll
                    for (int hf = 0; hf < 2; hf++)
                        mma_f16(s[(g * 2 + t) * 2 + hf], qfh[kc], &kh4[t][hf * 2]);
                #pragma unroll
                for (int t = 0; t < 2; t++)
                    #pragma unroll
                    for (int hf = 0; hf < 2; hf++)
                        mma_f16(s[(g * 2 + t) * 2 + hf], qfl[kc], &kh4[t][hf * 2]);
                #pragma unroll
                for (int t = 0; t < 2; t++)
                    #pragma unroll
                    for (int hf = 0; hf < 2; hf++)
                        mma_f16(s[(g * 2 + t) * 2 + hf], qfh[kc], &kl4[t][hf * 2]);
            }
        }

        // ---- causal mask (last two tiles only) ----
        if (kt >= KT - 2) {
            const int colBase = kt * 64 + (lane & 3) * 2;
            #pragma unroll
            for (int nt = 0; nt < 8; nt++)
                #pragma unroll
                for (int j = 0; j < 2; j++) {
                    const int c = colBase + nt * 8 + j;
                    if (c > r0g)     s[nt][j]     = -30000.f;
                    if (c > r0g + 8) s[nt][2 + j] = -30000.f;
                }
        }

        // ---- max-reduce + o rescale ----
        float tm0 = -1e30f, tm1 = -1e30f;
        #pragma unroll
        for (int nt = 0; nt < 8; nt++) {
            tm0 = fmaxf(tm0, fmaxf(s[nt][0], s[nt][1]));
            tm1 = fmaxf(tm1, fmaxf(s[nt][2], s[nt][3]));
        }
        tm0 = fmaxf(tm0, __shfl_xor_sync(0xffffffffu, tm0, 1));
        tm0 = fmaxf(tm0, __shfl_xor_sync(0xffffffffu, tm0, 2));
        tm1 = fmaxf(tm1, __shfl_xor_sync(0xffffffffu, tm1, 1));
        tm1 = fmaxf(tm1, __shfl_xor_sync(0xffffffffu, tm1, 2));

        const float mn0 = fmaxf(m0, tm0), mn1 = fmaxf(m1, tm1);
        const float c0 = ex2f(m0 - mn0), c1 = ex2f(m1 - mn1);
        m0 = mn0; m1 = mn1;

        #pragma unroll
        for (int nt = 0; nt < 8; nt++) {
            o[nt][0] *= c0; o[nt][1] *= c0;
            o[nt][2] *= c1; o[nt][3] *= c1;
        }

        // ---- P = ex2(S-m) f16; row sums via MMA; O += P Vh ----
        float dsum[4] = {0.f, 0.f, 0.f, 0.f};
        #pragma unroll
        for (int kc = 0; kc < 4; kc++) {
            const float* s0 = s[2 * kc];
            const float* s1 = s[2 * kc + 1];
            uint32_t ph[4];
            ph[0] = ex2h2(packh2(s0[0] - mn0, s0[1] - mn0));
            ph[1] = ex2h2(packh2(s0[2] - mn1, s0[3] - mn1));
            ph[2] = ex2h2(packh2(s1[0] - mn0, s1[1] - mn0));
            ph[3] = ex2h2(packh2(s1[2] - mn1, s1[3] - mn1));

            mma_f16(dsum, ph, ONES2);   // row sums of this 16-key chunk

            const int rowV = rVbase + kc * 16;
            #pragma unroll
            for (int nt16 = 0; nt16 < 4; nt16++) {
                uint32_t vh4[4];
                ldm_x4_t(vh4, stV + aswz(rowV, chV + nt16 * 2));
                #pragma unroll
                for (int hf = 0; hf < 2; hf++)
                    mma_f16(o[nt16 * 2 + hf], ph, &vh4[hf * 2]);
            }
        }
        l0 = l0 * c0 + dsum[0];
        l1 = l1 * c1 + dsum[2];

        // ---- advance pipeline (prefetch distance 3) ----
        __syncthreads();
        if (kt + 4 < KT) {
            load_kv(kt % ATT_NSTG, kt + 4);
            cp_wait<3>();
            __syncthreads();
        } else if (kt + 3 < KT) {
            cp_wait<2>();
            __syncthreads();
        } else if (kt + 2 < KT) {
            cp_wait<1>();
            __syncthreads();
        } else if (kt + 1 < KT) {
            cp_wait<0>();
            __syncthreads();
        }
    }

    // ---- finalize ----
    const float inv0 = 1.f / l0, inv1 = 1.f / l1;

    const size_t row0 = (size_t)b * T_ + qb * 128 + wid * 16 + (lane >> 2);
    const size_t row1 = row0 + 8;
    const int colB = h * HD_ + (lane & 3) * 2;

    #pragma unroll
    for (int nt = 0; nt < 8; nt++) {
        const float v0 = o[nt][0] * inv0, v1 = o[nt][1] * inv0;
        const float v2 = o[nt][2] * inv1, v3 = o[nt][3] * inv1;
        const size_t i0 = row0 * D_ + colB + nt * 8;
        const size_t i1 = row1 * D_ + colB + nt * 8;
        uint32_t hp, lp;
        split_pack_f16(v0, v1, hp, lp);
        reinterpret_cast<uint32_t*>(g_oh)[i0 >> 1] = hp;
        reinterpret_cast<uint32_t*>(g_ol)[i0 >> 1] = lp;
        split_pack_f16(v2, v3, hp, lp);
        reinterpret_cast<uint32_t*>(g_oh)[i1 >> 1] = hp;
        reinterpret_cast<uint32_t*>(g_ol)[i1 >> 1] = lp;
    }
}

// ---------------------------------------------------------------------------
// Conversion kernels
// ---------------------------------------------------------------------------
__global__ __launch_bounds__(256) void split_x_kernel(const float* __restrict__ src)
{
    const int i = blockIdx.x * 256 + threadIdx.x;
    const float v = src[i];
    const __half hv = __float2half_rn(v);
    g_xh[i] = hv;
    g_xl[i] = __float2half_rn(v - __half2float(hv));
}

__global__ __launch_bounds__(256) void wsplit_kernel(
    const float* __restrict__ wq, const float* __restrict__ wk,
    const float* __restrict__ wv, const float* __restrict__ wo)
{
    __shared__ float tile[32][33];
    const int z = blockIdx.z;
    const float* w = (z == 0) ? wq : (z == 1) ? wk : (z == 2) ? wv : wo;
    const int nB = blockIdx.x * 32, kB = blockIdx.y * 32;
    const int tx = threadIdx.x & 31, ty = threadIdx.x >> 5;

    #pragma unroll
    for (int r = ty; r < 32; r += 8)
        tile[r][tx] = w[(size_t)(kB + r) * D_ + nB + tx];
    __syncthreads();
    #pragma unroll
    for (int r = ty; r < 32; r += 8) {
        const float v = tile[tx][r];
        const size_t di = ((size_t)z << 20) + (size_t)(nB + r) * D_ + kB + tx;
        const __half hv = __float2half_rn(v);
        g_wth[di] = hv;
        g_wtl[di] = __float2half_rn(v - __half2float(hv));
    }
}

// ---------------------------------------------------------------------------
extern "C" void kernel_launch(void* const* d_in, const int* in_sizes, int n_in,
                              void* d_out, int out_size)
{
    const float* x  = (const float*)d_in[0];
    const float* wq = (const float*)d_in[1];
    const float* bq = (const float*)d_in[2];
    const float* wk = (const float*)d_in[3];
    const float* bk = (const float*)d_in[4];
    const float* wv = (const float*)d_in[5];
    const float* bv = (const float*)d_in[6];
    const float* wo = (const float*)d_in[7];
    const float* bo = (const float*)d_in[8];
    float* out = (float*)d_out;

    static bool attrSet = false;
    if (!attrSet) {
        cudaFuncSetAttribute(gemm_mma<0>,
                             cudaFuncAttributeMaxDynamicSharedMemorySize, GEMM_SMEM);
        cudaFuncSetAttribute(gemm_mma<1>,
                             cudaFuncAttributeMaxDynamicSharedMemorySize, GEMM_SMEM);
        cudaFuncSetAttribute(attn_mma,
                             cudaFuncAttributeMaxDynamicSharedMemorySize, ATT_SMEM);
        attrSet = true;
    }

    void *pxh, *pxl, *poh, *pol;
    cudaGetSymbolAddress(&pxh, g_xh);
    cudaGetSymbolAddress(&pxl, g_xl);
    cudaGetSymbolAddress(&poh, g_oh);
    cudaGetSymbolAddress(&pol, g_ol);

    const int nElem = M_ * D_;

    // 1) convert inputs to f16 hi/lo
    split_x_kernel<<<nElem / 256, 256>>>(x);
    wsplit_kernel<<<dim3(32, 32, 4), 256>>>(wq, wk, wv, wo);

    // 2) QKV projections -> f16 hi/lo [B,H,T,HD]; Q pre-scaled by 0.125*log2e
    gemm_mma<0><<<dim3(8, 64, 3), 256, GEMM_SMEM>>>(
        (const __half*)pxh, (const __half*)pxl, bq, bk, bv, nullptr, 0);

    // 3) tensor-core causal flash attention -> g_oh/g_ol [B*T, D]
    attn_mma<<<dim3(T_ / 128, H_, B_), 256, ATT_SMEM>>>();

    // 4) output projection
    gemm_mma<1><<<dim3(8, 64, 1), 256, GEMM_SMEM>>>(
        (const __half*)poh, (const __half*)pol, bo, bo, bo, out, 3);
}

// round 9
// speedup vs baseline: 6.9078x; 1.2567x over previous
#include <cuda_runtime.h>
#include <cuda_fp16.h>
#include <cstdint>
#include <cstddef>

// ---------------------------------------------------------------------------
// Problem constants
// ---------------------------------------------------------------------------
constexpr int B_  = 4;
constexpr int T_  = 2048;
constexpr int D_  = 1024;
constexpr int H_  = 16;
constexpr int HD_ = 64;
constexpr int M_  = B_ * T_;   // 8192

// 0.125 * log2(e): folded into Q so softmax uses exp2
constexpr float QSCALE = 0.18033688011112042f;

// ---------------------------------------------------------------------------
// Device scratch
// ---------------------------------------------------------------------------
__device__ __align__(128) __half g_x16[(size_t)M_ * D_];   // x quantized f16
__device__ __align__(128) __half g_o16[(size_t)M_ * D_];   // attnO f16 [B*T, D]
// QKV in [B, H, T, HD], f16 hi/lo
__device__ __align__(128) __half g_qh[(size_t)M_ * D_];
__device__ __align__(128) __half g_ql[(size_t)M_ * D_];
__device__ __align__(128) __half g_kh[(size_t)M_ * D_];
__device__ __align__(128) __half g_kl[(size_t)M_ * D_];
__device__ __align__(128) __half g_vh[(size_t)M_ * D_];
// 4 weights transposed to [N, K] f16 hi/lo, z: 0..3 -> wq,wk,wv,wo
__device__ __align__(128) __half g_wth[(size_t)4 * D_ * D_];
__device__ __align__(128) __half g_wtl[(size_t)4 * D_ * D_];

// ---------------------------------------------------------------------------
// PTX helpers
// ---------------------------------------------------------------------------
__device__ __forceinline__ uint32_t smem_u32(const void* p) {
    uint32_t a;
    asm("{ .reg .u64 t; cvta.to.shared.u64 t, %1; cvt.u32.u64 %0, t; }"
        : "=r"(a) : "l"(p));
    return a;
}
__device__ __forceinline__ void cp16(uint32_t saddr, const void* gaddr) {
    asm volatile("cp.async.cg.shared.global [%0], [%1], 16;"
                 :: "r"(saddr), "l"(gaddr));
}
__device__ __forceinline__ void cp_commit() {
    asm volatile("cp.async.commit_group;");
}
template <int N>
__device__ __forceinline__ void cp_wait() {
    asm volatile("cp.async.wait_group %0;" :: "n"(N));
}
__device__ __forceinline__ void ldm_x4(uint32_t* r, uint32_t addr) {
    asm volatile("ldmatrix.sync.aligned.m8n8.x4.shared.b16 {%0,%1,%2,%3}, [%4];"
                 : "=r"(r[0]), "=r"(r[1]), "=r"(r[2]), "=r"(r[3]) : "r"(addr));
}
__device__ __forceinline__ void ldm_x4_t(uint32_t* r, uint32_t addr) {
    asm volatile("ldmatrix.sync.aligned.m8n8.x4.trans.shared.b16 {%0,%1,%2,%3}, [%4];"
                 : "=r"(r[0]), "=r"(r[1]), "=r"(r[2]), "=r"(r[3]) : "r"(addr));
}
__device__ __forceinline__ void mma_f16(float* c, const uint32_t* a,
                                        const uint32_t* b) {
    asm volatile(
        "mma.sync.aligned.m16n8k16.row.col.f32.f16.f16.f32 "
        "{%0,%1,%2,%3}, {%4,%5,%6,%7}, {%8,%9}, {%0,%1,%2,%3};"
        : "+f"(c[0]), "+f"(c[1]), "+f"(c[2]), "+f"(c[3])
        : "r"(a[0]), "r"(a[1]), "r"(a[2]), "r"(a[3]), "r"(b[0]), "r"(b[1]));
}
__device__ __forceinline__ float ex2f(float x) {
    float r;
    asm("ex2.approx.ftz.f32 %0, %1;" : "=f"(r) : "f"(x));
    return r;
}
// packed f16x2: {low=lo, high=hi}
__device__ __forceinline__ uint32_t packh2(float lo, float hi) {
    uint32_t r;
    asm("cvt.rn.f16x2.f32 %0, %1, %2;" : "=r"(r) : "f"(hi), "f"(lo));
    return r;
}
__device__ __forceinline__ uint32_t ex2h2(uint32_t x) {
    uint32_t r;
    asm("ex2.approx.f16x2 %0, %1;" : "=r"(r) : "r"(x));
    return r;
}
// split v0,v1 into f16 hi pair + f16 lo (residual) pair
__device__ __forceinline__ void split_pack_f16(float v0, float v1,
                                               uint32_t& hi, uint32_t& lo) {
    hi = packh2(v0, v1);
    const float h0 = __half2float(__ushort_as_half((unsigned short)(hi & 0xFFFF)));
    const float h1 = __half2float(__ushort_as_half((unsigned short)(hi >> 16)));
    lo = packh2(v0 - h0, v1 - h1);
}

// ---------------------------------------------------------------------------
// HMMA GEMM, 2-term: C = A16 @ (Wh + Wl)^T + bias, fp32 accum.
// 8 warps (4Mx2N), warp 32x64, BK=32, 4-stage cp.async (24KB/stage, XOR
// swizzle), 2 CTAs/SM.
// MODE 0: dst = q/k/v f16 (hi/lo) [B,H,T,HD]; Q pre-scaled.
// MODE 1: dst = out fp32 [M, D].
// ---------------------------------------------------------------------------
constexpr int BK        = 32;
constexpr int G_ARR_B   = 128 * 64;                   // 8192 B per tile array
constexpr int G_STAGE_B = 3 * G_ARR_B;                // 24576 (A, Bh, Bl)
constexpr int G_NSTG    = 4;
constexpr int GEMM_SMEM = G_NSTG * G_STAGE_B;         // 98304 -> 2 CTAs/SM
constexpr int KT_G      = D_ / BK;                    // 32

__device__ __forceinline__ uint32_t gswz(int row, int chunk) {
    return (uint32_t)row * 64u + (uint32_t)((chunk ^ ((row >> 1) & 3)) << 4);
}

template <int MODE>
__global__ __launch_bounds__(256, 2)
void gemm_mma(const __half* __restrict__ A,
              const float* __restrict__ b0, const float* __restrict__ b1,
              const float* __restrict__ b2,
              float* __restrict__ out, int zbase)
{
    extern __shared__ __align__(128) char smem[];
    const uint32_t sb = smem_u32(smem);

    const int tid  = threadIdx.x;
    const int wid  = tid >> 5;
    const int lane = tid & 31;
    const int wm   = (wid & 3) * 32;
    const int wn   = (wid >> 2) * 64;

    const int mBase = blockIdx.y * 128;
    const int nBase = blockIdx.x * 128;
    const int z     = zbase + blockIdx.z;

    const __half* Bh = g_wth + ((size_t)z << 20);
    const __half* Bl = g_wtl + ((size_t)z << 20);

    const int c0r = tid >> 2,         c0q = tid & 3;
    const int c1r = (tid + 256) >> 2, c1q = (tid + 256) & 3;
    const uint32_t s0 = gswz(c0r, c0q), s1 = gswz(c1r, c1q);

    auto load_stage = [&](int stg, int kt) {
        const uint32_t st = sb + stg * G_STAGE_B;
        const int bk = kt * BK;
        {
            const size_t ga = (size_t)(mBase + c0r) * D_ + bk + c0q * 8;
            const size_t gb = (size_t)(mBase + c1r) * D_ + bk + c1q * 8;
            cp16(st + s0, A + ga);
            cp16(st + s1, A + gb);
        }
        {
            const size_t ga = (size_t)(nBase + c0r) * D_ + bk + c0q * 8;
            const size_t gb = (size_t)(nBase + c1r) * D_ + bk + c1q * 8;
            cp16(st + G_ARR_B + s0,     Bh + ga);
            cp16(st + G_ARR_B + s1,     Bh + gb);
            cp16(st + 2 * G_ARR_B + s0, Bl + ga);
            cp16(st + 2 * G_ARR_B + s1, Bl + gb);
        }
        cp_commit();
    };

    float acc[2][8][4];
    #pragma unroll
    for (int mi = 0; mi < 2; mi++)
        #pragma unroll
        for (int ni = 0; ni < 8; ni++)
            #pragma unroll
            for (int r = 0; r < 4; r++) acc[mi][ni][r] = 0.f;

    load_stage(0, 0);
    load_stage(1, 1);
    load_stage(2, 2);
    load_stage(3, 3);

    int rowA[2], rowB[4];
    #pragma unroll
    for (int mi = 0; mi < 2; mi++)
        rowA[mi] = wm + (lane & 7) + ((lane >> 3) & 1) * 8 + mi * 16;
    #pragma unroll
    for (int p = 0; p < 4; p++)
        rowB[p] = wn + ((lane >> 4) & 1) * 8 + (lane & 7) + p * 16;
    const int chA = (lane >> 4) & 1;
    const int chB = (lane >> 3) & 1;

    cp_wait<3>();            // stage 0 ready
    __syncthreads();

    #pragma unroll 1
    for (int kt = 0; kt < KT_G; kt++) {
        const uint32_t st  = sb + (kt % G_NSTG) * G_STAGE_B;
        const uint32_t sA  = st;
        const uint32_t sBh = st + G_ARR_B;
        const uint32_t sBl = st + 2 * G_ARR_B;

        #pragma unroll
        for (int ks = 0; ks < 2; ks++) {
            uint32_t af[2][4];
            #pragma unroll
            for (int mi = 0; mi < 2; mi++)
                ldm_x4(af[mi], sA + gswz(rowA[mi], chA + ks * 2));
            uint32_t bh4[4][4], bl4[4][4];
            #pragma unroll
            for (int p = 0; p < 4; p++) {
                const uint32_t off = gswz(rowB[p], chB + ks * 2);
                ldm_x4(bh4[p], sBh + off);
                ldm_x4(bl4[p], sBl + off);
            }
            #pragma unroll
            for (int mi = 0; mi < 2; mi++)
                #pragma unroll
                for (int p = 0; p < 4; p++)
                    #pragma unroll
                    for (int hf = 0; hf < 2; hf++)
                        mma_f16(acc[mi][p * 2 + hf], af[mi], &bh4[p][hf * 2]);
            #pragma unroll
            for (int mi = 0; mi < 2; mi++)
                #pragma unroll
                for (int p = 0; p < 4; p++)
                    #pragma unroll
                    for (int hf = 0; hf < 2; hf++)
                        mma_f16(acc[mi][p * 2 + hf], af[mi], &bl4[p][hf * 2]);
        }
        __syncthreads();
        if (kt + 4 < KT_G) {
            load_stage(kt % G_NSTG, kt + 4);
            cp_wait<3>();
            __syncthreads();
        } else if (kt + 3 < KT_G) {
            cp_wait<2>();
            __syncthreads();
        } else if (kt + 2 < KT_G) {
            cp_wait<1>();
            __syncthreads();
        } else if (kt + 1 < KT_G) {
            cp_wait<0>();
            __syncthreads();
        }
    }

    // --- epilogue ---
    const float* bias = (MODE == 0)
        ? (blockIdx.z == 0 ? b0 : blockIdx.z == 1 ? b1 : b2) : b0;

    __half *dh = nullptr, *dl = nullptr;
    float scale = 1.f;
    if (MODE == 0) {
        if (blockIdx.z == 0)      { dh = g_qh; dl = g_ql; scale = QSCALE; }
        else if (blockIdx.z == 1) { dh = g_kh; dl = g_kl; }
        else                      { dh = g_vh; dl = nullptr; }
    }

    #pragma unroll
    for (int mi = 0; mi < 2; mi++) {
        #pragma unroll
        for (int ni = 0; ni < 8; ni++) {
            const int n0 = nBase + wn + ni * 8 + (lane & 3) * 2;
            const float bv0 = __ldg(bias + n0), bv1 = __ldg(bias + n0 + 1);
            #pragma unroll
            for (int rr = 0; rr < 2; rr++) {
                const int m = mBase + wm + mi * 16 + (lane >> 2) + rr * 8;
                float v0 = acc[mi][ni][rr * 2 + 0] + bv0;
                float v1 = acc[mi][ni][rr * 2 + 1] + bv1;
                if (MODE == 0) {
                    v0 *= scale; v1 *= scale;
                    const int bb = m >> 11, tt = m & 2047;
                    const int hh = n0 >> 6, hd = n0 & 63;
                    const size_t idx =
                        ((((size_t)bb * H_ + hh) * T_ + tt) << 6) + hd;
                    if (dl) {
                        uint32_t hp, lp;
                        split_pack_f16(v0, v1, hp, lp);
                        reinterpret_cast<uint32_t*>(dh)[idx >> 1] = hp;
                        reinterpret_cast<uint32_t*>(dl)[idx >> 1] = lp;
                    } else {
                        reinterpret_cast<uint32_t*>(dh)[idx >> 1] = packh2(v0, v1);
                    }
                } else {
                    *reinterpret_cast<float2*>(out + (size_t)m * D_ + n0) =
                        make_float2(v0, v1);
                }
            }
        }
    }
}

// ---------------------------------------------------------------------------
// Tensor-core causal flash attention (unchanged from R8 except f16-only out).
// f16x3 for S = QK^T; P native f16 via ex2.approx.f16x2; PV = P·Vh.
// 4-stage KV pipeline (kh,kl,vh = 24KB/stage), SW128 swizzle, 2 CTAs/SM.
// ---------------------------------------------------------------------------
constexpr int ATT_ARR_B   = 64 * 128;                 // 8192 per array
constexpr int ATT_STAGE_B = 3 * ATT_ARR_B;            // 24576 (kh,kl,vh)
constexpr int ATT_NSTG    = 4;
constexpr int ATT_SMEM    = ATT_NSTG * ATT_STAGE_B;   // 98304 -> 2 CTAs/SM

__device__ __forceinline__ uint32_t aswz(int row, int chunk) {
    return (uint32_t)row * 128u + (uint32_t)((chunk ^ (row & 7)) << 4);
}

__global__ __launch_bounds__(256, 2)
void attn_mma()
{
    extern __shared__ __align__(128) char smem[];
    const uint32_t sb = smem_u32(smem);

    const int tid  = threadIdx.x;
    const int wid  = tid >> 5;
    const int lane = tid & 31;

    const int qb = (gridDim.x - 1) - blockIdx.x;     // largest-first
    const int h  = blockIdx.y, b = blockIdx.z;
    const size_t bh = ((size_t)(b * H_ + h)) * T_ * HD_;

    const __half* Qh = g_qh + bh + (size_t)qb * 128 * HD_;
    const __half* Ql = g_ql + bh + (size_t)qb * 128 * HD_;
    const __half* Kh = g_kh + bh;
    const __half* Kl = g_kl + bh;
    const __half* Vh = g_vh + bh;

    const int KT = 2 * qb + 2;   // >= 2

    // ---- prologue: Q -> stages 2..3 region ----
    const uint32_t qsb = sb + 2 * ATT_STAGE_B;
    #pragma unroll
    for (int i = 0; i < 8; i++) {
        const int c = i * 256 + tid;
        const int arr = c >> 10, row = (c >> 3) & 127, q8 = c & 7;
        const __half* src = (arr ? Ql : Qh) + (size_t)row * HD_ + q8 * 8;
        cp16(qsb + arr * (128 * 128) + aswz(row, q8), src);
    }
    cp_commit();

    auto load_kv = [&](int stg, int kt) {
        const uint32_t base = sb + stg * ATT_STAGE_B;
        #pragma unroll
        for (int i = 0; i < 6; i++) {
            const int c = i * 256 + tid;
            const int arr = c >> 9, row = (c >> 3) & 63, q8 = c & 7;
            const __half* g = (arr == 0) ? Kh : (arr == 1) ? Kl : Vh;
            cp16(base + arr * ATT_ARR_B + aswz(row, q8),
                 g + (size_t)(kt * 64 + row) * HD_ + q8 * 8);
        }
        cp_commit();
    };
    load_kv(0, 0);
    load_kv(1, 1);

    // ---- Q fragments to registers ----
    cp_wait<2>();
    __syncthreads();
    uint32_t qfh[4][4], qfl[4][4];
    {
        const int rowQ = wid * 16 + (lane & 7) + ((lane >> 3) & 1) * 8;
        const int chQ  = (lane >> 4) & 1;
        #pragma unroll
        for (int kc = 0; kc < 4; kc++) {
            const uint32_t off = aswz(rowQ, chQ + kc * 2);
            ldm_x4(qfh[kc], qsb + off);
            ldm_x4(qfl[kc], qsb + 128 * 128 + off);
        }
    }
    __syncthreads();
    load_kv(2, (2 < KT) ? 2 : KT - 1);
    load_kv(3, (3 < KT) ? 3 : KT - 1);
    cp_wait<3>();
    __syncthreads();

    float o[8][4];
    #pragma unroll
    for (int nt = 0; nt < 8; nt++)
        #pragma unroll
        for (int r = 0; r < 4; r++) o[nt][r] = 0.f;
    float m0 = -1e30f, m1 = -1e30f, l0 = 0.f, l1 = 0.f;

    const int r0g = qb * 128 + wid * 16 + (lane >> 2);

    const int rKbase = ((lane >> 4) & 1) * 8 + (lane & 7);
    const int chK    = (lane >> 3) & 1;
    const int rVbase = (lane & 7) + ((lane >> 3) & 1) * 8;
    const int chV    = (lane >> 4) & 1;

    const uint32_t ONES2[2] = {0x3C003C00u, 0x3C003C00u};

    #pragma unroll 1
    for (int kt = 0; kt < KT; kt++) {
        const uint32_t st  = sb + (kt % ATT_NSTG) * ATT_STAGE_B;
        const uint32_t stK = st;
        const uint32_t stV = st + 2 * ATT_ARR_B;

        // ---- S = Q K^T (f16x3) ----
        float s[8][4];
        #pragma unroll
        for (int nt = 0; nt < 8; nt++)
            #pragma unroll
            for (int r = 0; r < 4; r++) s[nt][r] = 0.f;

        #pragma unroll
        for (int kc = 0; kc < 4; kc++) {
            #pragma unroll
            for (int g = 0; g < 2; g++) {
                uint32_t kh4[2][4], kl4[2][4];
                #pragma unroll
                for (int t = 0; t < 2; t++) {
                    const int nt16 = g * 2 + t;
                    const uint32_t ad = aswz(rKbase + nt16 * 16, chK + kc * 2);
                    ldm_x4(kh4[t], stK + ad);
                    ldm_x4(kl4[t], stK + ATT_ARR_B + ad);
                }
                #pragma unroll
                for (int t = 0; t < 2; t++)
                    #pragma unroll
                    for (int hf = 0; hf < 2; hf++)
                        mma_f16(s[(g * 2 + t) * 2 + hf], qfh[kc], &kh4[t][hf * 2]);
                #pragma unroll
                for (int t = 0; t < 2; t++)
                    #pragma unroll
                    for (int hf = 0; hf < 2; hf++)
                        mma_f16(s[(g * 2 + t) * 2 + hf], qfl[kc], &kh4[t][hf * 2]);
                #pragma unroll
                for (int t = 0; t < 2; t++)
                    #pragma unroll
                    for (int hf = 0; hf < 2; hf++)
                        mma_f16(s[(g * 2 + t) * 2 + hf], qfh[kc], &kl4[t][hf * 2]);
            }
        }

        // ---- causal mask (last two tiles only) ----
        if (kt >= KT - 2) {
            const int colBase = kt * 64 + (lane & 3) * 2;
            #pragma unroll
            for (int nt = 0; nt < 8; nt++)
                #pragma unroll
                for (int j = 0; j < 2; j++) {
                    const int c = colBase + nt * 8 + j;
                    if (c > r0g)     s[nt][j]     = -30000.f;
                    if (c > r0g + 8) s[nt][2 + j] = -30000.f;
                }
        }

        // ---- max-reduce + o rescale ----
        float tm0 = -1e30f, tm1 = -1e30f;
        #pragma unroll
        for (int nt = 0; nt < 8; nt++) {
            tm0 = fmaxf(tm0, fmaxf(s[nt][0], s[nt][1]));
            tm1 = fmaxf(tm1, fmaxf(s[nt][2], s[nt][3]));
        }
        tm0 = fmaxf(tm0, __shfl_xor_sync(0xffffffffu, tm0, 1));
        tm0 = fmaxf(tm0, __shfl_xor_sync(0xffffffffu, tm0, 2));
        tm1 = fmaxf(tm1, __shfl_xor_sync(0xffffffffu, tm1, 1));
        tm1 = fmaxf(tm1, __shfl_xor_sync(0xffffffffu, tm1, 2));

        const float mn0 = fmaxf(m0, tm0), mn1 = fmaxf(m1, tm1);
        const float c0 = ex2f(m0 - mn0), c1 = ex2f(m1 - mn1);
        m0 = mn0; m1 = mn1;

        #pragma unroll
        for (int nt = 0; nt < 8; nt++) {
            o[nt][0] *= c0; o[nt][1] *= c0;
            o[nt][2] *= c1; o[nt][3] *= c1;
        }

        // ---- P = ex2(S-m) f16; row sums via MMA; O += P Vh ----
        float dsum[4] = {0.f, 0.f, 0.f, 0.f};
        #pragma unroll
        for (int kc = 0; kc < 4; kc++) {
            const float* s0 = s[2 * kc];
            const float* s1 = s[2 * kc + 1];
            uint32_t ph[4];
            ph[0] = ex2h2(packh2(s0[0] - mn0, s0[1] - mn0));
            ph[1] = ex2h2(packh2(s0[2] - mn1, s0[3] - mn1));
            ph[2] = ex2h2(packh2(s1[0] - mn0, s1[1] - mn0));
            ph[3] = ex2h2(packh2(s1[2] - mn1, s1[3] - mn1));

            mma_f16(dsum, ph, ONES2);

            const int rowV = rVbase + kc * 16;
            #pragma unroll
            for (int nt16 = 0; nt16 < 4; nt16++) {
                uint32_t vh4[4];
                ldm_x4_t(vh4, stV + aswz(rowV, chV + nt16 * 2));
                #pragma unroll
                for (int hf = 0; hf < 2; hf++)
                    mma_f16(o[nt16 * 2 + hf], ph, &vh4[hf * 2]);
            }
        }
        l0 = l0 * c0 + dsum[0];
        l1 = l1 * c1 + dsum[2];

        // ---- advance pipeline ----
        __syncthreads();
        if (kt + 4 < KT) {
            load_kv(kt % ATT_NSTG, kt + 4);
            cp_wait<3>();
            __syncthreads();
        } else if (kt + 3 < KT) {
            cp_wait<2>();
            __syncthreads();
        } else if (kt + 2 < KT) {
            cp_wait<1>();
            __syncthreads();
        } else if (kt + 1 < KT) {
            cp_wait<0>();
            __syncthreads();
        }
    }

    // ---- finalize: single f16 plane out ----
    const float inv0 = 1.f / l0, inv1 = 1.f / l1;

    const size_t row0 = (size_t)b * T_ + qb * 128 + wid * 16 + (lane >> 2);
    const size_t row1 = row0 + 8;
    const int colB = h * HD_ + (lane & 3) * 2;

    #pragma unroll
    for (int nt = 0; nt < 8; nt++) {
        const size_t i0 = row0 * D_ + colB + nt * 8;
        const size_t i1 = row1 * D_ + colB + nt * 8;
        reinterpret_cast<uint32_t*>(g_o16)[i0 >> 1] =
            packh2(o[nt][0] * inv0, o[nt][1] * inv0);
        reinterpret_cast<uint32_t*>(g_o16)[i1 >> 1] =
            packh2(o[nt][2] * inv1, o[nt][3] * inv1);
    }
}

// ---------------------------------------------------------------------------
// Conversion kernels
// ---------------------------------------------------------------------------
__global__ __launch_bounds__(256) void quant_x_kernel(const float* __restrict__ src)
{
    const int i = blockIdx.x * 256 + threadIdx.x;
    g_x16[i] = __float2half_rn(src[i]);
}

__global__ __launch_bounds__(256) void wsplit_kernel(
    const float* __restrict__ wq, const float* __restrict__ wk,
    const float* __restrict__ wv, const float* __restrict__ wo)
{
    __shared__ float tile[32][33];
    const int z = blockIdx.z;
    const float* w = (z == 0) ? wq : (z == 1) ? wk : (z == 2) ? wv : wo;
    const int nB = blockIdx.x * 32, kB = blockIdx.y * 32;
    const int tx = threadIdx.x & 31, ty = threadIdx.x >> 5;

    #pragma unroll
    for (int r = ty; r < 32; r += 8)
        tile[r][tx] = w[(size_t)(kB + r) * D_ + nB + tx];
    __syncthreads();
    #pragma unroll
    for (int r = ty; r < 32; r += 8) {
        const float v = tile[tx][r];
        const size_t di = ((size_t)z << 20) + (size_t)(nB + r) * D_ + kB + tx;
        const __half hv = __float2half_rn(v);
        g_wth[di] = hv;
        g_wtl[di] = __float2half_rn(v - __half2float(hv));
    }
}

// ---------------------------------------------------------------------------
extern "C" void kernel_launch(void* const* d_in, const int* in_sizes, int n_in,
                              void* d_out, int out_size)
{
    const float* x  = (const float*)d_in[0];
    const float* wq = (const float*)d_in[1];
    const float* bq = (const float*)d_in[2];
    const float* wk = (const float*)d_in[3];
    const float* bk = (const float*)d_in[4];
    const float* wv = (const float*)d_in[5];
    const float* bv = (const float*)d_in[6];
    const float* wo = (const float*)d_in[7];
    const float* bo = (const float*)d_in[8];
    float* out = (float*)d_out;

    static bool attrSet = false;
    if (!attrSet) {
        cudaFuncSetAttribute(gemm_mma<0>,
                             cudaFuncAttributeMaxDynamicSharedMemorySize, GEMM_SMEM);
        cudaFuncSetAttribute(gemm_mma<1>,
                             cudaFuncAttributeMaxDynamicSharedMemorySize, GEMM_SMEM);
        cudaFuncSetAttribute(attn_mma,
                             cudaFuncAttributeMaxDynamicSharedMemorySize, ATT_SMEM);
        attrSet = true;
    }

    void *px16, *po16;
    cudaGetSymbolAddress(&px16, g_x16);
    cudaGetSymbolAddress(&po16, g_o16);

    const int nElem = M_ * D_;

    // 1) convert inputs
    quant_x_kernel<<<nElem / 256, 256>>>(x);
    wsplit_kernel<<<dim3(32, 32, 4), 256>>>(wq, wk, wv, wo);

    // 2) QKV projections (2-term) -> q/k f16 hi/lo, v f16; Q pre-scaled
    gemm_mma<0><<<dim3(8, 64, 3), 256, GEMM_SMEM>>>(
        (const __half*)px16, bq, bk, bv, nullptr, 0);

    // 3) tensor-core causal flash attention -> g_o16 [B*T, D]
    attn_mma<<<dim3(T_ / 128, H_, B_), 256, ATT_SMEM>>>();

    // 4) output projection (2-term)
    gemm_mma<1><<<dim3(8, 64, 1), 256, GEMM_SMEM>>>(
        (const __half*)po16, bo, bo, bo, out, 3);
}

// round 10
// speedup vs baseline: 7.5997x; 1.1002x over previous
#include <cuda_runtime.h>
#include <cuda_fp16.h>
#include <cstdint>
#include <cstddef>

// ---------------------------------------------------------------------------
// Problem constants
// ---------------------------------------------------------------------------
constexpr int B_  = 4;
constexpr int T_  = 2048;
constexpr int D_  = 1024;
constexpr int H_  = 16;
constexpr int HD_ = 64;
constexpr int M_  = B_ * T_;   // 8192

// 0.125 * log2(e): folded into Q so softmax uses exp2
constexpr float QSCALE = 0.18033688011112042f;

// ---------------------------------------------------------------------------
// Device scratch
// ---------------------------------------------------------------------------
__device__ __align__(128) __half g_x16[(size_t)M_ * D_];   // x quantized f16
__device__ __align__(128) __half g_o16[(size_t)M_ * D_];   // attnO f16 [B*T, D]
// QKV in [B, H, T, HD]; q keeps hi/lo, k and v are single-plane f16
__device__ __align__(128) __half g_qh[(size_t)M_ * D_];
__device__ __align__(128) __half g_ql[(size_t)M_ * D_];
__device__ __align__(128) __half g_kh[(size_t)M_ * D_];
__device__ __align__(128) __half g_vh[(size_t)M_ * D_];
// 4 weights transposed to [N, K] f16 hi/lo, z: 0..3 -> wq,wk,wv,wo
__device__ __align__(128) __half g_wth[(size_t)4 * D_ * D_];
__device__ __align__(128) __half g_wtl[(size_t)4 * D_ * D_];

// ---------------------------------------------------------------------------
// PTX helpers
// ---------------------------------------------------------------------------
__device__ __forceinline__ uint32_t smem_u32(const void* p) {
    uint32_t a;
    asm("{ .reg .u64 t; cvta.to.shared.u64 t, %1; cvt.u32.u64 %0, t; }"
        : "=r"(a) : "l"(p));
    return a;
}
__device__ __forceinline__ void cp16(uint32_t saddr, const void* gaddr) {
    asm volatile("cp.async.cg.shared.global [%0], [%1], 16;"
                 :: "r"(saddr), "l"(gaddr));
}
__device__ __forceinline__ void cp_commit() {
    asm volatile("cp.async.commit_group;");
}
template <int N>
__device__ __forceinline__ void cp_wait() {
    asm volatile("cp.async.wait_group %0;" :: "n"(N));
}
__device__ __forceinline__ void ldm_x4(uint32_t* r, uint32_t addr) {
    asm volatile("ldmatrix.sync.aligned.m8n8.x4.shared.b16 {%0,%1,%2,%3}, [%4];"
                 : "=r"(r[0]), "=r"(r[1]), "=r"(r[2]), "=r"(r[3]) : "r"(addr));
}
__device__ __forceinline__ void ldm_x4_t(uint32_t* r, uint32_t addr) {
    asm volatile("ldmatrix.sync.aligned.m8n8.x4.trans.shared.b16 {%0,%1,%2,%3}, [%4];"
                 : "=r"(r[0]), "=r"(r[1]), "=r"(r[2]), "=r"(r[3]) : "r"(addr));
}
__device__ __forceinline__ void mma_f16(float* c, const uint32_t* a,
                                        const uint32_t* b) {
    asm volatile(
        "mma.sync.aligned.m16n8k16.row.col.f32.f16.f16.f32 "
        "{%0,%1,%2,%3}, {%4,%5,%6,%7}, {%8,%9}, {%0,%1,%2,%3};"
        : "+f"(c[0]), "+f"(c[1]), "+f"(c[2]), "+f"(c[3])
        : "r"(a[0]), "r"(a[1]), "r"(a[2]), "r"(a[3]), "r"(b[0]), "r"(b[1]));
}
__device__ __forceinline__ float ex2f(float x) {
    float r;
    asm("ex2.approx.ftz.f32 %0, %1;" : "=f"(r) : "f"(x));
    return r;
}
// packed f16x2: {low=lo, high=hi}
__device__ __forceinline__ uint32_t packh2(float lo, float hi) {
    uint32_t r;
    asm("cvt.rn.f16x2.f32 %0, %1, %2;" : "=r"(r) : "f"(hi), "f"(lo));
    return r;
}
__device__ __forceinline__ uint32_t ex2h2(uint32_t x) {
    uint32_t r;
    asm("ex2.approx.f16x2 %0, %1;" : "=r"(r) : "r"(x));
    return r;
}
// split v0,v1 into f16 hi pair + f16 lo (residual) pair
__device__ __forceinline__ void split_pack_f16(float v0, float v1,
                                               uint32_t& hi, uint32_t& lo) {
    hi = packh2(v0, v1);
    const float h0 = __half2float(__ushort_as_half((unsigned short)(hi & 0xFFFF)));
    const float h1 = __half2float(__ushort_as_half((unsigned short)(hi >> 16)));
    lo = packh2(v0 - h0, v1 - h1);
}

// ---------------------------------------------------------------------------
// HMMA GEMM, 2-term: C = A16 @ (Wh + Wl)^T + bias, fp32 accum.
// 8 warps (4Mx2N), warp 32x64, BK=32, 4-stage cp.async ring with single
// __syncthreads per iteration (prefetch distance 3), 2 CTAs/SM.
// MODE 0: dst = q f16 hi/lo, k f16, v f16 [B,H,T,HD]; Q pre-scaled.
// MODE 1: dst = out fp32 [M, D].
// ---------------------------------------------------------------------------
constexpr int BK        = 32;
constexpr int G_ARR_B   = 128 * 64;                   // 8192 B per tile array
constexpr int G_STAGE_B = 3 * G_ARR_B;                // 24576 (A, Bh, Bl)
constexpr int G_NSTG    = 4;
constexpr int GEMM_SMEM = G_NSTG * G_STAGE_B;         // 98304 -> 2 CTAs/SM
constexpr int KT_G      = D_ / BK;                    // 32

__device__ __forceinline__ uint32_t gswz(int row, int chunk) {
    return (uint32_t)row * 64u + (uint32_t)((chunk ^ ((row >> 1) & 3)) << 4);
}

template <int MODE>
__global__ __launch_bounds__(256, 2)
void gemm_mma(const __half* __restrict__ A,
              const float* __restrict__ b0, const float* __restrict__ b1,
              const float* __restrict__ b2,
              float* __restrict__ out, int zbase)
{
    extern __shared__ __align__(128) char smem[];
    const uint32_t sb = smem_u32(smem);

    const int tid  = threadIdx.x;
    const int wid  = tid >> 5;
    const int lane = tid & 31;
    const int wm   = (wid & 3) * 32;
    const int wn   = (wid >> 2) * 64;

    const int mBase = blockIdx.y * 128;
    const int nBase = blockIdx.x * 128;
    const int z     = zbase + blockIdx.z;

    const __half* Bh = g_wth + ((size_t)z << 20);
    const __half* Bl = g_wtl + ((size_t)z << 20);

    const int c0r = tid >> 2,         c0q = tid & 3;
    const int c1r = (tid + 256) >> 2, c1q = (tid + 256) & 3;
    const uint32_t s0 = gswz(c0r, c0q), s1 = gswz(c1r, c1q);

    auto load_stage = [&](int stg, int kt) {
        const uint32_t st = sb + stg * G_STAGE_B;
        const int bk = kt * BK;
        {
            const size_t ga = (size_t)(mBase + c0r) * D_ + bk + c0q * 8;
            const size_t gb = (size_t)(mBase + c1r) * D_ + bk + c1q * 8;
            cp16(st + s0, A + ga);
            cp16(st + s1, A + gb);
        }
        {
            const size_t ga = (size_t)(nBase + c0r) * D_ + bk + c0q * 8;
            const size_t gb = (size_t)(nBase + c1r) * D_ + bk + c1q * 8;
            cp16(st + G_ARR_B + s0,     Bh + ga);
            cp16(st + G_ARR_B + s1,     Bh + gb);
            cp16(st + 2 * G_ARR_B + s0, Bl + ga);
            cp16(st + 2 * G_ARR_B + s1, Bl + gb);
        }
        cp_commit();
    };

    float acc[2][8][4];
    #pragma unroll
    for (int mi = 0; mi < 2; mi++)
        #pragma unroll
        for (int ni = 0; ni < 8; ni++)
            #pragma unroll
            for (int r = 0; r < 4; r++) acc[mi][ni][r] = 0.f;

    load_stage(0, 0);
    load_stage(1, 1);
    load_stage(2, 2);

    int rowA[2], rowB[4];
    #pragma unroll
    for (int mi = 0; mi < 2; mi++)
        rowA[mi] = wm + (lane & 7) + ((lane >> 3) & 1) * 8 + mi * 16;
    #pragma unroll
    for (int p = 0; p < 4; p++)
        rowB[p] = wn + ((lane >> 4) & 1) * 8 + (lane & 7) + p * 16;
    const int chA = (lane >> 4) & 1;
    const int chB = (lane >> 3) & 1;

    #pragma unroll 1
    for (int kt = 0; kt < KT_G; kt++) {
        cp_wait<2>();            // stage kt ready
        __syncthreads();         // also: all warps done with stage kt-1

        // refill slot (kt+3)%4 == (kt-1)%4 (just retired). Empty commit at
        // tail keeps group accounting uniform.
        if (kt + 3 < KT_G) load_stage((kt + 3) % G_NSTG, kt + 3);
        else               cp_commit();

        const uint32_t st  = sb + (kt % G_NSTG) * G_STAGE_B;
        const uint32_t sA  = st;
        const uint32_t sBh = st + G_ARR_B;
        const uint32_t sBl = st + 2 * G_ARR_B;

        #pragma unroll
        for (int ks = 0; ks < 2; ks++) {
            uint32_t af[2][4];
            #pragma unroll
            for (int mi = 0; mi < 2; mi++)
                ldm_x4(af[mi], sA + gswz(rowA[mi], chA + ks * 2));
            uint32_t bh4[4][4], bl4[4][4];
            #pragma unroll
            for (int p = 0; p < 4; p++) {
                const uint32_t off = gswz(rowB[p], chB + ks * 2);
                ldm_x4(bh4[p], sBh + off);
                ldm_x4(bl4[p], sBl + off);
            }
            #pragma unroll
            for (int mi = 0; mi < 2; mi++)
                #pragma unroll
                for (int p = 0; p < 4; p++)
                    #pragma unroll
                    for (int hf = 0; hf < 2; hf++)
                        mma_f16(acc[mi][p * 2 + hf], af[mi], &bh4[p][hf * 2]);
            #pragma unroll
            for (int mi = 0; mi < 2; mi++)
                #pragma unroll
                for (int p = 0; p < 4; p++)
                    #pragma unroll
                    for (int hf = 0; hf < 2; hf++)
                        mma_f16(acc[mi][p * 2 + hf], af[mi], &bl4[p][hf * 2]);
        }
    }

    // --- epilogue ---
    const float* bias = (MODE == 0)
        ? (blockIdx.z == 0 ? b0 : blockIdx.z == 1 ? b1 : b2) : b0;

    __half *dh = nullptr, *dl = nullptr;
    float scale = 1.f;
    if (MODE == 0) {
        if (blockIdx.z == 0)      { dh = g_qh; dl = g_ql; scale = QSCALE; }
        else if (blockIdx.z == 1) { dh = g_kh; dl = nullptr; }
        else                      { dh = g_vh; dl = nullptr; }
    }

    #pragma unroll
    for (int mi = 0; mi < 2; mi++) {
        #pragma unroll
        for (int ni = 0; ni < 8; ni++) {
            const int n0 = nBase + wn + ni * 8 + (lane & 3) * 2;
            const float bv0 = __ldg(bias + n0), bv1 = __ldg(bias + n0 + 1);
            #pragma unroll
            for (int rr = 0; rr < 2; rr++) {
                const int m = mBase + wm + mi * 16 + (lane >> 2) + rr * 8;
                float v0 = acc[mi][ni][rr * 2 + 0] + bv0;
                float v1 = acc[mi][ni][rr * 2 + 1] + bv1;
                if (MODE == 0) {
                    v0 *= scale; v1 *= scale;
                    const int bb = m >> 11, tt = m & 2047;
                    const int hh = n0 >> 6, hd = n0 & 63;
                    const size_t idx =
                        ((((size_t)bb * H_ + hh) * T_ + tt) << 6) + hd;
                    if (dl) {
                        uint32_t hp, lp;
                        split_pack_f16(v0, v1, hp, lp);
                        reinterpret_cast<uint32_t*>(dh)[idx >> 1] = hp;
                        reinterpret_cast<uint32_t*>(dl)[idx >> 1] = lp;
                    } else {
                        reinterpret_cast<uint32_t*>(dh)[idx >> 1] = packh2(v0, v1);
                    }
                } else {
                    *reinterpret_cast<float2*>(out + (size_t)m * D_ + n0) =
                        make_float2(v0, v1);
                }
            }
        }
    }
}

// ---------------------------------------------------------------------------
// Tensor-core causal flash attention.
// S = (qh + ql) . kh  (2-term; q.kl dropped, ~2.4e-4 on P);
// P native f16 via ex2.approx.f16x2; PV = P.Vh; row sums via sum-MMA.
// 6-stage KV ring (kh,vh = 16KB/stage), single sync per iter, 2 CTAs/SM.
// ---------------------------------------------------------------------------
constexpr int ATT_ARR_B   = 64 * 128;                 // 8192 per array
constexpr int ATT_STAGE_B = 2 * ATT_ARR_B;            // 16384 (kh, vh)
constexpr int ATT_NSTG    = 6;
constexpr int ATT_SMEM    = ATT_NSTG * ATT_STAGE_B;   // 98304 -> 2 CTAs/SM

__device__ __forceinline__ uint32_t aswz(int row, int chunk) {
    return (uint32_t)row * 128u + (uint32_t)((chunk ^ (row & 7)) << 4);
}

__global__ __launch_bounds__(256, 2)
void attn_mma()
{
    extern __shared__ __align__(128) char smem[];
    const uint32_t sb = smem_u32(smem);

    const int tid  = threadIdx.x;
    const int wid  = tid >> 5;
    const int lane = tid & 31;

    const int qb = (gridDim.x - 1) - blockIdx.x;     // largest-first
    const int h  = blockIdx.y, b = blockIdx.z;
    const size_t bh = ((size_t)(b * H_ + h)) * T_ * HD_;

    const __half* Qh = g_qh + bh + (size_t)qb * 128 * HD_;
    const __half* Ql = g_ql + bh + (size_t)qb * 128 * HD_;
    const __half* Kh = g_kh + bh;
    const __half* Vh = g_vh + bh;

    const int KT = 2 * qb + 2;   // >= 2

    // ---- Q via ring stages 0-1 (transient), then extract fragments ----
    #pragma unroll
    for (int i = 0; i < 8; i++) {
        const int c = i * 256 + tid;
        const int arr = c >> 10, row = (c >> 3) & 127, q8 = c & 7;
        const __half* src = (arr ? Ql : Qh) + (size_t)row * HD_ + q8 * 8;
        cp16(sb + arr * ATT_STAGE_B + aswz(row, q8), src);
    }
    cp_commit();
    cp_wait<0>();
    __syncthreads();

    uint32_t qfh[4][4], qfl[4][4];
    {
        const int rowQ = wid * 16 + (lane & 7) + ((lane >> 3) & 1) * 8;
        const int chQ  = (lane >> 4) & 1;
        #pragma unroll
        for (int kc = 0; kc < 4; kc++) {
            const uint32_t off = aswz(rowQ, chQ + kc * 2);
            ldm_x4(qfh[kc], sb + off);
            ldm_x4(qfl[kc], sb + ATT_STAGE_B + off);
        }
    }
    __syncthreads();             // all warps done reading Q smem

    auto load_kv = [&](int stg, int kt) {
        const uint32_t base = sb + stg * ATT_STAGE_B;
        #pragma unroll
        for (int i = 0; i < 4; i++) {                // 2 arrays * 512 chunks
            const int c = i * 256 + tid;
            const int arr = c >> 9, row = (c >> 3) & 63, q8 = c & 7;
            const __half* g = arr ? Vh : Kh;
            cp16(base + arr * ATT_ARR_B + aswz(row, q8),
                 g + (size_t)(kt * 64 + row) * HD_ + q8 * 8);
        }
        cp_commit();
    };
    // prologue: fill stages 0..4 (empty commits past KT)
    #pragma unroll
    for (int j = 0; j < 5; j++) {
        if (j < KT) load_kv(j, j);
        else        cp_commit();
    }

    float o[8][4];
    #pragma unroll
    for (int nt = 0; nt < 8; nt++)
        #pragma unroll
        for (int r = 0; r < 4; r++) o[nt][r] = 0.f;
    float m0 = -1e30f, m1 = -1e30f, l0 = 0.f, l1 = 0.f;

    const int r0g = qb * 128 + wid * 16 + (lane >> 2);

    const int rKbase = ((lane >> 4) & 1) * 8 + (lane & 7);
    const int chK    = (lane >> 3) & 1;
    const int rVbase = (lane & 7) + ((lane >> 3) & 1) * 8;
    const int chV    = (lane >> 4) & 1;

    const uint32_t ONES2[2] = {0x3C003C00u, 0x3C003C00u};

    #pragma unroll 1
    for (int kt = 0; kt < KT; kt++) {
        cp_wait<4>();            // stage kt ready
        __syncthreads();         // all warps done with stage kt-1

        if (kt + 5 < KT) load_kv((kt + 5) % ATT_NSTG, kt + 5);
        else             cp_commit();

        const uint32_t st  = sb + (kt % ATT_NSTG) * ATT_STAGE_B;
        const uint32_t stK = st;
        const uint32_t stV = st + ATT_ARR_B;

        // ---- S = (qh + ql) . kh ----
        float s[8][4];
        #pragma unroll
        for (int nt = 0; nt < 8; nt++)
            #pragma unroll
            for (int r = 0; r < 4; r++) s[nt][r] = 0.f;

        #pragma unroll
        for (int kc = 0; kc < 4; kc++) {
            #pragma unroll
            for (int g = 0; g < 2; g++) {
                uint32_t kh4[2][4];
                #pragma unroll
                for (int t = 0; t < 2; t++) {
                    const int nt16 = g * 2 + t;
                    ldm_x4(kh4[t], stK + aswz(rKbase + nt16 * 16, chK + kc * 2));
                }
                #pragma unroll
                for (int t = 0; t < 2; t++)
                    #pragma unroll
                    for (int hf = 0; hf < 2; hf++)
                        mma_f16(s[(g * 2 + t) * 2 + hf], qfh[kc], &kh4[t][hf * 2]);
                #pragma unroll
                for (int t = 0; t < 2; t++)
                    #pragma unroll
                    for (int hf = 0; hf < 2; hf++)
                        mma_f16(s[(g * 2 + t) * 2 + hf], qfl[kc], &kh4[t][hf * 2]);
            }
        }

        // ---- causal mask (last two tiles only) ----
        if (kt >= KT - 2) {
            const int colBase = kt * 64 + (lane & 3) * 2;
            #pragma unroll
            for (int nt = 0; nt < 8; nt++)
                #pragma unroll
                for (int j = 0; j < 2; j++) {
                    const int c = colBase + nt * 8 + j;
                    if (c > r0g)     s[nt][j]     = -30000.f;
                    if (c > r0g + 8) s[nt][2 + j] = -30000.f;
                }
        }

        // ---- max-reduce + o rescale ----
        float tm0 = -1e30f, tm1 = -1e30f;
        #pragma unroll
        for (int nt = 0; nt < 8; nt++) {
            tm0 = fmaxf(tm0, fmaxf(s[nt][0], s[nt][1]));
            tm1 = fmaxf(tm1, fmaxf(s[nt][2], s[nt][3]));
        }
        tm0 = fmaxf(tm0, __shfl_xor_sync(0xffffffffu, tm0, 1));
        tm0 = fmaxf(tm0, __shfl_xor_sync(0xffffffffu, tm0, 2));
        tm1 = fmaxf(tm1, __shfl_xor_sync(0xffffffffu, tm1, 1));
        tm1 = fmaxf(tm1, __shfl_xor_sync(0xffffffffu, tm1, 2));

        const float mn0 = fmaxf(m0, tm0), mn1 = fmaxf(m1, tm1);
        const float c0 = ex2f(m0 - mn0), c1 = ex2f(m1 - mn1);
        m0 = mn0; m1 = mn1;

        #pragma unroll
        for (int nt = 0; nt < 8; nt++) {
            o[nt][0] *= c0; o[nt][1] *= c0;
            o[nt][2] *= c1; o[nt][3] *= c1;
        }

        // ---- P = ex2(S-m) f16; row sums via MMA; O += P Vh ----
        float dsum[4] = {0.f, 0.f, 0.f, 0.f};
        #pragma unroll
        for (int kc = 0; kc < 4; kc++) {
            const float* s0 = s[2 * kc];
            const float* s1 = s[2 * kc + 1];
            uint32_t ph[4];
            ph[0] = ex2h2(packh2(s0[0] - mn0, s0[1] - mn0));
            ph[1] = ex2h2(packh2(s0[2] - mn1, s0[3] - mn1));
            ph[2] = ex2h2(packh2(s1[0] - mn0, s1[1] - mn0));
            ph[3] = ex2h2(packh2(s1[2] - mn1, s1[3] - mn1));

            mma_f16(dsum, ph, ONES2);

            const int rowV = rVbase + kc * 16;
            #pragma unroll
            for (int nt16 = 0; nt16 < 4; nt16++) {
                uint32_t vh4[4];
                ldm_x4_t(vh4, stV + aswz(rowV, chV + nt16 * 2));
                #pragma unroll
                for (int hf = 0; hf < 2; hf++)
                    mma_f16(o[nt16 * 2 + hf], ph, &vh4[hf * 2]);
            }
        }
        l0 = l0 * c0 + dsum[0];
        l1 = l1 * c1 + dsum[2];
    }

    // ---- finalize: single f16 plane out ----
    const float inv0 = 1.f / l0, inv1 = 1.f / l1;

    const size_t row0 = (size_t)b * T_ + qb * 128 + wid * 16 + (lane >> 2);
    const size_t row1 = row0 + 8;
    const int colB = h * HD_ + (lane & 3) * 2;

    #pragma unroll
    for (int nt = 0; nt < 8; nt++) {
        const size_t i0 = row0 * D_ + colB + nt * 8;
        const size_t i1 = row1 * D_ + colB + nt * 8;
        reinterpret_cast<uint32_t*>(g_o16)[i0 >> 1] =
            packh2(o[nt][0] * inv0, o[nt][1] * inv0);
        reinterpret_cast<uint32_t*>(g_o16)[i1 >> 1] =
            packh2(o[nt][2] * inv1, o[nt][3] * inv1);
    }
}

// ---------------------------------------------------------------------------
// Conversion kernels
// ---------------------------------------------------------------------------
__global__ __launch_bounds__(256) void quant_x_kernel(const float* __restrict__ src)
{
    const int i = blockIdx.x * 256 + threadIdx.x;
    g_x16[i] = __float2half_rn(src[i]);
}

__global__ __launch_bounds__(256) void wsplit_kernel(
    const float* __restrict__ wq, const float* __restrict__ wk,
    const float* __restrict__ wv, const float* __restrict__ wo)
{
    __shared__ float tile[32][33];
    const int z = blockIdx.z;
    const float* w = (z == 0) ? wq : (z == 1) ? wk : (z == 2) ? wv : wo;
    const int nB = blockIdx.x * 32, kB = blockIdx.y * 32;
    const int tx = threadIdx.x & 31, ty = threadIdx.x >> 5;

    #pragma unroll
    for (int r = ty; r < 32; r += 8)
        tile[r][tx] = w[(size_t)(kB + r) * D_ + nB + tx];
    __syncthreads();
    #pragma unroll
    for (int r = ty; r < 32; r += 8) {
        const float v = tile[tx][r];
        const size_t di = ((size_t)z << 20) + (size_t)(nB + r) * D_ + kB + tx;
        const __half hv = __float2half_rn(v);
        g_wth[di] = hv;
        g_wtl[di] = __float2half_rn(v - __half2float(hv));
    }
}

// ---------------------------------------------------------------------------
extern "C" void kernel_launch(void* const* d_in, const int* in_sizes, int n_in,
                              void* d_out, int out_size)
{
    const float* x  = (const float*)d_in[0];
    const float* wq = (const float*)d_in[1];
    const float* bq = (const float*)d_in[2];
    const float* wk = (const float*)d_in[3];
    const float* bk = (const float*)d_in[4];
    const float* wv = (const float*)d_in[5];
    const float* bv = (const float*)d_in[6];
    const float* wo = (const float*)d_in[7];
    const float* bo = (const float*)d_in[8];
    float* out = (float*)d_out;

    static bool attrSet = false;
    if (!attrSet) {
        cudaFuncSetAttribute(gemm_mma<0>,
                             cudaFuncAttributeMaxDynamicSharedMemorySize, GEMM_SMEM);
        cudaFuncSetAttribute(gemm_mma<1>,
                             cudaFuncAttributeMaxDynamicSharedMemorySize, GEMM_SMEM);
        cudaFuncSetAttribute(attn_mma,
                             cudaFuncAttributeMaxDynamicSharedMemorySize, ATT_SMEM);
        attrSet = true;
    }

    void *px16, *po16;
    cudaGetSymbolAddress(&px16, g_x16);
    cudaGetSymbolAddress(&po16, g_o16);

    const int nElem = M_ * D_;

    // 1) convert inputs
    quant_x_kernel<<<nElem / 256, 256>>>(x);
    wsplit_kernel<<<dim3(32, 32, 4), 256>>>(wq, wk, wv, wo);

    // 2) QKV projections (2-term) -> q f16 hi/lo, k/v f16; Q pre-scaled
    gemm_mma<0><<<dim3(8, 64, 3), 256, GEMM_SMEM>>>(
        (const __half*)px16, bq, bk, bv, nullptr, 0);

    // 3) tensor-core causal flash attention -> g_o16 [B*T, D]
    attn_mma<<<dim3(T_ / 128, H_, B_), 256, ATT_SMEM>>>();

    // 4) output projection (2-term)
    gemm_mma<1><<<dim3(8, 64, 1), 256, GEMM_SMEM>>>(
        (const __half*)po16, bo, bo, bo, out, 3);
}

// round 11
// speedup vs baseline: 11.2930x; 1.4860x over previous
#include <cuda_runtime.h>
#include <cuda_fp16.h>
#include <cstdint>
#include <cstddef>

// ---------------------------------------------------------------------------
// Problem constants
// ---------------------------------------------------------------------------
constexpr int B_  = 4;
constexpr int T_  = 2048;
constexpr int D_  = 1024;
constexpr int H_  = 16;
constexpr int HD_ = 64;
constexpr int M_  = B_ * T_;   // 8192

// 0.125 * log2(e): folded into Q so softmax uses exp2
constexpr float QSCALE = 0.18033688011112042f;

// ---------------------------------------------------------------------------
// Device scratch (pure f16 pipeline, fp32 accumulation in-kernel)
// ---------------------------------------------------------------------------
__device__ __align__(128) __half g_x16[(size_t)M_ * D_];   // x f16
__device__ __align__(128) __half g_o16[(size_t)M_ * D_];   // attnO f16 [B*T, D]
__device__ __align__(128) __half g_q16[(size_t)M_ * D_];   // [B,H,T,HD]
__device__ __align__(128) __half g_k16[(size_t)M_ * D_];
__device__ __align__(128) __half g_v16[(size_t)M_ * D_];
// 4 weights transposed to [N, K] f16, z: 0..3 -> wq,wk,wv,wo
__device__ __align__(128) __half g_wt[(size_t)4 * D_ * D_];

// ---------------------------------------------------------------------------
// PTX helpers
// ---------------------------------------------------------------------------
__device__ __forceinline__ uint32_t smem_u32(const void* p) {
    uint32_t a;
    asm("{ .reg .u64 t; cvta.to.shared.u64 t, %1; cvt.u32.u64 %0, t; }"
        : "=r"(a) : "l"(p));
    return a;
}
__device__ __forceinline__ void cp16(uint32_t saddr, const void* gaddr) {
    asm volatile("cp.async.cg.shared.global [%0], [%1], 16;"
                 :: "r"(saddr), "l"(gaddr));
}
__device__ __forceinline__ void cp_commit() {
    asm volatile("cp.async.commit_group;");
}
template <int N>
__device__ __forceinline__ void cp_wait() {
    asm volatile("cp.async.wait_group %0;" :: "n"(N));
}
__device__ __forceinline__ void ldm_x4(uint32_t* r, uint32_t addr) {
    asm volatile("ldmatrix.sync.aligned.m8n8.x4.shared.b16 {%0,%1,%2,%3}, [%4];"
                 : "=r"(r[0]), "=r"(r[1]), "=r"(r[2]), "=r"(r[3]) : "r"(addr));
}
__device__ __forceinline__ void ldm_x4_t(uint32_t* r, uint32_t addr) {
    asm volatile("ldmatrix.sync.aligned.m8n8.x4.trans.shared.b16 {%0,%1,%2,%3}, [%4];"
                 : "=r"(r[0]), "=r"(r[1]), "=r"(r[2]), "=r"(r[3]) : "r"(addr));
}
__device__ __forceinline__ void mma_f16(float* c, const uint32_t* a,
                                        const uint32_t* b) {
    asm volatile(
        "mma.sync.aligned.m16n8k16.row.col.f32.f16.f16.f32 "
        "{%0,%1,%2,%3}, {%4,%5,%6,%7}, {%8,%9}, {%0,%1,%2,%3};"
        : "+f"(c[0]), "+f"(c[1]), "+f"(c[2]), "+f"(c[3])
        : "r"(a[0]), "r"(a[1]), "r"(a[2]), "r"(a[3]), "r"(b[0]), "r"(b[1]));
}
__device__ __forceinline__ float ex2f(float x) {
    float r;
    asm("ex2.approx.ftz.f32 %0, %1;" : "=f"(r) : "f"(x));
    return r;
}
// packed f16x2: {low=lo, high=hi}
__device__ __forceinline__ uint32_t packh2(float lo, float hi) {
    uint32_t r;
    asm("cvt.rn.f16x2.f32 %0, %1, %2;" : "=r"(r) : "f"(hi), "f"(lo));
    return r;
}
__device__ __forceinline__ uint32_t ex2h2(uint32_t x) {
    uint32_t r;
    asm("ex2.approx.f16x2 %0, %1;" : "=r"(r) : "r"(x));
    return r;
}

// ---------------------------------------------------------------------------
// HMMA GEMM, 1-term f16: C = A16 @ W16^T + bias, fp32 accum.
// 8 warps (4Mx2N), warp 32x64, BK=32, 6-stage cp.async ring (16KB/stage),
// single __syncthreads per iteration, 2 CTAs/SM.
// MODE 0: dst = q/k/v f16 [B,H,T,HD]; Q pre-scaled.
// MODE 1: dst = out fp32 [M, D].
// ---------------------------------------------------------------------------
constexpr int BK        = 32;
constexpr int G_ARR_B   = 128 * 64;                   // 8192 B per tile array
constexpr int G_STAGE_B = 2 * G_ARR_B;                // 16384 (A, W)
constexpr int G_NSTG    = 6;
constexpr int GEMM_SMEM = G_NSTG * G_STAGE_B;         // 98304 -> 2 CTAs/SM
constexpr int KT_G      = D_ / BK;                    // 32

__device__ __forceinline__ uint32_t gswz(int row, int chunk) {
    return (uint32_t)row * 64u + (uint32_t)((chunk ^ ((row >> 1) & 3)) << 4);
}

template <int MODE>
__global__ __launch_bounds__(256, 2)
void gemm_mma(const __half* __restrict__ A,
              const float* __restrict__ b0, const float* __restrict__ b1,
              const float* __restrict__ b2,
              float* __restrict__ out, int zbase)
{
    extern __shared__ __align__(128) char smem[];
    const uint32_t sb = smem_u32(smem);

    const int tid  = threadIdx.x;
    const int wid  = tid >> 5;
    const int lane = tid & 31;
    const int wm   = (wid & 3) * 32;
    const int wn   = (wid >> 2) * 64;

    const int mBase = blockIdx.y * 128;
    const int nBase = blockIdx.x * 128;
    const int z     = zbase + blockIdx.z;

    const __half* W = g_wt + ((size_t)z << 20);

    const int c0r = tid >> 2,         c0q = tid & 3;
    const int c1r = (tid + 256) >> 2, c1q = (tid + 256) & 3;
    const uint32_t s0 = gswz(c0r, c0q), s1 = gswz(c1r, c1q);

    auto load_stage = [&](int stg, int kt) {
        const uint32_t st = sb + stg * G_STAGE_B;
        const int bk = kt * BK;
        cp16(st + s0, A + (size_t)(mBase + c0r) * D_ + bk + c0q * 8);
        cp16(st + s1, A + (size_t)(mBase + c1r) * D_ + bk + c1q * 8);
        cp16(st + G_ARR_B + s0, W + (size_t)(nBase + c0r) * D_ + bk + c0q * 8);
        cp16(st + G_ARR_B + s1, W + (size_t)(nBase + c1r) * D_ + bk + c1q * 8);
        cp_commit();
    };

    float acc[2][8][4];
    #pragma unroll
    for (int mi = 0; mi < 2; mi++)
        #pragma unroll
        for (int ni = 0; ni < 8; ni++)
            #pragma unroll
            for (int r = 0; r < 4; r++) acc[mi][ni][r] = 0.f;

    // prologue: fill 5 stages
    #pragma unroll
    for (int j = 0; j < 5; j++) load_stage(j, j);

    int rowA[2], rowB[4];
    #pragma unroll
    for (int mi = 0; mi < 2; mi++)
        rowA[mi] = wm + (lane & 7) + ((lane >> 3) & 1) * 8 + mi * 16;
    #pragma unroll
    for (int p = 0; p < 4; p++)
        rowB[p] = wn + ((lane >> 4) & 1) * 8 + (lane & 7) + p * 16;
    const int chA = (lane >> 4) & 1;
    const int chB = (lane >> 3) & 1;

    #pragma unroll 1
    for (int kt = 0; kt < KT_G; kt++) {
        cp_wait<4>();            // stage kt ready
        __syncthreads();         // all warps done with stage kt-1

        if (kt + 5 < KT_G) load_stage((kt + 5) % G_NSTG, kt + 5);
        else               cp_commit();

        const uint32_t st = sb + (kt % G_NSTG) * G_STAGE_B;
        const uint32_t sA = st;
        const uint32_t sW = st + G_ARR_B;

        #pragma unroll
        for (int ks = 0; ks < 2; ks++) {
            uint32_t af[2][4];
            #pragma unroll
            for (int mi = 0; mi < 2; mi++)
                ldm_x4(af[mi], sA + gswz(rowA[mi], chA + ks * 2));
            uint32_t bf[4][4];
            #pragma unroll
            for (int p = 0; p < 4; p++)
                ldm_x4(bf[p], sW + gswz(rowB[p], chB + ks * 2));
            #pragma unroll
            for (int mi = 0; mi < 2; mi++)
                #pragma unroll
                for (int p = 0; p < 4; p++)
                    #pragma unroll
                    for (int hf = 0; hf < 2; hf++)
                        mma_f16(acc[mi][p * 2 + hf], af[mi], &bf[p][hf * 2]);
        }
    }

    // --- epilogue ---
    const float* bias = (MODE == 0)
        ? (blockIdx.z == 0 ? b0 : blockIdx.z == 1 ? b1 : b2) : b0;

    __half* dst16 = nullptr;
    float scale = 1.f;
    if (MODE == 0) {
        if (blockIdx.z == 0)      { dst16 = g_q16; scale = QSCALE; }
        else if (blockIdx.z == 1) { dst16 = g_k16; }
        else                      { dst16 = g_v16; }
    }

    #pragma unroll
    for (int mi = 0; mi < 2; mi++) {
        #pragma unroll
        for (int ni = 0; ni < 8; ni++) {
            const int n0 = nBase + wn + ni * 8 + (lane & 3) * 2;
            const float bv0 = __ldg(bias + n0), bv1 = __ldg(bias + n0 + 1);
            #pragma unroll
            for (int rr = 0; rr < 2; rr++) {
                const int m = mBase + wm + mi * 16 + (lane >> 2) + rr * 8;
                float v0 = acc[mi][ni][rr * 2 + 0] + bv0;
                float v1 = acc[mi][ni][rr * 2 + 1] + bv1;
                if (MODE == 0) {
                    v0 *= scale; v1 *= scale;
                    const int bb = m >> 11, tt = m & 2047;
                    const int hh = n0 >> 6, hd = n0 & 63;
                    const size_t idx =
                        ((((size_t)bb * H_ + hh) * T_ + tt) << 6) + hd;
                    reinterpret_cast<uint32_t*>(dst16)[idx >> 1] = packh2(v0, v1);
                } else {
                    *reinterpret_cast<float2*>(out + (size_t)m * D_ + n0) =
                        make_float2(v0, v1);
                }
            }
        }
    }
}

// ---------------------------------------------------------------------------
// Tensor-core causal flash attention, pure f16 operands, fp32 accum.
// S = q16 . k16; P native f16 via ex2.approx.f16x2; PV = P.V16;
// row sums via sum-MMA. 6-stage KV ring (16KB/stage), single sync per iter,
// 2 CTAs/SM.
// ---------------------------------------------------------------------------
constexpr int ATT_ARR_B   = 64 * 128;                 // 8192 per array
constexpr int ATT_STAGE_B = 2 * ATT_ARR_B;            // 16384 (k, v)
constexpr int ATT_NSTG    = 6;
constexpr int ATT_SMEM    = ATT_NSTG * ATT_STAGE_B;   // 98304 -> 2 CTAs/SM

__device__ __forceinline__ uint32_t aswz(int row, int chunk) {
    return (uint32_t)row * 128u + (uint32_t)((chunk ^ (row & 7)) << 4);
}

__global__ __launch_bounds__(256, 2)
void attn_mma()
{
    extern __shared__ __align__(128) char smem[];
    const uint32_t sb = smem_u32(smem);

    const int tid  = threadIdx.x;
    const int wid  = tid >> 5;
    const int lane = tid & 31;

    const int qb = (gridDim.x - 1) - blockIdx.x;     // largest-first
    const int h  = blockIdx.y, b = blockIdx.z;
    const size_t bh = ((size_t)(b * H_ + h)) * T_ * HD_;

    const __half* Q = g_q16 + bh + (size_t)qb * 128 * HD_;
    const __half* K = g_k16 + bh;
    const __half* V = g_v16 + bh;

    const int KT = 2 * qb + 2;   // >= 2

    // ---- Q via ring stage 0 (128 rows x 128B = 16KB), then to registers ----
    #pragma unroll
    for (int i = 0; i < 4; i++) {
        const int c = i * 256 + tid;
        const int row = c >> 3, q8 = c & 7;
        cp16(sb + aswz(row, q8), Q + (size_t)row * HD_ + q8 * 8);
    }
    cp_commit();
    cp_wait<0>();
    __syncthreads();

    uint32_t qf[4][4];
    {
        const int rowQ = wid * 16 + (lane & 7) + ((lane >> 3) & 1) * 8;
        const int chQ  = (lane >> 4) & 1;
        #pragma unroll
        for (int kc = 0; kc < 4; kc++)
            ldm_x4(qf[kc], sb + aswz(rowQ, chQ + kc * 2));
    }
    __syncthreads();             // all warps done reading Q smem

    auto load_kv = [&](int stg, int kt) {
        const uint32_t base = sb + stg * ATT_STAGE_B;
        #pragma unroll
        for (int i = 0; i < 4; i++) {                // 2 arrays * 512 chunks
            const int c = i * 256 + tid;
            const int arr = c >> 9, row = (c >> 3) & 63, q8 = c & 7;
            const __half* g = arr ? V : K;
            cp16(base + arr * ATT_ARR_B + aswz(row, q8),
                 g + (size_t)(kt * 64 + row) * HD_ + q8 * 8);
        }
        cp_commit();
    };
    // prologue: fill stages 0..4 (empty commits past KT)
    #pragma unroll
    for (int j = 0; j < 5; j++) {
        if (j < KT) load_kv(j, j);
        else        cp_commit();
    }

    float o[8][4];
    #pragma unroll
    for (int nt = 0; nt < 8; nt++)
        #pragma unroll
        for (int r = 0; r < 4; r++) o[nt][r] = 0.f;
    float m0 = -1e30f, m1 = -1e30f, l0 = 0.f, l1 = 0.f;

    const int r0g = qb * 128 + wid * 16 + (lane >> 2);

    const int rKbase = ((lane >> 4) & 1) * 8 + (lane & 7);
    const int chK    = (lane >> 3) & 1;
    const int rVbase = (lane & 7) + ((lane >> 3) & 1) * 8;
    const int chV    = (lane >> 4) & 1;

    const uint32_t ONES2[2] = {0x3C003C00u, 0x3C003C00u};

    #pragma unroll 1
    for (int kt = 0; kt < KT; kt++) {
        cp_wait<4>();            // stage kt ready
        __syncthreads();         // all warps done with stage kt-1

        if (kt + 5 < KT) load_kv((kt + 5) % ATT_NSTG, kt + 5);
        else             cp_commit();

        const uint32_t st  = sb + (kt % ATT_NSTG) * ATT_STAGE_B;
        const uint32_t stK = st;
        const uint32_t stV = st + ATT_ARR_B;

        // ---- S = q16 . k16 ----
        float s[8][4];
        #pragma unroll
        for (int nt = 0; nt < 8; nt++)
            #pragma unroll
            for (int r = 0; r < 4; r++) s[nt][r] = 0.f;

        #pragma unroll
        for (int kc = 0; kc < 4; kc++) {
            #pragma unroll
            for (int g = 0; g < 2; g++) {
                uint32_t kf[2][4];
                #pragma unroll
                for (int t = 0; t < 2; t++) {
                    const int nt16 = g * 2 + t;
                    ldm_x4(kf[t], stK + aswz(rKbase + nt16 * 16, chK + kc * 2));
                }
                #pragma unroll
                for (int t = 0; t < 2; t++)
                    #pragma unroll
                    for (int hf = 0; hf < 2; hf++)
                        mma_f16(s[(g * 2 + t) * 2 + hf], qf[kc], &kf[t][hf * 2]);
            }
        }

        // ---- causal mask (last two tiles only) ----
        if (kt >= KT - 2) {
            const int colBase = kt * 64 + (lane & 3) * 2;
            #pragma unroll
            for (int nt = 0; nt < 8; nt++)
                #pragma unroll
                for (int j = 0; j < 2; j++) {
                    const int c = colBase + nt * 8 + j;
                    if (c > r0g)     s[nt][j]     = -30000.f;
                    if (c > r0g + 8) s[nt][2 + j] = -30000.f;
                }
        }

        // ---- max-reduce + o rescale ----
        float tm0 = -1e30f, tm1 = -1e30f;
        #pragma unroll
        for (int nt = 0; nt < 8; nt++) {
            tm0 = fmaxf(tm0, fmaxf(s[nt][0], s[nt][1]));
            tm1 = fmaxf(tm1, fmaxf(s[nt][2], s[nt][3]));
        }
        tm0 = fmaxf(tm0, __shfl_xor_sync(0xffffffffu, tm0, 1));
        tm0 = fmaxf(tm0, __shfl_xor_sync(0xffffffffu, tm0, 2));
        tm1 = fmaxf(tm1, __shfl_xor_sync(0xffffffffu, tm1, 1));
        tm1 = fmaxf(tm1, __shfl_xor_sync(0xffffffffu, tm1, 2));

        const float mn0 = fmaxf(m0, tm0), mn1 = fmaxf(m1, tm1);
        const float c0 = ex2f(m0 - mn0), c1 = ex2f(m1 - mn1);
        m0 = mn0; m1 = mn1;

        #pragma unroll
        for (int nt = 0; nt < 8; nt++) {
            o[nt][0] *= c0; o[nt][1] *= c0;
            o[nt][2] *= c1; o[nt][3] *= c1;
        }

        // ---- P = ex2(S-m) f16; row sums via MMA; O += P V ----
        float dsum[4] = {0.f, 0.f, 0.f, 0.f};
        #pragma unroll
        for (int kc = 0; kc < 4; kc++) {
            const float* s0 = s[2 * kc];
            const float* s1 = s[2 * kc + 1];
            uint32_t ph[4];
            ph[0] = ex2h2(packh2(s0[0] - mn0, s0[1] - mn0));
            ph[1] = ex2h2(packh2(s0[2] - mn1, s0[3] - mn1));
            ph[2] = ex2h2(packh2(s1[0] - mn0, s1[1] - mn0));
            ph[3] = ex2h2(packh2(s1[2] - mn1, s1[3] - mn1));

            mma_f16(dsum, ph, ONES2);

            const int rowV = rVbase + kc * 16;
            #pragma unroll
            for (int nt16 = 0; nt16 < 4; nt16++) {
                uint32_t vf[4];
                ldm_x4_t(vf, stV + aswz(rowV, chV + nt16 * 2));
                #pragma unroll
                for (int hf = 0; hf < 2; hf++)
                    mma_f16(o[nt16 * 2 + hf], ph, &vf[hf * 2]);
            }
        }
        l0 = l0 * c0 + dsum[0];
        l1 = l1 * c1 + dsum[2];
    }

    // ---- finalize: single f16 plane out ----
    const float inv0 = 1.f / l0, inv1 = 1.f / l1;

    const size_t row0 = (size_t)b * T_ + qb * 128 + wid * 16 + (lane >> 2);
    const size_t row1 = row0 + 8;
    const int colB = h * HD_ + (lane & 3) * 2;

    #pragma unroll
    for (int nt = 0; nt < 8; nt++) {
        const size_t i0 = row0 * D_ + colB + nt * 8;
        const size_t i1 = row1 * D_ + colB + nt * 8;
        reinterpret_cast<uint32_t*>(g_o16)[i0 >> 1] =
            packh2(o[nt][0] * inv0, o[nt][1] * inv0);
        reinterpret_cast<uint32_t*>(g_o16)[i1 >> 1] =
            packh2(o[nt][2] * inv1, o[nt][3] * inv1);
    }
}

// ---------------------------------------------------------------------------
// Conversion kernels
// ---------------------------------------------------------------------------
__global__ __launch_bounds__(256) void quant_x_kernel(const float* __restrict__ src)
{
    const int i = blockIdx.x * 256 + threadIdx.x;
    g_x16[i] = __float2half_rn(src[i]);
}

// transpose + quantize 4 weights: g_wt[z][n][k] = f16(w_z[k][n])
__global__ __launch_bounds__(256) void wquant_kernel(
    const float* __restrict__ wq, const float* __restrict__ wk,
    const float* __restrict__ wv, const float* __restrict__ wo)
{
    __shared__ float tile[32][33];
    const int z = blockIdx.z;
    const float* w = (z == 0) ? wq : (z == 1) ? wk : (z == 2) ? wv : wo;
    const int nB = blockIdx.x * 32, kB = blockIdx.y * 32;
    const int tx = threadIdx.x & 31, ty = threadIdx.x >> 5;

    #pragma unroll
    for (int r = ty; r < 32; r += 8)
        tile[r][tx] = w[(size_t)(kB + r) * D_ + nB + tx];
    __syncthreads();
    #pragma unroll
    for (int r = ty; r < 32; r += 8) {
        const size_t di = ((size_t)z << 20) + (size_t)(nB + r) * D_ + kB + tx;
        g_wt[di] = __float2half_rn(tile[tx][r]);
    }
}

// ---------------------------------------------------------------------------
extern "C" void kernel_launch(void* const* d_in, const int* in_sizes, int n_in,
                              void* d_out, int out_size)
{
    const float* x  = (const float*)d_in[0];
    const float* wq = (const float*)d_in[1];
    const float* bq = (const float*)d_in[2];
    const float* wk = (const float*)d_in[3];
    const float* bk = (const float*)d_in[4];
    const float* wv = (const float*)d_in[5];
    const float* bv = (const float*)d_in[6];
    const float* wo = (const float*)d_in[7];
    const float* bo = (const float*)d_in[8];
    float* out = (float*)d_out;

    static bool attrSet = false;
    if (!attrSet) {
        cudaFuncSetAttribute(gemm_mma<0>,
                             cudaFuncAttributeMaxDynamicSharedMemorySize, GEMM_SMEM);
        cudaFuncSetAttribute(gemm_mma<1>,
                             cudaFuncAttributeMaxDynamicSharedMemorySize, GEMM_SMEM);
        cudaFuncSetAttribute(attn_mma,
                             cudaFuncAttributeMaxDynamicSharedMemorySize, ATT_SMEM);
        attrSet = true;
    }

    void *px16, *po16;
    cudaGetSymbolAddress(&px16, g_x16);
    cudaGetSymbolAddress(&po16, g_o16);

    const int nElem = M_ * D_;

    // 1) convert inputs
    quant_x_kernel<<<nElem / 256, 256>>>(x);
    wquant_kernel<<<dim3(32, 32, 4), 256>>>(wq, wk, wv, wo);

    // 2) QKV projections (1-term f16) -> q/k/v f16 [B,H,T,HD]; Q pre-scaled
    gemm_mma<0><<<dim3(8, 64, 3), 256, GEMM_SMEM>>>(
        (const __half*)px16, bq, bk, bv, nullptr, 0);

    // 3) tensor-core causal flash attention -> g_o16 [B*T, D]
    attn_mma<<<dim3(T_ / 128, H_, B_), 256, ATT_SMEM>>>();

    // 4) output projection (1-term f16)
    gemm_mma<1><<<dim3(8, 64, 1), 256, GEMM_SMEM>>>(
        (const __half*)po16, bo, bo, bo, out, 3);
}